// round 11
// baseline (speedup 1.0000x reference)
#include <cuda_runtime.h>
#include <cuda_bf16.h>
#include <cuda_fp16.h>
#include <math.h>
#include <cstdint>

#define B_   4
#define N_   1024
#define DIM_ 1024
#define H_   16
#define D_   64
#define SW_  256
#define LOG2E  1.4426950408889634f
#define QSCALE 0.18033688011112042f   // sm_scale * log2(e)

// ---------------- device globals (word = 2 bf16/f16) ----------------
// x/w/pw/AO stored CHUNK-BLOCKED: [kc][row][16 words] (kc = K/32 chunks)
__device__ unsigned g_xh[2097152],  g_xl[2097152];    // x      4096x1024 bf16
__device__ unsigned g_wh[1572864],  g_wl[1572864];    // qkv_w  3072x1024 bf16
__device__ unsigned g_pwh[524288],  g_pwl[524288];    // proj_w 1024x1024 bf16
__device__ unsigned g_Qh[2097152],  g_Ql[2097152];    // [b,h,n,d] bf16 (pre-scaled), row-major
__device__ unsigned g_Kh[2097152],  g_Kl[2097152];    // [b,h,n,d] bf16, row-major
__device__ unsigned g_Vh[2097152],  g_Vl[2097152];    // [b,h,n,d] f16, row-major
__device__ unsigned g_AOh[2097152], g_AOl[2097152];   // blocked [kc][4096][16]
__device__ float2  g_rope[32768];                     // [n][j] (cos, sin), j<32

#define CS_X  65536     // chunk stride (words): 4096 rows * 16
#define CS_W  49152     // 3072 * 16
#define CS_P  16384     // 1024 * 16

// ---------------- helpers ----------------
__device__ __forceinline__ void split2(float x, float y, unsigned &hi, unsigned &lo) {
    __nv_bfloat16 hx = __float2bfloat16(x), hy = __float2bfloat16(y);
    float rx = x - __bfloat162float(hx);
    float ry = y - __bfloat162float(hy);
    __nv_bfloat16 lx = __float2bfloat16(rx), ly = __float2bfloat16(ry);
    hi = ((unsigned)__bfloat16_as_ushort(hy) << 16) | (unsigned)__bfloat16_as_ushort(hx);
    lo = ((unsigned)__bfloat16_as_ushort(ly) << 16) | (unsigned)__bfloat16_as_ushort(lx);
}
__device__ __forceinline__ void splitf16(float x, float y, unsigned &hi, unsigned &lo) {
    __half hx = __float2half_rn(x), hy = __float2half_rn(y);
    float rx = x - __half2float(hx);
    float ry = y - __half2float(hy);
    __half lx = __float2half_rn(rx), ly = __float2half_rn(ry);
    hi = ((unsigned)__half_as_ushort(hy) << 16) | (unsigned)__half_as_ushort(hx);
    lo = ((unsigned)__half_as_ushort(ly) << 16) | (unsigned)__half_as_ushort(lx);
}
__device__ __forceinline__ void mma16816(float* c, unsigned a0, unsigned a1,
                                         unsigned a2, unsigned a3,
                                         unsigned b0, unsigned b1) {
    asm volatile(
        "mma.sync.aligned.m16n8k16.row.col.f32.bf16.bf16.f32 "
        "{%0,%1,%2,%3}, {%4,%5,%6,%7}, {%8,%9}, {%0,%1,%2,%3};"
        : "+f"(c[0]), "+f"(c[1]), "+f"(c[2]), "+f"(c[3])
        : "r"(a0), "r"(a1), "r"(a2), "r"(a3), "r"(b0), "r"(b1));
}
__device__ __forceinline__ void mma16816h(float* c, unsigned a0, unsigned a1,
                                          unsigned a2, unsigned a3,
                                          unsigned b0, unsigned b1) {
    asm volatile(
        "mma.sync.aligned.m16n8k16.row.col.f32.f16.f16.f32 "
        "{%0,%1,%2,%3}, {%4,%5,%6,%7}, {%8,%9}, {%0,%1,%2,%3};"
        : "+f"(c[0]), "+f"(c[1]), "+f"(c[2]), "+f"(c[3])
        : "r"(a0), "r"(a1), "r"(a2), "r"(a3), "r"(b0), "r"(b1));
}
__device__ __forceinline__ void ldsm4(unsigned &r0, unsigned &r1, unsigned &r2,
                                      unsigned &r3, unsigned addr) {
    asm volatile("ldmatrix.sync.aligned.m8n8.x4.shared.b16 {%0,%1,%2,%3}, [%4];"
                 : "=r"(r0), "=r"(r1), "=r"(r2), "=r"(r3) : "r"(addr));
}
__device__ __forceinline__ void ldsm4t(unsigned &r0, unsigned &r1, unsigned &r2,
                                       unsigned &r3, unsigned addr) {
    asm volatile("ldmatrix.sync.aligned.m8n8.x4.trans.shared.b16 {%0,%1,%2,%3}, [%4];"
                 : "=r"(r0), "=r"(r1), "=r"(r2), "=r"(r3) : "r"(addr));
}
__device__ __forceinline__ float ex2f(float x) {
    float y; asm("ex2.approx.f32 %0, %1;" : "=f"(y) : "f"(x)); return y;
}
__device__ __forceinline__ unsigned smem_u32(const void* p){
    unsigned a;
    asm("{ .reg .u64 t; cvta.to.shared.u64 t, %1; cvt.u32.u64 %0, t; }" : "=r"(a) : "l"(p));
    return a;
}
__device__ __forceinline__ void cpa16(unsigned daddr, const void* g){
    asm volatile("cp.async.cg.shared.global [%0], [%1], 16;" :: "r"(daddr), "l"(g) : "memory");
}
#define CP_COMMIT() asm volatile("cp.async.commit_group;" ::: "memory")

// ---------------- presplit: fp32 -> bf16 hi/lo, chunk-blocked; + rope table ---
__global__ void presplit_all(const float4* __restrict__ x,
                             const float4* __restrict__ w,
                             const float4* __restrict__ pw)
{
    if (blockIdx.y == 3) {
        for (int i = blockIdx.x * blockDim.x + threadIdx.x; i < 32768;
             i += gridDim.x * blockDim.x) {
            int n = i >> 5, j = i & 31;
            float invf = expf(-(float)j * 0.2878231366242557f);  // 10000^(-j/32)
            float sn, cs;
            sincosf((float)n * invf, &sn, &cs);
            g_rope[i] = make_float2(cs, sn);
        }
        return;
    }
    const float4* s; unsigned *hp, *lp; int rows;
    if (blockIdx.y == 0)      { s = x;  hp = g_xh;  lp = g_xl;  rows = 4096; }
    else if (blockIdx.y == 1) { s = w;  hp = g_wh;  lp = g_wl;  rows = 3072; }
    else                      { s = pw; hp = g_pwh; lp = g_pwl; rows = 1024; }
    const int n4 = rows * 256;
    for (int i = blockIdx.x * blockDim.x + threadIdx.x; i < n4; i += gridDim.x * blockDim.x) {
        float4 f = s[i];
        unsigned h0, l0, h1, l1;
        split2(f.x, f.y, h0, l0);
        split2(f.z, f.w, h1, l1);
        int r = i >> 8, c4 = i & 255;
        int kc = c4 >> 3, wic = (c4 & 7) * 2;
        size_t dw = (size_t)kc * rows * 16 + (size_t)r * 16 + wic;
        *(uint2*)(hp + dw) = make_uint2(h0, h1);
        *(uint2*)(lp + dw) = make_uint2(l0, l1);
    }
}

// ------------- GEMM mainloop: 3-stage, swizzled 16-word rows, 1 barrier/chunk --
#define STG_W  8192
#define O_ALO  2048
#define O_BHI  4096
#define O_BLO  6144
#define GEMM_SMEM 98304     // 3 stages * 32768 B

__device__ __forceinline__ void mainloop_pre(
    const unsigned* __restrict__ gAh, const unsigned* __restrict__ gAl,
    const unsigned* __restrict__ gBh, const unsigned* __restrict__ gBl,
    int row0, int col0, int csA, int csB, unsigned* u, float acc[4][4][4])
{
    const int tid = threadIdx.x;
    const int wid = tid >> 5, lane = tid & 31;
    const int wm = wid >> 2, wn = wid & 3;
    const int lq = lane >> 3, lr = lane & 7;
    const int lqh = lq >> 1, lql = lq & 1;
    const unsigned ub = smem_u32(u);

    int dof[2];
    const unsigned* aP[2]; const unsigned* bP[2];
    #pragma unroll
    for (int v = 0; v < 2; v++) {
        int q = tid + 256 * v;               // 0..511
        int r = q >> 2, qd = q & 3;
        dof[v] = r * 16 + ((qd ^ ((r >> 1) & 3)) << 2);
        aP[v] = gAh + (size_t)(row0 + r) * 16 + qd * 4;
        bP[v] = gBh + (size_t)(col0 + r) * 16 + qd * 4;
    }
    const ptrdiff_t dAl = gAl - gAh, dBl = gBl - gBh;

    const int rowA = 64 * wm + lql * 8 + lr;
    const int xrA  = (rowA >> 1) & 3;
    const unsigned aRow = ub + (unsigned)(rowA * 64);
    const unsigned qa0 = (unsigned)(((lqh    ) ^ xrA) << 4);
    const unsigned qa1 = (unsigned)(((lqh + 2) ^ xrA) << 4);
    const int rowB = 32 * wn + lqh * 8 + lr;
    const int xrB  = (rowB >> 1) & 3;
    const unsigned bRow = ub + (unsigned)(O_BHI * 4 + rowB * 64);
    const unsigned qb0 = (unsigned)(((lql    ) ^ xrB) << 4);
    const unsigned qb1 = (unsigned)(((lql + 2) ^ xrB) << 4);

    auto fill = [&](int stage, int cidx) {
        const int oa = cidx * csA, ob = cidx * csB;
        #pragma unroll
        for (int v = 0; v < 2; v++) {
            unsigned da = ub + (unsigned)((stage * STG_W + dof[v]) << 2);
            cpa16(da,               aP[v] + oa);
            cpa16(da + O_ALO * 4,   aP[v] + oa + dAl);
            cpa16(da + O_BHI * 4,   bP[v] + ob);
            cpa16(da + O_BLO * 4,   bP[v] + ob + dBl);
        }
        CP_COMMIT();
    };

    fill(0, 0);
    fill(1, 1);

    int stc = 0, stf = 2;
    for (int c = 0; c < 32; c++) {
        if (c < 31) asm volatile("cp.async.wait_group 1;" ::: "memory");
        else        asm volatile("cp.async.wait_group 0;" ::: "memory");
        __syncthreads();
        if (c + 2 < 32) { fill(stf, c + 2); stf = (stf == 2) ? 0 : stf + 1; }

        const unsigned so = (unsigned)(stc * (STG_W << 2));
        stc = (stc == 2) ? 0 : stc + 1;

        #pragma unroll
        for (int ks = 0; ks < 2; ks++) {
            const unsigned qa = ks ? qa1 : qa0;
            const unsigned qb = ks ? qb1 : qb0;
            unsigned bhf[2][4], blf[2][4];
            #pragma unroll
            for (int p = 0; p < 2; p++) {
                unsigned ad = bRow + so + (unsigned)(p * 1024) + qb;
                ldsm4(bhf[p][0], bhf[p][1], bhf[p][2], bhf[p][3], ad);
                ldsm4(blf[p][0], blf[p][1], blf[p][2], blf[p][3], ad + 8192);
            }
            #pragma unroll
            for (int mi = 0; mi < 4; mi++) {
                unsigned ad = aRow + so + (unsigned)(mi * 1024) + qa;
                unsigned ah0, ah1, ah2, ah3, al0, al1, al2, al3;
                ldsm4(ah0, ah1, ah2, ah3, ad);
                ldsm4(al0, al1, al2, al3, ad + 8192);
                mma16816(acc[mi][0], ah0, ah1, ah2, ah3, bhf[0][0], bhf[0][1]);
                mma16816(acc[mi][1], ah0, ah1, ah2, ah3, bhf[0][2], bhf[0][3]);
                mma16816(acc[mi][2], ah0, ah1, ah2, ah3, bhf[1][0], bhf[1][1]);
                mma16816(acc[mi][3], ah0, ah1, ah2, ah3, bhf[1][2], bhf[1][3]);
                mma16816(acc[mi][0], ah0, ah1, ah2, ah3, blf[0][0], blf[0][1]);
                mma16816(acc[mi][1], ah0, ah1, ah2, ah3, blf[0][2], blf[0][3]);
                mma16816(acc[mi][2], ah0, ah1, ah2, ah3, blf[1][0], blf[1][1]);
                mma16816(acc[mi][3], ah0, ah1, ah2, ah3, blf[1][2], blf[1][3]);
                mma16816(acc[mi][0], al0, al1, al2, al3, bhf[0][0], bhf[0][1]);
                mma16816(acc[mi][1], al0, al1, al2, al3, bhf[0][2], bhf[0][3]);
                mma16816(acc[mi][2], al0, al1, al2, al3, bhf[1][0], bhf[1][1]);
                mma16816(acc[mi][3], al0, al1, al2, al3, bhf[1][2], bhf[1][3]);
            }
        }
    }
    __syncthreads();
}

// ---------------- Kernel 1: QKV GEMM + LN + RoPE + split-store ----------------
__global__ __launch_bounds__(256, 2) void qkv_mm(
    const float* __restrict__ qn_w, const float* __restrict__ qn_b,
    const float* __restrict__ kn_w, const float* __restrict__ kn_b)
{
    extern __shared__ __align__(16) unsigned u[];
    const int tid = threadIdx.x;
    const int wid = tid >> 5, lane = tid & 31;
    const int wm = wid >> 2, wn = wid & 3;
    const int grp = lane >> 2, qid = lane & 3;
    const int row0 = blockIdx.y * 128;
    const int col0 = blockIdx.x * 128;

    float acc[4][4][4];
    #pragma unroll
    for (int i = 0; i < 4; i++)
        #pragma unroll
        for (int j = 0; j < 4; j++)
            #pragma unroll
            for (int k = 0; k < 4; k++) acc[i][j][k] = 0.f;

    mainloop_pre(g_xh, g_xl, g_wh, g_wl, row0, col0, CS_X, CS_W, u, acc);

    // stage 128x128 f32 tile (stride 132)
    float* stg = (float*)u;
    #pragma unroll
    for (int mi = 0; mi < 4; mi++) {
        int rr2 = 64 * wm + 16 * mi + grp;
        #pragma unroll
        for (int ni = 0; ni < 4; ni++) {
            int cc = 32 * wn + 8 * ni + 2 * qid;
            stg[rr2 * 132 + cc]           = acc[mi][ni][0];
            stg[rr2 * 132 + cc + 1]       = acc[mi][ni][1];
            stg[(rr2 + 8) * 132 + cc]     = acc[mi][ni][2];
            stg[(rr2 + 8) * 132 + cc + 1] = acc[mi][ni][3];
        }
    }
    __syncthreads();

    const int hh = tid >> 7, r = tid & 127;
    float d[64];
    const float* src = stg + r * 132 + hh * 64;
    #pragma unroll
    for (int j = 0; j < 16; j++) {
        float4 v = *(const float4*)(src + 4 * j);
        d[4*j] = v.x; d[4*j+1] = v.y; d[4*j+2] = v.z; d[4*j+3] = v.w;
    }

    const int t = col0 >> 10;                      // 0=q,1=k,2=v
    const int h = ((col0 & 1023) >> 6) + hh;
    const int grow = row0 + r;
    const int b = grow >> 10, n = grow & 1023;
    const size_t wbase = ((size_t)(b * H_ + h) * N_ + n) * 32;   // word offset

    unsigned hw[32], lw2[32];
    if (t == 2) {
        #pragma unroll
        for (int cpair = 0; cpair < 32; cpair++)
            splitf16(d[2*cpair], d[2*cpair+1], hw[cpair], lw2[cpair]);
        #pragma unroll
        for (int q8 = 0; q8 < 8; q8++) {
            *(uint4*)(g_Vh + wbase + 4*q8) = make_uint4(hw[4*q8], hw[4*q8+1], hw[4*q8+2], hw[4*q8+3]);
            *(uint4*)(g_Vl + wbase + 4*q8) = make_uint4(lw2[4*q8], lw2[4*q8+1], lw2[4*q8+2], lw2[4*q8+3]);
        }
        return;
    }

    const float* lw = t ? kn_w : qn_w;
    const float* lb = t ? kn_b : qn_b;
    float s1 = 0.f, s2 = 0.f;
    #pragma unroll
    for (int j = 0; j < 64; j++) { s1 += d[j]; s2 += d[j] * d[j]; }
    float mu = s1 * (1.f / 64.f);
    float var = s2 * (1.f / 64.f) - mu * mu;
    float rstd = rsqrtf(var + 1e-5f);
    #pragma unroll
    for (int j = 0; j < 64; j++)
        d[j] = (d[j] - mu) * rstd * __ldg(lw + j) + __ldg(lb + j);
    const float2* rt = g_rope + n * 32;
    #pragma unroll
    for (int j = 0; j < 32; j++) {
        float2 cs = __ldg(rt + j);
        float t0 = d[j];
        d[j]      = t0 * cs.x - d[j + 32] * cs.y;
        d[j + 32] = d[j + 32] * cs.x + t0 * cs.y;
    }
    if (t == 0) {
        #pragma unroll
        for (int j = 0; j < 64; j++) d[j] *= QSCALE;           // fold sm_scale*log2e into Q
    }
    #pragma unroll
    for (int cpair = 0; cpair < 32; cpair++)
        split2(d[2*cpair], d[2*cpair+1], hw[cpair], lw2[cpair]);
    unsigned* dh = t ? g_Kh : g_Qh;
    unsigned* dl = t ? g_Kl : g_Ql;
    #pragma unroll
    for (int q8 = 0; q8 < 8; q8++) {
        *(uint4*)(dh + wbase + 4*q8) = make_uint4(hw[4*q8], hw[4*q8+1], hw[4*q8+2], hw[4*q8+3]);
        *(uint4*)(dl + wbase + 4*q8) = make_uint4(lw2[4*q8], lw2[4*q8+1], lw2[4*q8+2], lw2[4*q8+3]);
    }
}

// ---------------- Kernel 3: proj GEMM + bias ----------------
__global__ __launch_bounds__(256, 2) void proj_mm(
    const float* __restrict__ bias, float* __restrict__ out)
{
    extern __shared__ __align__(16) unsigned u[];
    const int tid = threadIdx.x;
    const int wid = tid >> 5, lane = tid & 31;
    const int wm = wid >> 2, wn = wid & 3;
    const int grp = lane >> 2, qid = lane & 3;
    const int row0 = blockIdx.y * 128;
    const int col0 = blockIdx.x * 128;

    float acc[4][4][4];
    #pragma unroll
    for (int i = 0; i < 4; i++)
        #pragma unroll
        for (int j = 0; j < 4; j++)
            #pragma unroll
            for (int k = 0; k < 4; k++) acc[i][j][k] = 0.f;

    mainloop_pre(g_AOh, g_AOl, g_pwh, g_pwl, row0, col0, CS_X, CS_P, u, acc);

    #pragma unroll
    for (int mi = 0; mi < 4; mi++) {
        int rr = row0 + 64 * wm + 16 * mi + grp;
        #pragma unroll
        for (int ni = 0; ni < 4; ni++) {
            int cc = col0 + 32 * wn + 8 * ni + 2 * qid;
            float b0 = __ldg(bias + cc), b1 = __ldg(bias + cc + 1);
            *(float2*)(out + (size_t)rr * DIM_ + cc) =
                make_float2(acc[mi][ni][0] + b0, acc[mi][ni][1] + b1);
            *(float2*)(out + (size_t)(rr + 8) * DIM_ + cc) =
                make_float2(acc[mi][ni][2] + b0, acc[mi][ni][3] + b1);
        }
    }
}

// ------- Kernel 2: flash attention, 128-query CTAs + whole-tile skipping ------
// smem word offsets: Qh(128x36), Ql(128x36), Kh,Kl,Vh,Vl (64x36 each)
#define AQH 0
#define AQL 4608
#define AKH 9216
#define AKL 11520
#define AVH 13824
#define AVL 16128
#define ATT_SMEM 73728

__global__ __launch_bounds__(256) void attn_tc(const float* __restrict__ sinks)
{
    extern __shared__ __align__(16) unsigned u[];
    const int tid = threadIdx.x;
    const int wid = tid >> 5, lane = tid & 31;
    const int g8 = lane >> 2, qid = lane & 3;
    const int lq = lane >> 3, lr = lane & 7;
    const int bh = blockIdx.y, b = bh >> 4, h = bh & 15;
    const int q0 = blockIdx.x * 128;
    const unsigned ub = smem_u32(u);

    const size_t base = (size_t)(b * H_ + h) * N_ * 32;   // word base of this (b,h)
    const unsigned* Qhg = g_Qh + base + (size_t)q0 * 32;
    const unsigned* Qlg = g_Ql + base + (size_t)q0 * 32;
    const unsigned* Khg = g_Kh + base;
    const unsigned* Klg = g_Kl + base;
    const unsigned* Vhg = g_Vh + base;
    const unsigned* Vlg = g_Vl + base;

    #pragma unroll
    for (int v = 0; v < 4; v++) {
        int idx = tid + 256 * v;          // 0..1023 (128 rows x 8 uint4)
        int r = idx >> 3, f = idx & 7;
        *(uint4*)(u + AQH + r * 36 + f * 4) = *(const uint4*)(Qhg + r * 32 + f * 4);
        *(uint4*)(u + AQL + r * 36 + f * 4) = *(const uint4*)(Qlg + r * 32 + f * 4);
    }
    __syncthreads();

    // hoist Q fragments (loop-invariant over kt); warp owns rows 16*wid..+15
    unsigned qh[4][4], ql[4][4];
    const unsigned qBase = ub + ((AQH + (16 * wid + (lq & 1) * 8 + lr) * 36 + (lq >> 1) * 4) << 2);
    #pragma unroll
    for (int ks = 0; ks < 4; ks++) {
        ldsm4(qh[ks][0], qh[ks][1], qh[ks][2], qh[ks][3], qBase + (unsigned)((ks * 8) << 2));
        ldsm4(ql[ks][0], ql[ks][1], ql[ks][2], ql[ks][3],
              qBase + (unsigned)((AQL - AQH + ks * 8) << 2));
    }

    const unsigned kBase = ub + ((AKH + ((lq >> 1) * 8 + lr) * 36 + (lq & 1) * 4) << 2);
    const unsigned vBase = ub + ((AVH + ((lq & 1) * 8 + lr) * 36 + (lq >> 1) * 4) << 2);

    float m0 = __ldg(sinks + h) * LOG2E, m1 = m0;
    float d0 = 1.f, d1 = 1.f;
    float oacc[8][4];
    #pragma unroll
    for (int i = 0; i < 8; i++)
        #pragma unroll
        for (int j = 0; j < 4; j++) oacc[i][j] = 0.f;

    const int i0 = q0 + 16 * wid + g8;
    const int i1 = i0 + 8;
    const int rmin = q0 + 16 * wid;          // warp's min row
    const int rmax = rmin + 15;              // warp's max row
    const int kt_lo = (q0 >= SW_) ? ((q0 - SW_ + 1) >> 6) : 0;
    const int kt_hi = (q0 + 127) >> 6;

    for (int kt = kt_lo; kt <= kt_hi; kt++) {
        const int k0 = kt << 6;
        __syncthreads();
        #pragma unroll
        for (int v = 0; v < 2; v++) {
            int idx = tid + 256 * v;          // 0..511 (64 rows x 8 uint4)
            int r = idx >> 3, f = idx & 7;
            *(uint4*)(u + AKH + r * 36 + f * 4) = *(const uint4*)(Khg + (k0 + r) * 32 + f * 4);
            *(uint4*)(u + AKL + r * 36 + f * 4) = *(const uint4*)(Klg + (k0 + r) * 32 + f * 4);
            *(uint4*)(u + AVH + r * 36 + f * 4) = *(const uint4*)(Vhg + (k0 + r) * 32 + f * 4);
            *(uint4*)(u + AVL + r * 36 + f * 4) = *(const uint4*)(Vlg + (k0 + r) * 32 + f * 4);
        }
        __syncthreads();

        // whole-tile warp-level skip (keys [k0, k0+63] vs warp window)
        if (k0 > rmax || k0 + 63 < rmin - (SW_ - 1)) continue;

        // S = Q K^T (bf16 3-pass, base-2 logits); skip fully-masked 16-col blocks
        float sacc[8][4];
        #pragma unroll
        for (int i = 0; i < 8; i++)
            #pragma unroll
            for (int j = 0; j < 4; j++) sacc[i][j] = 0.f;

        #pragma unroll
        for (int p = 0; p < 4; p++) {
            const int c0b = k0 + 16 * p;
            if (c0b > rmax || c0b + 15 < rmin - (SW_ - 1)) continue;   // warp-uniform
            #pragma unroll
            for (int ks = 0; ks < 4; ks++) {
                unsigned kh0, kh1, kh2, kh3, kl0, kl1, kl2, kl3;
                unsigned ad = kBase + (unsigned)((p * 576 + ks * 8) << 2);
                ldsm4(kh0, kh1, kh2, kh3, ad);
                ldsm4(kl0, kl1, kl2, kl3, ad + (unsigned)((AKL - AKH) << 2));
                mma16816(sacc[2*p],   qh[ks][0], qh[ks][1], qh[ks][2], qh[ks][3], kh0, kh1);
                mma16816(sacc[2*p+1], qh[ks][0], qh[ks][1], qh[ks][2], qh[ks][3], kh2, kh3);
                mma16816(sacc[2*p],   qh[ks][0], qh[ks][1], qh[ks][2], qh[ks][3], kl0, kl1);
                mma16816(sacc[2*p+1], qh[ks][0], qh[ks][1], qh[ks][2], qh[ks][3], kl2, kl3);
                mma16816(sacc[2*p],   ql[ks][0], ql[ks][1], ql[ks][2], ql[ks][3], kh0, kh1);
                mma16816(sacc[2*p+1], ql[ks][0], ql[ks][1], ql[ks][2], ql[ks][3], kh2, kh3);
            }
        }

        // mask + row max
        float mx0 = -1e30f, mx1 = -1e30f;
        #pragma unroll
        for (int ni = 0; ni < 8; ni++) {
            int j = k0 + 8 * ni + 2 * qid;
            sacc[ni][0] = (j     <= i0 && j     > i0 - SW_) ? sacc[ni][0] : -1e30f;
            sacc[ni][1] = (j + 1 <= i0 && j + 1 > i0 - SW_) ? sacc[ni][1] : -1e30f;
            sacc[ni][2] = (j     <= i1 && j     > i1 - SW_) ? sacc[ni][2] : -1e30f;
            sacc[ni][3] = (j + 1 <= i1 && j + 1 > i1 - SW_) ? sacc[ni][3] : -1e30f;
            mx0 = fmaxf(mx0, fmaxf(sacc[ni][0], sacc[ni][1]));
            mx1 = fmaxf(mx1, fmaxf(sacc[ni][2], sacc[ni][3]));
        }
        mx0 = fmaxf(mx0, __shfl_xor_sync(0xffffffffu, mx0, 1));
        mx0 = fmaxf(mx0, __shfl_xor_sync(0xffffffffu, mx0, 2));
        mx1 = fmaxf(mx1, __shfl_xor_sync(0xffffffffu, mx1, 1));
        mx1 = fmaxf(mx1, __shfl_xor_sync(0xffffffffu, mx1, 2));
        float mn0 = fmaxf(m0, mx0), mn1 = fmaxf(m1, mx1);
        float sc0 = ex2f(m0 - mn0), sc1 = ex2f(m1 - mn1);
        m0 = mn0; m1 = mn1; d0 *= sc0; d1 *= sc1;
        #pragma unroll
        for (int nd = 0; nd < 8; nd++) {
            oacc[nd][0] *= sc0; oacc[nd][1] *= sc0;
            oacc[nd][2] *= sc1; oacc[nd][3] *= sc1;
        }

        // e = 2^(s-m), split to f16 hi/lo; accumulate row sums
        unsigned pfh[8][2], pfl[8][2];
        float t0 = 0.f, t1 = 0.f;
        #pragma unroll
        for (int ni = 0; ni < 8; ni++) {
            float e0 = ex2f(fmaxf(sacc[ni][0] - mn0, -126.f));
            float e1 = ex2f(fmaxf(sacc[ni][1] - mn0, -126.f));
            float e2 = ex2f(fmaxf(sacc[ni][2] - mn1, -126.f));
            float e3 = ex2f(fmaxf(sacc[ni][3] - mn1, -126.f));
            t0 += e0 + e1; t1 += e2 + e3;
            splitf16(e0, e1, pfh[ni][0], pfl[ni][0]);
            splitf16(e2, e3, pfh[ni][1], pfl[ni][1]);
        }
        t0 += __shfl_xor_sync(0xffffffffu, t0, 1);
        t0 += __shfl_xor_sync(0xffffffffu, t0, 2);
        t1 += __shfl_xor_sync(0xffffffffu, t1, 1);
        t1 += __shfl_xor_sync(0xffffffffu, t1, 2);
        d0 += t0; d1 += t1;

        // O += P V; skip kf blocks whose key columns are fully masked (P == 0)
        #pragma unroll
        for (int kf = 0; kf < 4; kf++) {
            const int c0b = k0 + 16 * kf;
            if (c0b > rmax || c0b + 15 < rmin - (SW_ - 1)) continue;   // warp-uniform
            unsigned a0 = pfh[2*kf][0], a1 = pfh[2*kf][1];
            unsigned a2 = pfh[2*kf+1][0], a3 = pfh[2*kf+1][1];
            unsigned c0 = pfl[2*kf][0], c1 = pfl[2*kf][1];
            unsigned c2 = pfl[2*kf+1][0], c3 = pfl[2*kf+1][1];
            #pragma unroll
            for (int p = 0; p < 4; p++) {
                unsigned vh0, vh1, vh2, vh3, vl0, vl1, vl2, vl3;
                unsigned ad = vBase + (unsigned)((kf * 576 + p * 8) << 2);
                ldsm4t(vh0, vh1, vh2, vh3, ad);
                ldsm4t(vl0, vl1, vl2, vl3, ad + (unsigned)((AVL - AVH) << 2));
                mma16816h(oacc[2*p],   a0, a1, a2, a3, vh0, vh1);
                mma16816h(oacc[2*p+1], a0, a1, a2, a3, vh2, vh3);
                mma16816h(oacc[2*p],   a0, a1, a2, a3, vl0, vl1);
                mma16816h(oacc[2*p+1], a0, a1, a2, a3, vl2, vl3);
                mma16816h(oacc[2*p],   c0, c1, c2, c3, vh0, vh1);
                mma16816h(oacc[2*p+1], c0, c1, c2, c3, vh2, vh3);
            }
        }
    }

    // epilogue: AO blocked [kc][4096 rows][16 words]
    float inv0 = 1.f / d0, inv1 = 1.f / d1;
    #pragma unroll
    for (int nd = 0; nd < 8; nd++) {
        int col = 64 * h + 8 * nd + 2 * qid;
        int kc = col >> 5, wic = (col & 31) >> 1;
        unsigned hi, lo;
        split2(oacc[nd][0] * inv0, oacc[nd][1] * inv0, hi, lo);
        size_t w0 = (size_t)kc * CS_X + (size_t)(b * N_ + i0) * 16 + wic;
        g_AOh[w0] = hi; g_AOl[w0] = lo;
        split2(oacc[nd][2] * inv1, oacc[nd][3] * inv1, hi, lo);
        size_t w1 = (size_t)kc * CS_X + (size_t)(b * N_ + i1) * 16 + wic;
        g_AOh[w1] = hi; g_AOl[w1] = lo;
    }
}

extern "C" void kernel_launch(void* const* d_in, const int* in_sizes, int n_in,
                              void* d_out, int out_size)
{
    const float* x      = (const float*)d_in[0];
    const float* qkv_w  = (const float*)d_in[1];
    const float* qn_w   = (const float*)d_in[2];
    const float* qn_b   = (const float*)d_in[3];
    const float* kn_w   = (const float*)d_in[4];
    const float* kn_b   = (const float*)d_in[5];
    const float* sinks  = (const float*)d_in[6];
    const float* proj_w = (const float*)d_in[7];
    const float* proj_b = (const float*)d_in[8];
    float* out = (float*)d_out;

    cudaFuncSetAttribute(qkv_mm,  cudaFuncAttributeMaxDynamicSharedMemorySize, GEMM_SMEM);
    cudaFuncSetAttribute(proj_mm, cudaFuncAttributeMaxDynamicSharedMemorySize, GEMM_SMEM);
    cudaFuncSetAttribute(attn_tc, cudaFuncAttributeMaxDynamicSharedMemorySize, ATT_SMEM);

    presplit_all<<<dim3(1024, 4), 256>>>((const float4*)x, (const float4*)qkv_w,
                                         (const float4*)proj_w);
    qkv_mm<<<dim3(24, 32), 256, GEMM_SMEM>>>(qn_w, qn_b, kn_w, kn_b);
    attn_tc<<<dim3(8, 64), 256, ATT_SMEM>>>(sinks);
    proj_mm<<<dim3(8, 32), 256, GEMM_SMEM>>>(proj_b, out);
}

// round 12
// speedup vs baseline: 1.0524x; 1.0524x over previous
#include <cuda_runtime.h>
#include <cuda_bf16.h>
#include <cuda_fp16.h>
#include <math.h>
#include <cstdint>

#define B_   4
#define N_   1024
#define DIM_ 1024
#define H_   16
#define D_   64
#define SW_  256
#define LOG2E  1.4426950408889634f
#define QSCALE 0.18033688011112042f   // sm_scale * log2(e)

// ---------------- device globals (word = 2 bf16/f16) ----------------
// x/w/pw/AO stored CHUNK-BLOCKED: [kc][row][16 words] (kc = K/32 chunks)
__device__ unsigned g_xh[2097152],  g_xl[2097152];    // x      4096x1024 bf16
__device__ unsigned g_wh[1572864],  g_wl[1572864];    // qkv_w  3072x1024 bf16
__device__ unsigned g_pwh[524288],  g_pwl[524288];    // proj_w 1024x1024 bf16
__device__ unsigned g_Qh[2097152],  g_Ql[2097152];    // [b,h,n,d] bf16 (pre-scaled), row-major
__device__ unsigned g_Kh[2097152],  g_Kl[2097152];    // [b,h,n,d] bf16, row-major
__device__ unsigned g_Vh[2097152],  g_Vl[2097152];    // [b,h,n,d] f16, row-major
__device__ unsigned g_AOh[2097152], g_AOl[2097152];   // blocked [kc][4096][16]
__device__ float2  g_rope[32768];                     // [n][j] (cos, sin), j<32

#define CS_X  65536     // chunk stride (words): 4096 rows * 16
#define CS_W  49152     // 3072 * 16
#define CS_P  16384     // 1024 * 16

// ---------------- helpers ----------------
__device__ __forceinline__ void split2(float x, float y, unsigned &hi, unsigned &lo) {
    __nv_bfloat16 hx = __float2bfloat16(x), hy = __float2bfloat16(y);
    float rx = x - __bfloat162float(hx);
    float ry = y - __bfloat162float(hy);
    __nv_bfloat16 lx = __float2bfloat16(rx), ly = __float2bfloat16(ry);
    hi = ((unsigned)__bfloat16_as_ushort(hy) << 16) | (unsigned)__bfloat16_as_ushort(hx);
    lo = ((unsigned)__bfloat16_as_ushort(ly) << 16) | (unsigned)__bfloat16_as_ushort(lx);
}
__device__ __forceinline__ void splitf16(float x, float y, unsigned &hi, unsigned &lo) {
    __half hx = __float2half_rn(x), hy = __float2half_rn(y);
    float rx = x - __half2float(hx);
    float ry = y - __half2float(hy);
    __half lx = __float2half_rn(rx), ly = __float2half_rn(ry);
    hi = ((unsigned)__half_as_ushort(hy) << 16) | (unsigned)__half_as_ushort(hx);
    lo = ((unsigned)__half_as_ushort(ly) << 16) | (unsigned)__half_as_ushort(lx);
}
__device__ __forceinline__ void mma16816(float* c, unsigned a0, unsigned a1,
                                         unsigned a2, unsigned a3,
                                         unsigned b0, unsigned b1) {
    asm volatile(
        "mma.sync.aligned.m16n8k16.row.col.f32.bf16.bf16.f32 "
        "{%0,%1,%2,%3}, {%4,%5,%6,%7}, {%8,%9}, {%0,%1,%2,%3};"
        : "+f"(c[0]), "+f"(c[1]), "+f"(c[2]), "+f"(c[3])
        : "r"(a0), "r"(a1), "r"(a2), "r"(a3), "r"(b0), "r"(b1));
}
__device__ __forceinline__ void mma16816h(float* c, unsigned a0, unsigned a1,
                                          unsigned a2, unsigned a3,
                                          unsigned b0, unsigned b1) {
    asm volatile(
        "mma.sync.aligned.m16n8k16.row.col.f32.f16.f16.f32 "
        "{%0,%1,%2,%3}, {%4,%5,%6,%7}, {%8,%9}, {%0,%1,%2,%3};"
        : "+f"(c[0]), "+f"(c[1]), "+f"(c[2]), "+f"(c[3])
        : "r"(a0), "r"(a1), "r"(a2), "r"(a3), "r"(b0), "r"(b1));
}
__device__ __forceinline__ void ldsm4(unsigned &r0, unsigned &r1, unsigned &r2,
                                      unsigned &r3, unsigned addr) {
    asm volatile("ldmatrix.sync.aligned.m8n8.x4.shared.b16 {%0,%1,%2,%3}, [%4];"
                 : "=r"(r0), "=r"(r1), "=r"(r2), "=r"(r3) : "r"(addr));
}
__device__ __forceinline__ void ldsm4t(unsigned &r0, unsigned &r1, unsigned &r2,
                                       unsigned &r3, unsigned addr) {
    asm volatile("ldmatrix.sync.aligned.m8n8.x4.trans.shared.b16 {%0,%1,%2,%3}, [%4];"
                 : "=r"(r0), "=r"(r1), "=r"(r2), "=r"(r3) : "r"(addr));
}
__device__ __forceinline__ float ex2f(float x) {
    float y; asm("ex2.approx.f32 %0, %1;" : "=f"(y) : "f"(x)); return y;
}
__device__ __forceinline__ unsigned smem_u32(const void* p){
    unsigned a;
    asm("{ .reg .u64 t; cvta.to.shared.u64 t, %1; cvt.u32.u64 %0, t; }" : "=r"(a) : "l"(p));
    return a;
}
__device__ __forceinline__ void cpa16(unsigned daddr, const void* g){
    asm volatile("cp.async.cg.shared.global [%0], [%1], 16;" :: "r"(daddr), "l"(g) : "memory");
}
#define CP_COMMIT() asm volatile("cp.async.commit_group;" ::: "memory")
#define CP_WAIT0()  asm volatile("cp.async.wait_group 0;" ::: "memory")

// ---------------- presplit: fp32 -> bf16 hi/lo, chunk-blocked; + rope table ---
__global__ void presplit_all(const float4* __restrict__ x,
                             const float4* __restrict__ w,
                             const float4* __restrict__ pw)
{
    if (blockIdx.y == 3) {
        for (int i = blockIdx.x * blockDim.x + threadIdx.x; i < 32768;
             i += gridDim.x * blockDim.x) {
            int n = i >> 5, j = i & 31;
            float invf = expf(-(float)j * 0.2878231366242557f);  // 10000^(-j/32)
            float sn, cs;
            sincosf((float)n * invf, &sn, &cs);
            g_rope[i] = make_float2(cs, sn);
        }
        return;
    }
    const float4* s; unsigned *hp, *lp; int rows;
    if (blockIdx.y == 0)      { s = x;  hp = g_xh;  lp = g_xl;  rows = 4096; }
    else if (blockIdx.y == 1) { s = w;  hp = g_wh;  lp = g_wl;  rows = 3072; }
    else                      { s = pw; hp = g_pwh; lp = g_pwl; rows = 1024; }
    const int n4 = rows * 256;
    for (int i = blockIdx.x * blockDim.x + threadIdx.x; i < n4; i += gridDim.x * blockDim.x) {
        float4 f = s[i];
        unsigned h0, l0, h1, l1;
        split2(f.x, f.y, h0, l0);
        split2(f.z, f.w, h1, l1);
        int r = i >> 8, c4 = i & 255;
        int kc = c4 >> 3, wic = (c4 & 7) * 2;
        size_t dw = (size_t)kc * rows * 16 + (size_t)r * 16 + wic;
        *(uint2*)(hp + dw) = make_uint2(h0, h1);
        *(uint2*)(lp + dw) = make_uint2(l0, l1);
    }
}

// ------------- GEMM mainloop: 3-stage, swizzled 16-word rows, 1 barrier/chunk --
#define STG_W  8192
#define O_ALO  2048
#define O_BHI  4096
#define O_BLO  6144
#define GEMM_SMEM 98304     // 3 stages * 32768 B

__device__ __forceinline__ void mainloop_pre(
    const unsigned* __restrict__ gAh, const unsigned* __restrict__ gAl,
    const unsigned* __restrict__ gBh, const unsigned* __restrict__ gBl,
    int row0, int col0, int csA, int csB, unsigned* u, float acc[4][4][4])
{
    const int tid = threadIdx.x;
    const int wid = tid >> 5, lane = tid & 31;
    const int wm = wid >> 2, wn = wid & 3;
    const int lq = lane >> 3, lr = lane & 7;
    const int lqh = lq >> 1, lql = lq & 1;
    const unsigned ub = smem_u32(u);

    int dof[2];
    const unsigned* aP[2]; const unsigned* bP[2];
    #pragma unroll
    for (int v = 0; v < 2; v++) {
        int q = tid + 256 * v;               // 0..511
        int r = q >> 2, qd = q & 3;
        dof[v] = r * 16 + ((qd ^ ((r >> 1) & 3)) << 2);
        aP[v] = gAh + (size_t)(row0 + r) * 16 + qd * 4;
        bP[v] = gBh + (size_t)(col0 + r) * 16 + qd * 4;
    }
    const ptrdiff_t dAl = gAl - gAh, dBl = gBl - gBh;

    const int rowA = 64 * wm + lql * 8 + lr;
    const int xrA  = (rowA >> 1) & 3;
    const unsigned aRow = ub + (unsigned)(rowA * 64);
    const unsigned qa0 = (unsigned)(((lqh    ) ^ xrA) << 4);
    const unsigned qa1 = (unsigned)(((lqh + 2) ^ xrA) << 4);
    const int rowB = 32 * wn + lqh * 8 + lr;
    const int xrB  = (rowB >> 1) & 3;
    const unsigned bRow = ub + (unsigned)(O_BHI * 4 + rowB * 64);
    const unsigned qb0 = (unsigned)(((lql    ) ^ xrB) << 4);
    const unsigned qb1 = (unsigned)(((lql + 2) ^ xrB) << 4);

    auto fill = [&](int stage, int cidx) {
        const int oa = cidx * csA, ob = cidx * csB;
        #pragma unroll
        for (int v = 0; v < 2; v++) {
            unsigned da = ub + (unsigned)((stage * STG_W + dof[v]) << 2);
            cpa16(da,               aP[v] + oa);
            cpa16(da + O_ALO * 4,   aP[v] + oa + dAl);
            cpa16(da + O_BHI * 4,   bP[v] + ob);
            cpa16(da + O_BLO * 4,   bP[v] + ob + dBl);
        }
        CP_COMMIT();
    };

    fill(0, 0);
    fill(1, 1);

    int stc = 0, stf = 2;
    for (int c = 0; c < 32; c++) {
        if (c < 31) asm volatile("cp.async.wait_group 1;" ::: "memory");
        else        asm volatile("cp.async.wait_group 0;" ::: "memory");
        __syncthreads();
        if (c + 2 < 32) { fill(stf, c + 2); stf = (stf == 2) ? 0 : stf + 1; }

        const unsigned so = (unsigned)(stc * (STG_W << 2));
        stc = (stc == 2) ? 0 : stc + 1;

        #pragma unroll
        for (int ks = 0; ks < 2; ks++) {
            const unsigned qa = ks ? qa1 : qa0;
            const unsigned qb = ks ? qb1 : qb0;
            unsigned bhf[2][4], blf[2][4];
            #pragma unroll
            for (int p = 0; p < 2; p++) {
                unsigned ad = bRow + so + (unsigned)(p * 1024) + qb;
                ldsm4(bhf[p][0], bhf[p][1], bhf[p][2], bhf[p][3], ad);
                ldsm4(blf[p][0], blf[p][1], blf[p][2], blf[p][3], ad + 8192);
            }
            #pragma unroll
            for (int mi = 0; mi < 4; mi++) {
                unsigned ad = aRow + so + (unsigned)(mi * 1024) + qa;
                unsigned ah0, ah1, ah2, ah3, al0, al1, al2, al3;
                ldsm4(ah0, ah1, ah2, ah3, ad);
                ldsm4(al0, al1, al2, al3, ad + 8192);
                mma16816(acc[mi][0], ah0, ah1, ah2, ah3, bhf[0][0], bhf[0][1]);
                mma16816(acc[mi][1], ah0, ah1, ah2, ah3, bhf[0][2], bhf[0][3]);
                mma16816(acc[mi][2], ah0, ah1, ah2, ah3, bhf[1][0], bhf[1][1]);
                mma16816(acc[mi][3], ah0, ah1, ah2, ah3, bhf[1][2], bhf[1][3]);
                mma16816(acc[mi][0], ah0, ah1, ah2, ah3, blf[0][0], blf[0][1]);
                mma16816(acc[mi][1], ah0, ah1, ah2, ah3, blf[0][2], blf[0][3]);
                mma16816(acc[mi][2], ah0, ah1, ah2, ah3, blf[1][0], blf[1][1]);
                mma16816(acc[mi][3], ah0, ah1, ah2, ah3, blf[1][2], blf[1][3]);
                mma16816(acc[mi][0], al0, al1, al2, al3, bhf[0][0], bhf[0][1]);
                mma16816(acc[mi][1], al0, al1, al2, al3, bhf[0][2], bhf[0][3]);
                mma16816(acc[mi][2], al0, al1, al2, al3, bhf[1][0], bhf[1][1]);
                mma16816(acc[mi][3], al0, al1, al2, al3, bhf[1][2], bhf[1][3]);
            }
        }
    }
    __syncthreads();
}

// ---------------- Kernel 1: QKV GEMM + LN + RoPE + split-store ----------------
__global__ __launch_bounds__(256, 2) void qkv_mm(
    const float* __restrict__ qn_w, const float* __restrict__ qn_b,
    const float* __restrict__ kn_w, const float* __restrict__ kn_b)
{
    extern __shared__ __align__(16) unsigned u[];
    const int tid = threadIdx.x;
    const int wid = tid >> 5, lane = tid & 31;
    const int wm = wid >> 2, wn = wid & 3;
    const int grp = lane >> 2, qid = lane & 3;
    const int row0 = blockIdx.y * 128;
    const int col0 = blockIdx.x * 128;

    float acc[4][4][4];
    #pragma unroll
    for (int i = 0; i < 4; i++)
        #pragma unroll
        for (int j = 0; j < 4; j++)
            #pragma unroll
            for (int k = 0; k < 4; k++) acc[i][j][k] = 0.f;

    mainloop_pre(g_xh, g_xl, g_wh, g_wl, row0, col0, CS_X, CS_W, u, acc);

    // stage 128x128 f32 tile (stride 132)
    float* stg = (float*)u;
    #pragma unroll
    for (int mi = 0; mi < 4; mi++) {
        int rr2 = 64 * wm + 16 * mi + grp;
        #pragma unroll
        for (int ni = 0; ni < 4; ni++) {
            int cc = 32 * wn + 8 * ni + 2 * qid;
            stg[rr2 * 132 + cc]           = acc[mi][ni][0];
            stg[rr2 * 132 + cc + 1]       = acc[mi][ni][1];
            stg[(rr2 + 8) * 132 + cc]     = acc[mi][ni][2];
            stg[(rr2 + 8) * 132 + cc + 1] = acc[mi][ni][3];
        }
    }
    __syncthreads();

    const int hh = tid >> 7, r = tid & 127;
    float d[64];
    const float* src = stg + r * 132 + hh * 64;
    #pragma unroll
    for (int j = 0; j < 16; j++) {
        float4 v = *(const float4*)(src + 4 * j);
        d[4*j] = v.x; d[4*j+1] = v.y; d[4*j+2] = v.z; d[4*j+3] = v.w;
    }

    const int t = col0 >> 10;                      // 0=q,1=k,2=v
    const int h = ((col0 & 1023) >> 6) + hh;
    const int grow = row0 + r;
    const int b = grow >> 10, n = grow & 1023;
    const size_t wbase = ((size_t)(b * H_ + h) * N_ + n) * 32;   // word offset

    unsigned hw[32], lw2[32];
    if (t == 2) {
        #pragma unroll
        for (int cpair = 0; cpair < 32; cpair++)
            splitf16(d[2*cpair], d[2*cpair+1], hw[cpair], lw2[cpair]);
        #pragma unroll
        for (int q8 = 0; q8 < 8; q8++) {
            *(uint4*)(g_Vh + wbase + 4*q8) = make_uint4(hw[4*q8], hw[4*q8+1], hw[4*q8+2], hw[4*q8+3]);
            *(uint4*)(g_Vl + wbase + 4*q8) = make_uint4(lw2[4*q8], lw2[4*q8+1], lw2[4*q8+2], lw2[4*q8+3]);
        }
        return;
    }

    const float* lw = t ? kn_w : qn_w;
    const float* lb = t ? kn_b : qn_b;
    float s1 = 0.f, s2 = 0.f;
    #pragma unroll
    for (int j = 0; j < 64; j++) { s1 += d[j]; s2 += d[j] * d[j]; }
    float mu = s1 * (1.f / 64.f);
    float var = s2 * (1.f / 64.f) - mu * mu;
    float rstd = rsqrtf(var + 1e-5f);
    #pragma unroll
    for (int j = 0; j < 64; j++)
        d[j] = (d[j] - mu) * rstd * __ldg(lw + j) + __ldg(lb + j);
    const float2* rt = g_rope + n * 32;
    #pragma unroll
    for (int j = 0; j < 32; j++) {
        float2 cs = __ldg(rt + j);
        float t0 = d[j];
        d[j]      = t0 * cs.x - d[j + 32] * cs.y;
        d[j + 32] = d[j + 32] * cs.x + t0 * cs.y;
    }
    if (t == 0) {
        #pragma unroll
        for (int j = 0; j < 64; j++) d[j] *= QSCALE;           // fold sm_scale*log2e into Q
    }
    #pragma unroll
    for (int cpair = 0; cpair < 32; cpair++)
        split2(d[2*cpair], d[2*cpair+1], hw[cpair], lw2[cpair]);
    unsigned* dh = t ? g_Kh : g_Qh;
    unsigned* dl = t ? g_Kl : g_Ql;
    #pragma unroll
    for (int q8 = 0; q8 < 8; q8++) {
        *(uint4*)(dh + wbase + 4*q8) = make_uint4(hw[4*q8], hw[4*q8+1], hw[4*q8+2], hw[4*q8+3]);
        *(uint4*)(dl + wbase + 4*q8) = make_uint4(lw2[4*q8], lw2[4*q8+1], lw2[4*q8+2], lw2[4*q8+3]);
    }
}

// ---------------- Kernel 3: proj GEMM + bias ----------------
__global__ __launch_bounds__(256, 2) void proj_mm(
    const float* __restrict__ bias, float* __restrict__ out)
{
    extern __shared__ __align__(16) unsigned u[];
    const int tid = threadIdx.x;
    const int wid = tid >> 5, lane = tid & 31;
    const int wm = wid >> 2, wn = wid & 3;
    const int grp = lane >> 2, qid = lane & 3;
    const int row0 = blockIdx.y * 128;
    const int col0 = blockIdx.x * 128;

    float acc[4][4][4];
    #pragma unroll
    for (int i = 0; i < 4; i++)
        #pragma unroll
        for (int j = 0; j < 4; j++)
            #pragma unroll
            for (int k = 0; k < 4; k++) acc[i][j][k] = 0.f;

    mainloop_pre(g_AOh, g_AOl, g_pwh, g_pwl, row0, col0, CS_X, CS_P, u, acc);

    #pragma unroll
    for (int mi = 0; mi < 4; mi++) {
        int rr = row0 + 64 * wm + 16 * mi + grp;
        #pragma unroll
        for (int ni = 0; ni < 4; ni++) {
            int cc = col0 + 32 * wn + 8 * ni + 2 * qid;
            float b0 = __ldg(bias + cc), b1 = __ldg(bias + cc + 1);
            *(float2*)(out + (size_t)rr * DIM_ + cc) =
                make_float2(acc[mi][ni][0] + b0, acc[mi][ni][1] + b1);
            *(float2*)(out + (size_t)(rr + 8) * DIM_ + cc) =
                make_float2(acc[mi][ni][2] + b0, acc[mi][ni][3] + b1);
        }
    }
}

// ---------------- Kernel 2: flash attention (R10 config, cp.async loads) ------
// smem word offsets: Qh,Ql,Kh,Kl,Vh,Vl each 64 rows x 36 words
#define AQH 0
#define AQL 2304
#define AKH 4608
#define AKL 6912
#define AVH 9216
#define AVL 11520
#define ATT_SMEM 55296

__global__ __launch_bounds__(128) void attn_tc(const float* __restrict__ sinks)
{
    extern __shared__ __align__(16) unsigned u[];
    const int tid = threadIdx.x;
    const int wid = tid >> 5, lane = tid & 31;
    const int g8 = lane >> 2, qid = lane & 3;
    const int lq = lane >> 3, lr = lane & 7;
    const int bh = blockIdx.y, b = bh >> 4, h = bh & 15;
    const int q0 = blockIdx.x * 64;
    const unsigned ub = smem_u32(u);

    const size_t base = (size_t)(b * H_ + h) * N_ * 32;   // word base of this (b,h)
    const unsigned* Qhg = g_Qh + base + (size_t)q0 * 32;
    const unsigned* Qlg = g_Ql + base + (size_t)q0 * 32;
    const unsigned* Khg = g_Kh + base;
    const unsigned* Klg = g_Kl + base;
    const unsigned* Vhg = g_Vh + base;
    const unsigned* Vlg = g_Vl + base;

    #pragma unroll
    for (int v = 0; v < 4; v++) {
        int idx = tid + 128 * v;          // 0..511
        int r = idx >> 3, f = (idx & 7) * 4;
        unsigned da = ub + (unsigned)((r * 36 + f) << 2);
        cpa16(da + AQH * 4, Qhg + r * 32 + f);
        cpa16(da + AQL * 4, Qlg + r * 32 + f);
    }
    CP_COMMIT(); CP_WAIT0();
    __syncthreads();

    // hoist Q fragments (loop-invariant over kt)
    unsigned qh[4][4], ql[4][4];
    const unsigned qBase = ub + ((AQH + (16 * wid + (lq & 1) * 8 + lr) * 36 + (lq >> 1) * 4) << 2);
    #pragma unroll
    for (int ks = 0; ks < 4; ks++) {
        ldsm4(qh[ks][0], qh[ks][1], qh[ks][2], qh[ks][3], qBase + (unsigned)((ks * 8) << 2));
        ldsm4(ql[ks][0], ql[ks][1], ql[ks][2], ql[ks][3],
              qBase + (unsigned)((AQL - AQH + ks * 8) << 2));
    }

    const unsigned kBase = ub + ((AKH + ((lq >> 1) * 8 + lr) * 36 + (lq & 1) * 4) << 2);
    const unsigned vBase = ub + ((AVH + ((lq & 1) * 8 + lr) * 36 + (lq >> 1) * 4) << 2);

    float m0 = __ldg(sinks + h) * LOG2E, m1 = m0;
    float d0 = 1.f, d1 = 1.f;
    float oacc[8][4];
    #pragma unroll
    for (int i = 0; i < 8; i++)
        #pragma unroll
        for (int j = 0; j < 4; j++) oacc[i][j] = 0.f;

    const int i0 = q0 + 16 * wid + g8;
    const int i1 = i0 + 8;
    const int rmin = q0 + 16 * wid;          // warp's min row
    const int rmax = rmin + 15;              // warp's max row
    const int kt_lo = (q0 >= SW_) ? ((q0 - SW_ + 1) >> 6) : 0;
    const int kt_hi = q0 >> 6;

    for (int kt = kt_lo; kt <= kt_hi; kt++) {
        const int k0 = kt << 6;
        __syncthreads();
        #pragma unroll
        for (int v = 0; v < 4; v++) {
            int idx = tid + 128 * v;
            int r = idx >> 3, f = (idx & 7) * 4;
            unsigned da = ub + (unsigned)((r * 36 + f) << 2);
            int so = (k0 + r) * 32 + f;
            cpa16(da + AKH * 4, Khg + so);
            cpa16(da + AKL * 4, Klg + so);
            cpa16(da + AVH * 4, Vhg + so);
            cpa16(da + AVL * 4, Vlg + so);
        }
        CP_COMMIT(); CP_WAIT0();
        __syncthreads();

        // S = Q K^T (bf16 3-pass, base-2 logits); skip fully-masked 16-col blocks
        float sacc[8][4];
        #pragma unroll
        for (int i = 0; i < 8; i++)
            #pragma unroll
            for (int j = 0; j < 4; j++) sacc[i][j] = 0.f;

        #pragma unroll
        for (int p = 0; p < 4; p++) {
            const int c0b = k0 + 16 * p;
            if (c0b > rmax || c0b + 15 < rmin - (SW_ - 1)) continue;   // warp-uniform
            #pragma unroll
            for (int ks = 0; ks < 4; ks++) {
                unsigned kh0, kh1, kh2, kh3, kl0, kl1, kl2, kl3;
                unsigned ad = kBase + (unsigned)((p * 576 + ks * 8) << 2);
                ldsm4(kh0, kh1, kh2, kh3, ad);
                ldsm4(kl0, kl1, kl2, kl3, ad + (unsigned)((AKL - AKH) << 2));
                mma16816(sacc[2*p],   qh[ks][0], qh[ks][1], qh[ks][2], qh[ks][3], kh0, kh1);
                mma16816(sacc[2*p+1], qh[ks][0], qh[ks][1], qh[ks][2], qh[ks][3], kh2, kh3);
                mma16816(sacc[2*p],   qh[ks][0], qh[ks][1], qh[ks][2], qh[ks][3], kl0, kl1);
                mma16816(sacc[2*p+1], qh[ks][0], qh[ks][1], qh[ks][2], qh[ks][3], kl2, kl3);
                mma16816(sacc[2*p],   ql[ks][0], ql[ks][1], ql[ks][2], ql[ks][3], kh0, kh1);
                mma16816(sacc[2*p+1], ql[ks][0], ql[ks][1], ql[ks][2], ql[ks][3], kh2, kh3);
            }
        }

        // mask + row max
        float mx0 = -1e30f, mx1 = -1e30f;
        #pragma unroll
        for (int ni = 0; ni < 8; ni++) {
            int j = k0 + 8 * ni + 2 * qid;
            sacc[ni][0] = (j     <= i0 && j     > i0 - SW_) ? sacc[ni][0] : -1e30f;
            sacc[ni][1] = (j + 1 <= i0 && j + 1 > i0 - SW_) ? sacc[ni][1] : -1e30f;
            sacc[ni][2] = (j     <= i1 && j     > i1 - SW_) ? sacc[ni][2] : -1e30f;
            sacc[ni][3] = (j + 1 <= i1 && j + 1 > i1 - SW_) ? sacc[ni][3] : -1e30f;
            mx0 = fmaxf(mx0, fmaxf(sacc[ni][0], sacc[ni][1]));
            mx1 = fmaxf(mx1, fmaxf(sacc[ni][2], sacc[ni][3]));
        }
        mx0 = fmaxf(mx0, __shfl_xor_sync(0xffffffffu, mx0, 1));
        mx0 = fmaxf(mx0, __shfl_xor_sync(0xffffffffu, mx0, 2));
        mx1 = fmaxf(mx1, __shfl_xor_sync(0xffffffffu, mx1, 1));
        mx1 = fmaxf(mx1, __shfl_xor_sync(0xffffffffu, mx1, 2));
        float mn0 = fmaxf(m0, mx0), mn1 = fmaxf(m1, mx1);
        float sc0 = ex2f(m0 - mn0), sc1 = ex2f(m1 - mn1);
        m0 = mn0; m1 = mn1; d0 *= sc0; d1 *= sc1;
        #pragma unroll
        for (int nd = 0; nd < 8; nd++) {
            oacc[nd][0] *= sc0; oacc[nd][1] *= sc0;
            oacc[nd][2] *= sc1; oacc[nd][3] *= sc1;
        }

        // e = 2^(s-m), split to f16 hi/lo; accumulate row sums
        unsigned pfh[8][2], pfl[8][2];
        float t0 = 0.f, t1 = 0.f;
        #pragma unroll
        for (int ni = 0; ni < 8; ni++) {
            float e0 = ex2f(fmaxf(sacc[ni][0] - mn0, -126.f));
            float e1 = ex2f(fmaxf(sacc[ni][1] - mn0, -126.f));
            float e2 = ex2f(fmaxf(sacc[ni][2] - mn1, -126.f));
            float e3 = ex2f(fmaxf(sacc[ni][3] - mn1, -126.f));
            t0 += e0 + e1; t1 += e2 + e3;
            splitf16(e0, e1, pfh[ni][0], pfl[ni][0]);
            splitf16(e2, e3, pfh[ni][1], pfl[ni][1]);
        }
        t0 += __shfl_xor_sync(0xffffffffu, t0, 1);
        t0 += __shfl_xor_sync(0xffffffffu, t0, 2);
        t1 += __shfl_xor_sync(0xffffffffu, t1, 1);
        t1 += __shfl_xor_sync(0xffffffffu, t1, 2);
        d0 += t0; d1 += t1;

        // O += P V; skip kf blocks whose key columns are fully masked (P == 0)
        #pragma unroll
        for (int kf = 0; kf < 4; kf++) {
            const int c0b = k0 + 16 * kf;
            if (c0b > rmax || c0b + 15 < rmin - (SW_ - 1)) continue;   // warp-uniform
            unsigned a0 = pfh[2*kf][0], a1 = pfh[2*kf][1];
            unsigned a2 = pfh[2*kf+1][0], a3 = pfh[2*kf+1][1];
            unsigned c0 = pfl[2*kf][0], c1 = pfl[2*kf][1];
            unsigned c2 = pfl[2*kf+1][0], c3 = pfl[2*kf+1][1];
            #pragma unroll
            for (int p = 0; p < 4; p++) {
                unsigned vh0, vh1, vh2, vh3, vl0, vl1, vl2, vl3;
                unsigned ad = vBase + (unsigned)((kf * 576 + p * 8) << 2);
                ldsm4t(vh0, vh1, vh2, vh3, ad);
                ldsm4t(vl0, vl1, vl2, vl3, ad + (unsigned)((AVL - AVH) << 2));
                mma16816h(oacc[2*p],   a0, a1, a2, a3, vh0, vh1);
                mma16816h(oacc[2*p+1], a0, a1, a2, a3, vh2, vh3);
                mma16816h(oacc[2*p],   a0, a1, a2, a3, vl0, vl1);
                mma16816h(oacc[2*p+1], a0, a1, a2, a3, vl2, vl3);
                mma16816h(oacc[2*p],   c0, c1, c2, c3, vh0, vh1);
                mma16816h(oacc[2*p+1], c0, c1, c2, c3, vh2, vh3);
            }
        }
    }

    // epilogue: AO blocked [kc][4096 rows][16 words]
    float inv0 = 1.f / d0, inv1 = 1.f / d1;
    #pragma unroll
    for (int nd = 0; nd < 8; nd++) {
        int col = 64 * h + 8 * nd + 2 * qid;
        int kc = col >> 5, wic = (col & 31) >> 1;
        unsigned hi, lo;
        split2(oacc[nd][0] * inv0, oacc[nd][1] * inv0, hi, lo);
        size_t w0 = (size_t)kc * CS_X + (size_t)(b * N_ + i0) * 16 + wic;
        g_AOh[w0] = hi; g_AOl[w0] = lo;
        split2(oacc[nd][2] * inv1, oacc[nd][3] * inv1, hi, lo);
        size_t w1 = (size_t)kc * CS_X + (size_t)(b * N_ + i1) * 16 + wic;
        g_AOh[w1] = hi; g_AOl[w1] = lo;
    }
}

extern "C" void kernel_launch(void* const* d_in, const int* in_sizes, int n_in,
                              void* d_out, int out_size)
{
    const float* x      = (const float*)d_in[0];
    const float* qkv_w  = (const float*)d_in[1];
    const float* qn_w   = (const float*)d_in[2];
    const float* qn_b   = (const float*)d_in[3];
    const float* kn_w   = (const float*)d_in[4];
    const float* kn_b   = (const float*)d_in[5];
    const float* sinks  = (const float*)d_in[6];
    const float* proj_w = (const float*)d_in[7];
    const float* proj_b = (const float*)d_in[8];
    float* out = (float*)d_out;

    cudaFuncSetAttribute(qkv_mm,  cudaFuncAttributeMaxDynamicSharedMemorySize, GEMM_SMEM);
    cudaFuncSetAttribute(proj_mm, cudaFuncAttributeMaxDynamicSharedMemorySize, GEMM_SMEM);
    cudaFuncSetAttribute(attn_tc, cudaFuncAttributeMaxDynamicSharedMemorySize, ATT_SMEM);

    presplit_all<<<dim3(1024, 4), 256>>>((const float4*)x, (const float4*)qkv_w,
                                         (const float4*)proj_w);
    qkv_mm<<<dim3(24, 32), 256, GEMM_SMEM>>>(qn_w, qn_b, kn_w, kn_b);
    attn_tc<<<dim3(16, 64), 128, ATT_SMEM>>>(sinks);
    proj_mm<<<dim3(8, 32), 256, GEMM_SMEM>>>(proj_b, out);
}

// round 13
// speedup vs baseline: 1.1389x; 1.0822x over previous
#include <cuda_runtime.h>
#include <cuda_bf16.h>
#include <cuda_fp16.h>
#include <math.h>
#include <cstdint>

#define B_   4
#define N_   1024
#define DIM_ 1024
#define H_   16
#define D_   64
#define SW_  256
#define LOG2E  1.4426950408889634f
#define QSCALE 0.18033688011112042f   // sm_scale * log2(e)

// ---------------- device globals (word = 2 f16) ----------------
// x/w/pw/AO stored CHUNK-BLOCKED: [kc][row][16 words] (kc = K/32 chunks)
__device__ unsigned g_xh[2097152],  g_xl[2097152];    // x      4096x1024 f16 split
__device__ unsigned g_wh[1572864],  g_wl[1572864];    // qkv_w  3072x1024 f16 split
__device__ unsigned g_pwh[524288],  g_pwl[524288];    // proj_w 1024x1024 f16 split
__device__ unsigned g_Qh[2097152],  g_Ql[2097152];    // [b,h,n,d] f16 split (pre-scaled)
__device__ unsigned g_Kh[2097152],  g_Kl[2097152];    // [b,h,n,d] f16 split
__device__ unsigned g_Vh[2097152],  g_Vl[2097152];    // [b,h,n,d] f16 split
__device__ unsigned g_AOh[2097152], g_AOl[2097152];   // blocked [kc][4096][16] f16 split
__device__ float2  g_rope[32768];                     // [n][j] (cos, sin), j<32

#define CS_X  65536     // chunk stride (words): 4096 rows * 16
#define CS_W  49152     // 3072 * 16
#define CS_P  16384     // 1024 * 16

// ---------------- helpers ----------------
__device__ __forceinline__ void splitf16(float x, float y, unsigned &hi, unsigned &lo) {
    __half hx = __float2half_rn(x), hy = __float2half_rn(y);
    float rx = x - __half2float(hx);
    float ry = y - __half2float(hy);
    __half lx = __float2half_rn(rx), ly = __float2half_rn(ry);
    hi = ((unsigned)__half_as_ushort(hy) << 16) | (unsigned)__half_as_ushort(hx);
    lo = ((unsigned)__half_as_ushort(ly) << 16) | (unsigned)__half_as_ushort(lx);
}
__device__ __forceinline__ unsigned packh(float x, float y) {
    __half hx = __float2half_rn(x), hy = __float2half_rn(y);
    return ((unsigned)__half_as_ushort(hy) << 16) | (unsigned)__half_as_ushort(hx);
}
__device__ __forceinline__ void mma16816h(float* c, unsigned a0, unsigned a1,
                                          unsigned a2, unsigned a3,
                                          unsigned b0, unsigned b1) {
    asm volatile(
        "mma.sync.aligned.m16n8k16.row.col.f32.f16.f16.f32 "
        "{%0,%1,%2,%3}, {%4,%5,%6,%7}, {%8,%9}, {%0,%1,%2,%3};"
        : "+f"(c[0]), "+f"(c[1]), "+f"(c[2]), "+f"(c[3])
        : "r"(a0), "r"(a1), "r"(a2), "r"(a3), "r"(b0), "r"(b1));
}
__device__ __forceinline__ void ldsm4(unsigned &r0, unsigned &r1, unsigned &r2,
                                      unsigned &r3, unsigned addr) {
    asm volatile("ldmatrix.sync.aligned.m8n8.x4.shared.b16 {%0,%1,%2,%3}, [%4];"
                 : "=r"(r0), "=r"(r1), "=r"(r2), "=r"(r3) : "r"(addr));
}
__device__ __forceinline__ void ldsm4t(unsigned &r0, unsigned &r1, unsigned &r2,
                                       unsigned &r3, unsigned addr) {
    asm volatile("ldmatrix.sync.aligned.m8n8.x4.trans.shared.b16 {%0,%1,%2,%3}, [%4];"
                 : "=r"(r0), "=r"(r1), "=r"(r2), "=r"(r3) : "r"(addr));
}
__device__ __forceinline__ float ex2f(float x) {
    float y; asm("ex2.approx.f32 %0, %1;" : "=f"(y) : "f"(x)); return y;
}
__device__ __forceinline__ unsigned smem_u32(const void* p){
    unsigned a;
    asm("{ .reg .u64 t; cvta.to.shared.u64 t, %1; cvt.u32.u64 %0, t; }" : "=r"(a) : "l"(p));
    return a;
}
__device__ __forceinline__ void cpa16(unsigned daddr, const void* g){
    asm volatile("cp.async.cg.shared.global [%0], [%1], 16;" :: "r"(daddr), "l"(g) : "memory");
}
#define CP_COMMIT() asm volatile("cp.async.commit_group;" ::: "memory")
#define CP_WAIT0()  asm volatile("cp.async.wait_group 0;" ::: "memory")

// ---------------- presplit: fp32 -> f16 hi/lo, chunk-blocked; + rope table ----
__global__ void presplit_all(const float4* __restrict__ x,
                             const float4* __restrict__ w,
                             const float4* __restrict__ pw)
{
    if (blockIdx.y == 3) {
        for (int i = blockIdx.x * blockDim.x + threadIdx.x; i < 32768;
             i += gridDim.x * blockDim.x) {
            int n = i >> 5, j = i & 31;
            float invf = expf(-(float)j * 0.2878231366242557f);  // 10000^(-j/32)
            float sn, cs;
            sincosf((float)n * invf, &sn, &cs);
            g_rope[i] = make_float2(cs, sn);
        }
        return;
    }
    const float4* s; unsigned *hp, *lp; int rows;
    if (blockIdx.y == 0)      { s = x;  hp = g_xh;  lp = g_xl;  rows = 4096; }
    else if (blockIdx.y == 1) { s = w;  hp = g_wh;  lp = g_wl;  rows = 3072; }
    else                      { s = pw; hp = g_pwh; lp = g_pwl; rows = 1024; }
    const int n4 = rows * 256;
    for (int i = blockIdx.x * blockDim.x + threadIdx.x; i < n4; i += gridDim.x * blockDim.x) {
        float4 f = s[i];
        unsigned h0, l0, h1, l1;
        splitf16(f.x, f.y, h0, l0);
        splitf16(f.z, f.w, h1, l1);
        int r = i >> 8, c4 = i & 255;
        int kc = c4 >> 3, wic = (c4 & 7) * 2;
        size_t dw = (size_t)kc * rows * 16 + (size_t)r * 16 + wic;
        *(uint2*)(hp + dw) = make_uint2(h0, h1);
        *(uint2*)(lp + dw) = make_uint2(l0, l1);
    }
}

// ------------- GEMM mainloop: 3-stage, swizzled 16-word rows, 1 barrier/chunk --
// full=1: C = Ah*Bh + Al*Bh + Ah*Bl (err 2^-22). full=0: C = Ah*Bh + Al*Bh.
#define STG_W  8192
#define O_ALO  2048
#define O_BHI  4096
#define O_BLO  6144
#define GEMM_SMEM 98304     // 3 stages * 32768 B

__device__ __forceinline__ void mainloop_pre(
    const unsigned* __restrict__ gAh, const unsigned* __restrict__ gAl,
    const unsigned* __restrict__ gBh, const unsigned* __restrict__ gBl,
    int row0, int col0, int csA, int csB, int full, unsigned* u, float acc[4][4][4])
{
    const int tid = threadIdx.x;
    const int wid = tid >> 5, lane = tid & 31;
    const int wm = wid >> 2, wn = wid & 3;
    const int lq = lane >> 3, lr = lane & 7;
    const int lqh = lq >> 1, lql = lq & 1;
    const unsigned ub = smem_u32(u);

    int dof[2];
    const unsigned* aP[2]; const unsigned* bP[2];
    #pragma unroll
    for (int v = 0; v < 2; v++) {
        int q = tid + 256 * v;               // 0..511
        int r = q >> 2, qd = q & 3;
        dof[v] = r * 16 + ((qd ^ ((r >> 1) & 3)) << 2);
        aP[v] = gAh + (size_t)(row0 + r) * 16 + qd * 4;
        bP[v] = gBh + (size_t)(col0 + r) * 16 + qd * 4;
    }
    const ptrdiff_t dAl = gAl - gAh, dBl = gBl - gBh;

    const int rowA = 64 * wm + lql * 8 + lr;
    const int xrA  = (rowA >> 1) & 3;
    const unsigned aRow = ub + (unsigned)(rowA * 64);
    const unsigned qa0 = (unsigned)(((lqh    ) ^ xrA) << 4);
    const unsigned qa1 = (unsigned)(((lqh + 2) ^ xrA) << 4);
    const int rowB = 32 * wn + lqh * 8 + lr;
    const int xrB  = (rowB >> 1) & 3;
    const unsigned bRow = ub + (unsigned)(O_BHI * 4 + rowB * 64);
    const unsigned qb0 = (unsigned)(((lql    ) ^ xrB) << 4);
    const unsigned qb1 = (unsigned)(((lql + 2) ^ xrB) << 4);

    auto fill = [&](int stage, int cidx) {
        const int oa = cidx * csA, ob = cidx * csB;
        #pragma unroll
        for (int v = 0; v < 2; v++) {
            unsigned da = ub + (unsigned)((stage * STG_W + dof[v]) << 2);
            cpa16(da,               aP[v] + oa);
            cpa16(da + O_ALO * 4,   aP[v] + oa + dAl);
            cpa16(da + O_BHI * 4,   bP[v] + ob);
            if (full) cpa16(da + O_BLO * 4, bP[v] + ob + dBl);
        }
        CP_COMMIT();
    };

    fill(0, 0);
    fill(1, 1);

    int stc = 0, stf = 2;
    for (int c = 0; c < 32; c++) {
        if (c < 31) asm volatile("cp.async.wait_group 1;" ::: "memory");
        else        asm volatile("cp.async.wait_group 0;" ::: "memory");
        __syncthreads();
        if (c + 2 < 32) { fill(stf, c + 2); stf = (stf == 2) ? 0 : stf + 1; }

        const unsigned so = (unsigned)(stc * (STG_W << 2));
        stc = (stc == 2) ? 0 : stc + 1;

        #pragma unroll
        for (int ks = 0; ks < 2; ks++) {
            const unsigned qa = ks ? qa1 : qa0;
            const unsigned qb = ks ? qb1 : qb0;
            unsigned bhf[2][4], blf[2][4];
            #pragma unroll
            for (int p = 0; p < 2; p++) {
                unsigned ad = bRow + so + (unsigned)(p * 1024) + qb;
                ldsm4(bhf[p][0], bhf[p][1], bhf[p][2], bhf[p][3], ad);
                if (full)
                    ldsm4(blf[p][0], blf[p][1], blf[p][2], blf[p][3], ad + 8192);
            }
            #pragma unroll
            for (int mi = 0; mi < 4; mi++) {
                unsigned ad = aRow + so + (unsigned)(mi * 1024) + qa;
                unsigned ah0, ah1, ah2, ah3, al0, al1, al2, al3;
                ldsm4(ah0, ah1, ah2, ah3, ad);
                ldsm4(al0, al1, al2, al3, ad + 8192);
                mma16816h(acc[mi][0], ah0, ah1, ah2, ah3, bhf[0][0], bhf[0][1]);
                mma16816h(acc[mi][1], ah0, ah1, ah2, ah3, bhf[0][2], bhf[0][3]);
                mma16816h(acc[mi][2], ah0, ah1, ah2, ah3, bhf[1][0], bhf[1][1]);
                mma16816h(acc[mi][3], ah0, ah1, ah2, ah3, bhf[1][2], bhf[1][3]);
                mma16816h(acc[mi][0], al0, al1, al2, al3, bhf[0][0], bhf[0][1]);
                mma16816h(acc[mi][1], al0, al1, al2, al3, bhf[0][2], bhf[0][3]);
                mma16816h(acc[mi][2], al0, al1, al2, al3, bhf[1][0], bhf[1][1]);
                mma16816h(acc[mi][3], al0, al1, al2, al3, bhf[1][2], bhf[1][3]);
                if (full) {
                    mma16816h(acc[mi][0], ah0, ah1, ah2, ah3, blf[0][0], blf[0][1]);
                    mma16816h(acc[mi][1], ah0, ah1, ah2, ah3, blf[0][2], blf[0][3]);
                    mma16816h(acc[mi][2], ah0, ah1, ah2, ah3, blf[1][0], blf[1][1]);
                    mma16816h(acc[mi][3], ah0, ah1, ah2, ah3, blf[1][2], blf[1][3]);
                }
            }
        }
    }
    __syncthreads();
}

// ---------------- Kernel 1: QKV GEMM + LN + RoPE + split-store ----------------
__global__ __launch_bounds__(256, 2) void qkv_mm(
    const float* __restrict__ qn_w, const float* __restrict__ qn_b,
    const float* __restrict__ kn_w, const float* __restrict__ kn_b)
{
    extern __shared__ __align__(16) unsigned u[];
    const int tid = threadIdx.x;
    const int wid = tid >> 5, lane = tid & 31;
    const int wm = wid >> 2, wn = wid & 3;
    const int grp = lane >> 2, qid = lane & 3;
    const int row0 = blockIdx.y * 128;
    const int col0 = blockIdx.x * 128;

    float acc[4][4][4];
    #pragma unroll
    for (int i = 0; i < 4; i++)
        #pragma unroll
        for (int j = 0; j < 4; j++)
            #pragma unroll
            for (int k = 0; k < 4; k++) acc[i][j][k] = 0.f;

    // Q/K tiles (col0 < 2048): 3-pass; V tiles: 2-pass (w single f16)
    mainloop_pre(g_xh, g_xl, g_wh, g_wl, row0, col0, CS_X, CS_W,
                 col0 < 2048 ? 1 : 0, u, acc);

    // stage 128x128 f32 tile (stride 132)
    float* stg = (float*)u;
    #pragma unroll
    for (int mi = 0; mi < 4; mi++) {
        int rr2 = 64 * wm + 16 * mi + grp;
        #pragma unroll
        for (int ni = 0; ni < 4; ni++) {
            int cc = 32 * wn + 8 * ni + 2 * qid;
            stg[rr2 * 132 + cc]           = acc[mi][ni][0];
            stg[rr2 * 132 + cc + 1]       = acc[mi][ni][1];
            stg[(rr2 + 8) * 132 + cc]     = acc[mi][ni][2];
            stg[(rr2 + 8) * 132 + cc + 1] = acc[mi][ni][3];
        }
    }
    __syncthreads();

    const int hh = tid >> 7, r = tid & 127;
    float d[64];
    const float* src = stg + r * 132 + hh * 64;
    #pragma unroll
    for (int j = 0; j < 16; j++) {
        float4 v = *(const float4*)(src + 4 * j);
        d[4*j] = v.x; d[4*j+1] = v.y; d[4*j+2] = v.z; d[4*j+3] = v.w;
    }

    const int t = col0 >> 10;                      // 0=q,1=k,2=v
    const int h = ((col0 & 1023) >> 6) + hh;
    const int grow = row0 + r;
    const int b = grow >> 10, n = grow & 1023;
    const size_t wbase = ((size_t)(b * H_ + h) * N_ + n) * 32;   // word offset

    unsigned hw[32], lw2[32];
    if (t == 2) {
        #pragma unroll
        for (int cpair = 0; cpair < 32; cpair++)
            splitf16(d[2*cpair], d[2*cpair+1], hw[cpair], lw2[cpair]);
        #pragma unroll
        for (int q8 = 0; q8 < 8; q8++) {
            *(uint4*)(g_Vh + wbase + 4*q8) = make_uint4(hw[4*q8], hw[4*q8+1], hw[4*q8+2], hw[4*q8+3]);
            *(uint4*)(g_Vl + wbase + 4*q8) = make_uint4(lw2[4*q8], lw2[4*q8+1], lw2[4*q8+2], lw2[4*q8+3]);
        }
        return;
    }

    const float* lw = t ? kn_w : qn_w;
    const float* lb = t ? kn_b : qn_b;
    float s1 = 0.f, s2 = 0.f;
    #pragma unroll
    for (int j = 0; j < 64; j++) { s1 += d[j]; s2 += d[j] * d[j]; }
    float mu = s1 * (1.f / 64.f);
    float var = s2 * (1.f / 64.f) - mu * mu;
    float rstd = rsqrtf(var + 1e-5f);
    #pragma unroll
    for (int j = 0; j < 64; j++)
        d[j] = (d[j] - mu) * rstd * __ldg(lw + j) + __ldg(lb + j);
    const float2* rt = g_rope + n * 32;
    #pragma unroll
    for (int j = 0; j < 32; j++) {
        float2 cs = __ldg(rt + j);
        float t0 = d[j];
        d[j]      = t0 * cs.x - d[j + 32] * cs.y;
        d[j + 32] = d[j + 32] * cs.x + t0 * cs.y;
    }
    if (t == 0) {
        #pragma unroll
        for (int j = 0; j < 64; j++) d[j] *= QSCALE;           // fold sm_scale*log2e into Q
    }
    #pragma unroll
    for (int cpair = 0; cpair < 32; cpair++)
        splitf16(d[2*cpair], d[2*cpair+1], hw[cpair], lw2[cpair]);
    unsigned* dh = t ? g_Kh : g_Qh;
    unsigned* dl = t ? g_Kl : g_Ql;
    #pragma unroll
    for (int q8 = 0; q8 < 8; q8++) {
        *(uint4*)(dh + wbase + 4*q8) = make_uint4(hw[4*q8], hw[4*q8+1], hw[4*q8+2], hw[4*q8+3]);
        *(uint4*)(dl + wbase + 4*q8) = make_uint4(lw2[4*q8], lw2[4*q8+1], lw2[4*q8+2], lw2[4*q8+3]);
    }
}

// ---------------- Kernel 3: proj GEMM + bias (2-pass) ----------------
__global__ __launch_bounds__(256, 2) void proj_mm(
    const float* __restrict__ bias, float* __restrict__ out)
{
    extern __shared__ __align__(16) unsigned u[];
    const int tid = threadIdx.x;
    const int wid = tid >> 5, lane = tid & 31;
    const int wm = wid >> 2, wn = wid & 3;
    const int grp = lane >> 2, qid = lane & 3;
    const int row0 = blockIdx.y * 128;
    const int col0 = blockIdx.x * 128;

    float acc[4][4][4];
    #pragma unroll
    for (int i = 0; i < 4; i++)
        #pragma unroll
        for (int j = 0; j < 4; j++)
            #pragma unroll
            for (int k = 0; k < 4; k++) acc[i][j][k] = 0.f;

    mainloop_pre(g_AOh, g_AOl, g_pwh, g_pwl, row0, col0, CS_X, CS_P, 0, u, acc);

    #pragma unroll
    for (int mi = 0; mi < 4; mi++) {
        int rr = row0 + 64 * wm + 16 * mi + grp;
        #pragma unroll
        for (int ni = 0; ni < 4; ni++) {
            int cc = col0 + 32 * wn + 8 * ni + 2 * qid;
            float b0 = __ldg(bias + cc), b1 = __ldg(bias + cc + 1);
            *(float2*)(out + (size_t)rr * DIM_ + cc) =
                make_float2(acc[mi][ni][0] + b0, acc[mi][ni][1] + b1);
            *(float2*)(out + (size_t)(rr + 8) * DIM_ + cc) =
                make_float2(acc[mi][ni][2] + b0, acc[mi][ni][3] + b1);
        }
    }
}

// ---------------- Kernel 2: flash attention (f16 splits, 2-pass PV) -----------
// smem word offsets: Qh,Ql,Kh,Kl,Vh,Vl each 64 rows x 36 words
#define AQH 0
#define AQL 2304
#define AKH 4608
#define AKL 6912
#define AVH 9216
#define AVL 11520
#define ATT_SMEM 55296

__global__ __launch_bounds__(128) void attn_tc(const float* __restrict__ sinks)
{
    extern __shared__ __align__(16) unsigned u[];
    const int tid = threadIdx.x;
    const int wid = tid >> 5, lane = tid & 31;
    const int g8 = lane >> 2, qid = lane & 3;
    const int lq = lane >> 3, lr = lane & 7;
    const int bh = blockIdx.y, b = bh >> 4, h = bh & 15;
    const int q0 = blockIdx.x * 64;
    const unsigned ub = smem_u32(u);

    const size_t base = (size_t)(b * H_ + h) * N_ * 32;   // word base of this (b,h)
    const unsigned* Qhg = g_Qh + base + (size_t)q0 * 32;
    const unsigned* Qlg = g_Ql + base + (size_t)q0 * 32;
    const unsigned* Khg = g_Kh + base;
    const unsigned* Klg = g_Kl + base;
    const unsigned* Vhg = g_Vh + base;
    const unsigned* Vlg = g_Vl + base;

    #pragma unroll
    for (int v = 0; v < 4; v++) {
        int idx = tid + 128 * v;          // 0..511
        int r = idx >> 3, f = (idx & 7) * 4;
        unsigned da = ub + (unsigned)((r * 36 + f) << 2);
        cpa16(da + AQH * 4, Qhg + r * 32 + f);
        cpa16(da + AQL * 4, Qlg + r * 32 + f);
    }
    CP_COMMIT(); CP_WAIT0();
    __syncthreads();

    // hoist Q fragments (loop-invariant over kt)
    unsigned qh[4][4], ql[4][4];
    const unsigned qBase = ub + ((AQH + (16 * wid + (lq & 1) * 8 + lr) * 36 + (lq >> 1) * 4) << 2);
    #pragma unroll
    for (int ks = 0; ks < 4; ks++) {
        ldsm4(qh[ks][0], qh[ks][1], qh[ks][2], qh[ks][3], qBase + (unsigned)((ks * 8) << 2));
        ldsm4(ql[ks][0], ql[ks][1], ql[ks][2], ql[ks][3],
              qBase + (unsigned)((AQL - AQH + ks * 8) << 2));
    }

    const unsigned kBase = ub + ((AKH + ((lq >> 1) * 8 + lr) * 36 + (lq & 1) * 4) << 2);
    const unsigned vBase = ub + ((AVH + ((lq & 1) * 8 + lr) * 36 + (lq >> 1) * 4) << 2);

    float m0 = __ldg(sinks + h) * LOG2E, m1 = m0;
    float d0 = 1.f, d1 = 1.f;
    float oacc[8][4];
    #pragma unroll
    for (int i = 0; i < 8; i++)
        #pragma unroll
        for (int j = 0; j < 4; j++) oacc[i][j] = 0.f;

    const int i0 = q0 + 16 * wid + g8;
    const int i1 = i0 + 8;
    const int rmin = q0 + 16 * wid;          // warp's min row
    const int rmax = rmin + 15;              // warp's max row
    const int kt_lo = (q0 >= SW_) ? ((q0 - SW_ + 1) >> 6) : 0;
    const int kt_hi = q0 >> 6;

    for (int kt = kt_lo; kt <= kt_hi; kt++) {
        const int k0 = kt << 6;
        __syncthreads();
        #pragma unroll
        for (int v = 0; v < 4; v++) {
            int idx = tid + 128 * v;
            int r = idx >> 3, f = (idx & 7) * 4;
            unsigned da = ub + (unsigned)((r * 36 + f) << 2);
            int so = (k0 + r) * 32 + f;
            cpa16(da + AKH * 4, Khg + so);
            cpa16(da + AKL * 4, Klg + so);
            cpa16(da + AVH * 4, Vhg + so);
            cpa16(da + AVL * 4, Vlg + so);
        }
        CP_COMMIT(); CP_WAIT0();
        __syncthreads();

        // S = Q K^T (f16 3-pass, base-2 logits); skip fully-masked 16-col blocks
        float sacc[8][4];
        #pragma unroll
        for (int i = 0; i < 8; i++)
            #pragma unroll
            for (int j = 0; j < 4; j++) sacc[i][j] = 0.f;

        #pragma unroll
        for (int p = 0; p < 4; p++) {
            const int c0b = k0 + 16 * p;
            if (c0b > rmax || c0b + 15 < rmin - (SW_ - 1)) continue;   // warp-uniform
            #pragma unroll
            for (int ks = 0; ks < 4; ks++) {
                unsigned kh0, kh1, kh2, kh3, kl0, kl1, kl2, kl3;
                unsigned ad = kBase + (unsigned)((p * 576 + ks * 8) << 2);
                ldsm4(kh0, kh1, kh2, kh3, ad);
                ldsm4(kl0, kl1, kl2, kl3, ad + (unsigned)((AKL - AKH) << 2));
                mma16816h(sacc[2*p],   qh[ks][0], qh[ks][1], qh[ks][2], qh[ks][3], kh0, kh1);
                mma16816h(sacc[2*p+1], qh[ks][0], qh[ks][1], qh[ks][2], qh[ks][3], kh2, kh3);
                mma16816h(sacc[2*p],   qh[ks][0], qh[ks][1], qh[ks][2], qh[ks][3], kl0, kl1);
                mma16816h(sacc[2*p+1], qh[ks][0], qh[ks][1], qh[ks][2], qh[ks][3], kl2, kl3);
                mma16816h(sacc[2*p],   ql[ks][0], ql[ks][1], ql[ks][2], ql[ks][3], kh0, kh1);
                mma16816h(sacc[2*p+1], ql[ks][0], ql[ks][1], ql[ks][2], ql[ks][3], kh2, kh3);
            }
        }

        // mask + row max
        float mx0 = -1e30f, mx1 = -1e30f;
        #pragma unroll
        for (int ni = 0; ni < 8; ni++) {
            int j = k0 + 8 * ni + 2 * qid;
            sacc[ni][0] = (j     <= i0 && j     > i0 - SW_) ? sacc[ni][0] : -1e30f;
            sacc[ni][1] = (j + 1 <= i0 && j + 1 > i0 - SW_) ? sacc[ni][1] : -1e30f;
            sacc[ni][2] = (j     <= i1 && j     > i1 - SW_) ? sacc[ni][2] : -1e30f;
            sacc[ni][3] = (j + 1 <= i1 && j + 1 > i1 - SW_) ? sacc[ni][3] : -1e30f;
            mx0 = fmaxf(mx0, fmaxf(sacc[ni][0], sacc[ni][1]));
            mx1 = fmaxf(mx1, fmaxf(sacc[ni][2], sacc[ni][3]));
        }
        mx0 = fmaxf(mx0, __shfl_xor_sync(0xffffffffu, mx0, 1));
        mx0 = fmaxf(mx0, __shfl_xor_sync(0xffffffffu, mx0, 2));
        mx1 = fmaxf(mx1, __shfl_xor_sync(0xffffffffu, mx1, 1));
        mx1 = fmaxf(mx1, __shfl_xor_sync(0xffffffffu, mx1, 2));
        float mn0 = fmaxf(m0, mx0), mn1 = fmaxf(m1, mx1);
        float sc0 = ex2f(m0 - mn0), sc1 = ex2f(m1 - mn1);
        m0 = mn0; m1 = mn1; d0 *= sc0; d1 *= sc1;
        #pragma unroll
        for (int nd = 0; nd < 8; nd++) {
            oacc[nd][0] *= sc0; oacc[nd][1] *= sc0;
            oacc[nd][2] *= sc1; oacc[nd][3] *= sc1;
        }

        // e = 2^(s-m), pack to f16 (hi only); accumulate row sums
        unsigned pfh[8][2];
        float t0 = 0.f, t1 = 0.f;
        #pragma unroll
        for (int ni = 0; ni < 8; ni++) {
            float e0 = ex2f(fmaxf(sacc[ni][0] - mn0, -126.f));
            float e1 = ex2f(fmaxf(sacc[ni][1] - mn0, -126.f));
            float e2 = ex2f(fmaxf(sacc[ni][2] - mn1, -126.f));
            float e3 = ex2f(fmaxf(sacc[ni][3] - mn1, -126.f));
            t0 += e0 + e1; t1 += e2 + e3;
            pfh[ni][0] = packh(e0, e1);
            pfh[ni][1] = packh(e2, e3);
        }
        t0 += __shfl_xor_sync(0xffffffffu, t0, 1);
        t0 += __shfl_xor_sync(0xffffffffu, t0, 2);
        t1 += __shfl_xor_sync(0xffffffffu, t1, 1);
        t1 += __shfl_xor_sync(0xffffffffu, t1, 2);
        d0 += t0; d1 += t1;

        // O += P V (2-pass: Phi*Vhi + Phi*Vlo); skip fully-masked kf blocks
        #pragma unroll
        for (int kf = 0; kf < 4; kf++) {
            const int c0b = k0 + 16 * kf;
            if (c0b > rmax || c0b + 15 < rmin - (SW_ - 1)) continue;   // warp-uniform
            unsigned a0 = pfh[2*kf][0], a1 = pfh[2*kf][1];
            unsigned a2 = pfh[2*kf+1][0], a3 = pfh[2*kf+1][1];
            #pragma unroll
            for (int p = 0; p < 4; p++) {
                unsigned vh0, vh1, vh2, vh3, vl0, vl1, vl2, vl3;
                unsigned ad = vBase + (unsigned)((kf * 576 + p * 8) << 2);
                ldsm4t(vh0, vh1, vh2, vh3, ad);
                ldsm4t(vl0, vl1, vl2, vl3, ad + (unsigned)((AVL - AVH) << 2));
                mma16816h(oacc[2*p],   a0, a1, a2, a3, vh0, vh1);
                mma16816h(oacc[2*p+1], a0, a1, a2, a3, vh2, vh3);
                mma16816h(oacc[2*p],   a0, a1, a2, a3, vl0, vl1);
                mma16816h(oacc[2*p+1], a0, a1, a2, a3, vl2, vl3);
            }
        }
    }

    // epilogue: AO blocked [kc][4096 rows][16 words], f16 split
    float inv0 = 1.f / d0, inv1 = 1.f / d1;
    #pragma unroll
    for (int nd = 0; nd < 8; nd++) {
        int col = 64 * h + 8 * nd + 2 * qid;
        int kc = col >> 5, wic = (col & 31) >> 1;
        unsigned hi, lo;
        splitf16(oacc[nd][0] * inv0, oacc[nd][1] * inv0, hi, lo);
        size_t w0 = (size_t)kc * CS_X + (size_t)(b * N_ + i0) * 16 + wic;
        g_AOh[w0] = hi; g_AOl[w0] = lo;
        splitf16(oacc[nd][2] * inv1, oacc[nd][3] * inv1, hi, lo);
        size_t w1 = (size_t)kc * CS_X + (size_t)(b * N_ + i1) * 16 + wic;
        g_AOh[w1] = hi; g_AOl[w1] = lo;
    }
}

extern "C" void kernel_launch(void* const* d_in, const int* in_sizes, int n_in,
                              void* d_out, int out_size)
{
    const float* x      = (const float*)d_in[0];
    const float* qkv_w  = (const float*)d_in[1];
    const float* qn_w   = (const float*)d_in[2];
    const float* qn_b   = (const float*)d_in[3];
    const float* kn_w   = (const float*)d_in[4];
    const float* kn_b   = (const float*)d_in[5];
    const float* sinks  = (const float*)d_in[6];
    const float* proj_w = (const float*)d_in[7];
    const float* proj_b = (const float*)d_in[8];
    float* out = (float*)d_out;

    cudaFuncSetAttribute(qkv_mm,  cudaFuncAttributeMaxDynamicSharedMemorySize, GEMM_SMEM);
    cudaFuncSetAttribute(proj_mm, cudaFuncAttributeMaxDynamicSharedMemorySize, GEMM_SMEM);
    cudaFuncSetAttribute(attn_tc, cudaFuncAttributeMaxDynamicSharedMemorySize, ATT_SMEM);

    presplit_all<<<dim3(1024, 4), 256>>>((const float4*)x, (const float4*)qkv_w,
                                         (const float4*)proj_w);
    qkv_mm<<<dim3(24, 32), 256, GEMM_SMEM>>>(qn_w, qn_b, kn_w, kn_b);
    attn_tc<<<dim3(16, 64), 128, ATT_SMEM>>>(sinks);
    proj_mm<<<dim3(8, 32), 256, GEMM_SMEM>>>(proj_b, out);
}

// round 14
// speedup vs baseline: 1.3904x; 1.2209x over previous
#include <cuda_runtime.h>
#include <cuda_bf16.h>
#include <cuda_fp16.h>
#include <math.h>
#include <cstdint>

#define B_   4
#define N_   1024
#define DIM_ 1024
#define H_   16
#define D_   64
#define SW_  256
#define LOG2E  1.4426950408889634f
#define QSCALE 0.18033688011112042f   // sm_scale * log2(e)

// ---------------- device globals (word = 2 f16) ----------------
// x/w/pw/AO stored CHUNK-BLOCKED: [kc][row][16 words] (kc = K/32 chunks)
__device__ unsigned g_xh[2097152],  g_xl[2097152];    // x      4096x1024 f16 split
__device__ unsigned g_wh[1572864],  g_wl[1572864];    // qkv_w  3072x1024 f16 split
__device__ unsigned g_pwh[524288],  g_pwl[524288];    // proj_w 1024x1024 f16 split
__device__ unsigned g_Qh[2097152];                    // [b,h,n,d] f16 (pre-scaled)
__device__ unsigned g_Kh[2097152],  g_Kl[2097152];    // [b,h,n,d] f16 split
__device__ unsigned g_Vh[2097152],  g_Vl[2097152];    // [b,h,n,d] f16 split
__device__ unsigned g_AOh[2097152], g_AOl[2097152];   // blocked [kc][4096][16] f16 split
__device__ float2  g_rope[32768];                     // [n][j] (cos, sin), j<32

#define CS_X  65536     // chunk stride (words): 4096 rows * 16
#define CS_W  49152     // 3072 * 16
#define CS_P  16384     // 1024 * 16

// ---------------- helpers ----------------
__device__ __forceinline__ void splitf16(float x, float y, unsigned &hi, unsigned &lo) {
    __half hx = __float2half_rn(x), hy = __float2half_rn(y);
    float rx = x - __half2float(hx);
    float ry = y - __half2float(hy);
    __half lx = __float2half_rn(rx), ly = __float2half_rn(ry);
    hi = ((unsigned)__half_as_ushort(hy) << 16) | (unsigned)__half_as_ushort(hx);
    lo = ((unsigned)__half_as_ushort(ly) << 16) | (unsigned)__half_as_ushort(lx);
}
__device__ __forceinline__ unsigned packh(float x, float y) {
    __half hx = __float2half_rn(x), hy = __float2half_rn(y);
    return ((unsigned)__half_as_ushort(hy) << 16) | (unsigned)__half_as_ushort(hx);
}
__device__ __forceinline__ void mma16816h(float* c, unsigned a0, unsigned a1,
                                          unsigned a2, unsigned a3,
                                          unsigned b0, unsigned b1) {
    asm volatile(
        "mma.sync.aligned.m16n8k16.row.col.f32.f16.f16.f32 "
        "{%0,%1,%2,%3}, {%4,%5,%6,%7}, {%8,%9}, {%0,%1,%2,%3};"
        : "+f"(c[0]), "+f"(c[1]), "+f"(c[2]), "+f"(c[3])
        : "r"(a0), "r"(a1), "r"(a2), "r"(a3), "r"(b0), "r"(b1));
}
__device__ __forceinline__ void ldsm4(unsigned &r0, unsigned &r1, unsigned &r2,
                                      unsigned &r3, unsigned addr) {
    asm volatile("ldmatrix.sync.aligned.m8n8.x4.shared.b16 {%0,%1,%2,%3}, [%4];"
                 : "=r"(r0), "=r"(r1), "=r"(r2), "=r"(r3) : "r"(addr));
}
__device__ __forceinline__ void ldsm4t(unsigned &r0, unsigned &r1, unsigned &r2,
                                       unsigned &r3, unsigned addr) {
    asm volatile("ldmatrix.sync.aligned.m8n8.x4.trans.shared.b16 {%0,%1,%2,%3}, [%4];"
                 : "=r"(r0), "=r"(r1), "=r"(r2), "=r"(r3) : "r"(addr));
}
__device__ __forceinline__ float ex2f(float x) {
    float y; asm("ex2.approx.f32 %0, %1;" : "=f"(y) : "f"(x)); return y;
}
__device__ __forceinline__ unsigned smem_u32(const void* p){
    unsigned a;
    asm("{ .reg .u64 t; cvta.to.shared.u64 t, %1; cvt.u32.u64 %0, t; }" : "=r"(a) : "l"(p));
    return a;
}
__device__ __forceinline__ void cpa16(unsigned daddr, const void* g){
    asm volatile("cp.async.cg.shared.global [%0], [%1], 16;" :: "r"(daddr), "l"(g) : "memory");
}
#define CP_COMMIT() asm volatile("cp.async.commit_group;" ::: "memory")
#define CP_WAIT0()  asm volatile("cp.async.wait_group 0;" ::: "memory")

// ---------------- presplit: fp32 -> f16 hi/lo, chunk-blocked; + rope table ----
__global__ void presplit_all(const float4* __restrict__ x,
                             const float4* __restrict__ w,
                             const float4* __restrict__ pw)
{
    if (blockIdx.y == 3) {
        for (int i = blockIdx.x * blockDim.x + threadIdx.x; i < 32768;
             i += gridDim.x * blockDim.x) {
            int n = i >> 5, j = i & 31;
            float invf = expf(-(float)j * 0.2878231366242557f);  // 10000^(-j/32)
            float sn, cs;
            sincosf((float)n * invf, &sn, &cs);
            g_rope[i] = make_float2(cs, sn);
        }
        return;
    }
    const float4* s; unsigned *hp, *lp; int rows;
    if (blockIdx.y == 0)      { s = x;  hp = g_xh;  lp = g_xl;  rows = 4096; }
    else if (blockIdx.y == 1) { s = w;  hp = g_wh;  lp = g_wl;  rows = 3072; }
    else                      { s = pw; hp = g_pwh; lp = g_pwl; rows = 1024; }
    const int n4 = rows * 256;
    for (int i = blockIdx.x * blockDim.x + threadIdx.x; i < n4; i += gridDim.x * blockDim.x) {
        float4 f = s[i];
        unsigned h0, l0, h1, l1;
        splitf16(f.x, f.y, h0, l0);
        splitf16(f.z, f.w, h1, l1);
        int r = i >> 8, c4 = i & 255;
        int kc = c4 >> 3, wic = (c4 & 7) * 2;
        size_t dw = (size_t)kc * rows * 16 + (size_t)r * 16 + wic;
        *(uint2*)(hp + dw) = make_uint2(h0, h1);
        *(uint2*)(lp + dw) = make_uint2(l0, l1);
    }
}

// ------------- GEMM mainloop: 3-stage, swizzled 16-word rows, 1 barrier/chunk --
// 2-pass: C = Ah*Bh + Al*Bh (B single f16, err ~2e-4 rel)
#define STG_W  8192
#define O_ALO  2048
#define O_BHI  4096
#define GEMM_SMEM 98304     // 3 stages * 32768 B (BLO slot unused)

__device__ __forceinline__ void mainloop_pre(
    const unsigned* __restrict__ gAh, const unsigned* __restrict__ gAl,
    const unsigned* __restrict__ gBh,
    int row0, int col0, int csA, int csB, unsigned* u, float acc[4][4][4])
{
    const int tid = threadIdx.x;
    const int wid = tid >> 5, lane = tid & 31;
    const int wm = wid >> 2, wn = wid & 3;
    const int lq = lane >> 3, lr = lane & 7;
    const int lqh = lq >> 1, lql = lq & 1;
    const unsigned ub = smem_u32(u);

    int dof[2];
    const unsigned* aP[2]; const unsigned* bP[2];
    #pragma unroll
    for (int v = 0; v < 2; v++) {
        int q = tid + 256 * v;               // 0..511
        int r = q >> 2, qd = q & 3;
        dof[v] = r * 16 + ((qd ^ ((r >> 1) & 3)) << 2);
        aP[v] = gAh + (size_t)(row0 + r) * 16 + qd * 4;
        bP[v] = gBh + (size_t)(col0 + r) * 16 + qd * 4;
    }
    const ptrdiff_t dAl = gAl - gAh;

    const int rowA = 64 * wm + lql * 8 + lr;
    const int xrA  = (rowA >> 1) & 3;
    const unsigned aRow = ub + (unsigned)(rowA * 64);
    const unsigned qa0 = (unsigned)(((lqh    ) ^ xrA) << 4);
    const unsigned qa1 = (unsigned)(((lqh + 2) ^ xrA) << 4);
    const int rowB = 32 * wn + lqh * 8 + lr;
    const int xrB  = (rowB >> 1) & 3;
    const unsigned bRow = ub + (unsigned)(O_BHI * 4 + rowB * 64);
    const unsigned qb0 = (unsigned)(((lql    ) ^ xrB) << 4);
    const unsigned qb1 = (unsigned)(((lql + 2) ^ xrB) << 4);

    auto fill = [&](int stage, int cidx) {
        const int oa = cidx * csA, ob = cidx * csB;
        #pragma unroll
        for (int v = 0; v < 2; v++) {
            unsigned da = ub + (unsigned)((stage * STG_W + dof[v]) << 2);
            cpa16(da,               aP[v] + oa);
            cpa16(da + O_ALO * 4,   aP[v] + oa + dAl);
            cpa16(da + O_BHI * 4,   bP[v] + ob);
        }
        CP_COMMIT();
    };

    fill(0, 0);
    fill(1, 1);

    int stc = 0, stf = 2;
    for (int c = 0; c < 32; c++) {
        if (c < 31) asm volatile("cp.async.wait_group 1;" ::: "memory");
        else        asm volatile("cp.async.wait_group 0;" ::: "memory");
        __syncthreads();
        if (c + 2 < 32) { fill(stf, c + 2); stf = (stf == 2) ? 0 : stf + 1; }

        const unsigned so = (unsigned)(stc * (STG_W << 2));
        stc = (stc == 2) ? 0 : stc + 1;

        #pragma unroll
        for (int ks = 0; ks < 2; ks++) {
            const unsigned qa = ks ? qa1 : qa0;
            const unsigned qb = ks ? qb1 : qb0;
            unsigned bhf[2][4];
            #pragma unroll
            for (int p = 0; p < 2; p++) {
                unsigned ad = bRow + so + (unsigned)(p * 1024) + qb;
                ldsm4(bhf[p][0], bhf[p][1], bhf[p][2], bhf[p][3], ad);
            }
            #pragma unroll
            for (int mi = 0; mi < 4; mi++) {
                unsigned ad = aRow + so + (unsigned)(mi * 1024) + qa;
                unsigned ah0, ah1, ah2, ah3, al0, al1, al2, al3;
                ldsm4(ah0, ah1, ah2, ah3, ad);
                ldsm4(al0, al1, al2, al3, ad + 8192);
                mma16816h(acc[mi][0], ah0, ah1, ah2, ah3, bhf[0][0], bhf[0][1]);
                mma16816h(acc[mi][1], ah0, ah1, ah2, ah3, bhf[0][2], bhf[0][3]);
                mma16816h(acc[mi][2], ah0, ah1, ah2, ah3, bhf[1][0], bhf[1][1]);
                mma16816h(acc[mi][3], ah0, ah1, ah2, ah3, bhf[1][2], bhf[1][3]);
                mma16816h(acc[mi][0], al0, al1, al2, al3, bhf[0][0], bhf[0][1]);
                mma16816h(acc[mi][1], al0, al1, al2, al3, bhf[0][2], bhf[0][3]);
                mma16816h(acc[mi][2], al0, al1, al2, al3, bhf[1][0], bhf[1][1]);
                mma16816h(acc[mi][3], al0, al1, al2, al3, bhf[1][2], bhf[1][3]);
            }
        }
    }
    __syncthreads();
}

// ---------------- Kernel 1: QKV GEMM + LN + RoPE + split-store ----------------
__global__ __launch_bounds__(256, 2) void qkv_mm(
    const float* __restrict__ qn_w, const float* __restrict__ qn_b,
    const float* __restrict__ kn_w, const float* __restrict__ kn_b)
{
    extern __shared__ __align__(16) unsigned u[];
    const int tid = threadIdx.x;
    const int wid = tid >> 5, lane = tid & 31;
    const int wm = wid >> 2, wn = wid & 3;
    const int grp = lane >> 2, qid = lane & 3;
    const int row0 = blockIdx.y * 128;
    const int col0 = blockIdx.x * 128;

    float acc[4][4][4];
    #pragma unroll
    for (int i = 0; i < 4; i++)
        #pragma unroll
        for (int j = 0; j < 4; j++)
            #pragma unroll
            for (int k = 0; k < 4; k++) acc[i][j][k] = 0.f;

    mainloop_pre(g_xh, g_xl, g_wh, row0, col0, CS_X, CS_W, u, acc);

    // stage 128x128 f32 tile (stride 132)
    float* stg = (float*)u;
    #pragma unroll
    for (int mi = 0; mi < 4; mi++) {
        int rr2 = 64 * wm + 16 * mi + grp;
        #pragma unroll
        for (int ni = 0; ni < 4; ni++) {
            int cc = 32 * wn + 8 * ni + 2 * qid;
            stg[rr2 * 132 + cc]           = acc[mi][ni][0];
            stg[rr2 * 132 + cc + 1]       = acc[mi][ni][1];
            stg[(rr2 + 8) * 132 + cc]     = acc[mi][ni][2];
            stg[(rr2 + 8) * 132 + cc + 1] = acc[mi][ni][3];
        }
    }
    __syncthreads();

    const int hh = tid >> 7, r = tid & 127;
    float d[64];
    const float* src = stg + r * 132 + hh * 64;
    #pragma unroll
    for (int j = 0; j < 16; j++) {
        float4 v = *(const float4*)(src + 4 * j);
        d[4*j] = v.x; d[4*j+1] = v.y; d[4*j+2] = v.z; d[4*j+3] = v.w;
    }

    const int t = col0 >> 10;                      // 0=q,1=k,2=v
    const int h = ((col0 & 1023) >> 6) + hh;
    const int grow = row0 + r;
    const int b = grow >> 10, n = grow & 1023;
    const size_t wbase = ((size_t)(b * H_ + h) * N_ + n) * 32;   // word offset

    unsigned hw[32], lw2[32];
    if (t == 2) {
        #pragma unroll
        for (int cpair = 0; cpair < 32; cpair++)
            splitf16(d[2*cpair], d[2*cpair+1], hw[cpair], lw2[cpair]);
        #pragma unroll
        for (int q8 = 0; q8 < 8; q8++) {
            *(uint4*)(g_Vh + wbase + 4*q8) = make_uint4(hw[4*q8], hw[4*q8+1], hw[4*q8+2], hw[4*q8+3]);
            *(uint4*)(g_Vl + wbase + 4*q8) = make_uint4(lw2[4*q8], lw2[4*q8+1], lw2[4*q8+2], lw2[4*q8+3]);
        }
        return;
    }

    const float* lw = t ? kn_w : qn_w;
    const float* lb = t ? kn_b : qn_b;
    float s1 = 0.f, s2 = 0.f;
    #pragma unroll
    for (int j = 0; j < 64; j++) { s1 += d[j]; s2 += d[j] * d[j]; }
    float mu = s1 * (1.f / 64.f);
    float var = s2 * (1.f / 64.f) - mu * mu;
    float rstd = rsqrtf(var + 1e-5f);
    #pragma unroll
    for (int j = 0; j < 64; j++)
        d[j] = (d[j] - mu) * rstd * __ldg(lw + j) + __ldg(lb + j);
    const float2* rt = g_rope + n * 32;
    #pragma unroll
    for (int j = 0; j < 32; j++) {
        float2 cs = __ldg(rt + j);
        float t0 = d[j];
        d[j]      = t0 * cs.x - d[j + 32] * cs.y;
        d[j + 32] = d[j + 32] * cs.x + t0 * cs.y;
    }
    if (t == 0) {
        // Q: single f16 (pre-scaled); lo not stored
        #pragma unroll
        for (int cpair = 0; cpair < 32; cpair++)
            hw[cpair] = packh(d[2*cpair] * QSCALE, d[2*cpair+1] * QSCALE);
        #pragma unroll
        for (int q8 = 0; q8 < 8; q8++)
            *(uint4*)(g_Qh + wbase + 4*q8) = make_uint4(hw[4*q8], hw[4*q8+1], hw[4*q8+2], hw[4*q8+3]);
        return;
    }
    #pragma unroll
    for (int cpair = 0; cpair < 32; cpair++)
        splitf16(d[2*cpair], d[2*cpair+1], hw[cpair], lw2[cpair]);
    #pragma unroll
    for (int q8 = 0; q8 < 8; q8++) {
        *(uint4*)(g_Kh + wbase + 4*q8) = make_uint4(hw[4*q8], hw[4*q8+1], hw[4*q8+2], hw[4*q8+3]);
        *(uint4*)(g_Kl + wbase + 4*q8) = make_uint4(lw2[4*q8], lw2[4*q8+1], lw2[4*q8+2], lw2[4*q8+3]);
    }
}

// ---------------- Kernel 3: proj GEMM + bias (2-pass) ----------------
__global__ __launch_bounds__(256, 2) void proj_mm(
    const float* __restrict__ bias, float* __restrict__ out)
{
    extern __shared__ __align__(16) unsigned u[];
    const int tid = threadIdx.x;
    const int wid = tid >> 5, lane = tid & 31;
    const int wm = wid >> 2, wn = wid & 3;
    const int grp = lane >> 2, qid = lane & 3;
    const int row0 = blockIdx.y * 128;
    const int col0 = blockIdx.x * 128;

    float acc[4][4][4];
    #pragma unroll
    for (int i = 0; i < 4; i++)
        #pragma unroll
        for (int j = 0; j < 4; j++)
            #pragma unroll
            for (int k = 0; k < 4; k++) acc[i][j][k] = 0.f;

    mainloop_pre(g_AOh, g_AOl, g_pwh, row0, col0, CS_X, CS_P, u, acc);

    #pragma unroll
    for (int mi = 0; mi < 4; mi++) {
        int rr = row0 + 64 * wm + 16 * mi + grp;
        #pragma unroll
        for (int ni = 0; ni < 4; ni++) {
            int cc = col0 + 32 * wn + 8 * ni + 2 * qid;
            float b0 = __ldg(bias + cc), b1 = __ldg(bias + cc + 1);
            *(float2*)(out + (size_t)rr * DIM_ + cc) =
                make_float2(acc[mi][ni][0] + b0, acc[mi][ni][1] + b1);
            *(float2*)(out + (size_t)(rr + 8) * DIM_ + cc) =
                make_float2(acc[mi][ni][2] + b0, acc[mi][ni][3] + b1);
        }
    }
}

// ------ Kernel 2: flash attention (Q single f16; QK 2-pass; PV 2-pass) --------
// smem word offsets: Qh, Kh, Kl, Vh, Vl each 64 rows x 36 words
#define AQH 0
#define AKH 2304
#define AKL 4608
#define AVH 6912
#define AVL 9216
#define ATT_SMEM 46080

__global__ __launch_bounds__(128) void attn_tc(const float* __restrict__ sinks)
{
    extern __shared__ __align__(16) unsigned u[];
    const int tid = threadIdx.x;
    const int wid = tid >> 5, lane = tid & 31;
    const int g8 = lane >> 2, qid = lane & 3;
    const int lq = lane >> 3, lr = lane & 7;
    const int bh = blockIdx.y, b = bh >> 4, h = bh & 15;
    const int q0 = blockIdx.x * 64;
    const unsigned ub = smem_u32(u);

    const size_t base = (size_t)(b * H_ + h) * N_ * 32;   // word base of this (b,h)
    const unsigned* Qhg = g_Qh + base + (size_t)q0 * 32;
    const unsigned* Khg = g_Kh + base;
    const unsigned* Klg = g_Kl + base;
    const unsigned* Vhg = g_Vh + base;
    const unsigned* Vlg = g_Vl + base;

    #pragma unroll
    for (int v = 0; v < 4; v++) {
        int idx = tid + 128 * v;          // 0..511
        int r = idx >> 3, f = (idx & 7) * 4;
        unsigned da = ub + (unsigned)((r * 36 + f) << 2);
        cpa16(da + AQH * 4, Qhg + r * 32 + f);
    }
    CP_COMMIT(); CP_WAIT0();
    __syncthreads();

    // hoist Q fragments (loop-invariant over kt)
    unsigned qh[4][4];
    const unsigned qBase = ub + ((AQH + (16 * wid + (lq & 1) * 8 + lr) * 36 + (lq >> 1) * 4) << 2);
    #pragma unroll
    for (int ks = 0; ks < 4; ks++)
        ldsm4(qh[ks][0], qh[ks][1], qh[ks][2], qh[ks][3], qBase + (unsigned)((ks * 8) << 2));

    const unsigned kBase = ub + ((AKH + ((lq >> 1) * 8 + lr) * 36 + (lq & 1) * 4) << 2);
    const unsigned vBase = ub + ((AVH + ((lq & 1) * 8 + lr) * 36 + (lq >> 1) * 4) << 2);

    float m0 = __ldg(sinks + h) * LOG2E, m1 = m0;
    float d0 = 1.f, d1 = 1.f;
    float oacc[8][4];
    #pragma unroll
    for (int i = 0; i < 8; i++)
        #pragma unroll
        for (int j = 0; j < 4; j++) oacc[i][j] = 0.f;

    const int i0 = q0 + 16 * wid + g8;
    const int i1 = i0 + 8;
    const int rmin = q0 + 16 * wid;          // warp's min row
    const int rmax = rmin + 15;              // warp's max row
    const int kt_lo = (q0 >= SW_) ? ((q0 - SW_ + 1) >> 6) : 0;
    const int kt_hi = q0 >> 6;

    for (int kt = kt_lo; kt <= kt_hi; kt++) {
        const int k0 = kt << 6;
        __syncthreads();
        #pragma unroll
        for (int v = 0; v < 4; v++) {
            int idx = tid + 128 * v;
            int r = idx >> 3, f = (idx & 7) * 4;
            unsigned da = ub + (unsigned)((r * 36 + f) << 2);
            int so = (k0 + r) * 32 + f;
            cpa16(da + AKH * 4, Khg + so);
            cpa16(da + AKL * 4, Klg + so);
            cpa16(da + AVH * 4, Vhg + so);
            cpa16(da + AVL * 4, Vlg + so);
        }
        CP_COMMIT(); CP_WAIT0();
        __syncthreads();

        // S = Q K^T (2-pass: Qh*Kh + Qh*Kl); skip fully-masked 16-col blocks
        float sacc[8][4];
        #pragma unroll
        for (int i = 0; i < 8; i++)
            #pragma unroll
            for (int j = 0; j < 4; j++) sacc[i][j] = 0.f;

        #pragma unroll
        for (int p = 0; p < 4; p++) {
            const int c0b = k0 + 16 * p;
            if (c0b > rmax || c0b + 15 < rmin - (SW_ - 1)) continue;   // warp-uniform
            #pragma unroll
            for (int ks = 0; ks < 4; ks++) {
                unsigned kh0, kh1, kh2, kh3, kl0, kl1, kl2, kl3;
                unsigned ad = kBase + (unsigned)((p * 576 + ks * 8) << 2);
                ldsm4(kh0, kh1, kh2, kh3, ad);
                ldsm4(kl0, kl1, kl2, kl3, ad + (unsigned)((AKL - AKH) << 2));
                mma16816h(sacc[2*p],   qh[ks][0], qh[ks][1], qh[ks][2], qh[ks][3], kh0, kh1);
                mma16816h(sacc[2*p+1], qh[ks][0], qh[ks][1], qh[ks][2], qh[ks][3], kh2, kh3);
                mma16816h(sacc[2*p],   qh[ks][0], qh[ks][1], qh[ks][2], qh[ks][3], kl0, kl1);
                mma16816h(sacc[2*p+1], qh[ks][0], qh[ks][1], qh[ks][2], qh[ks][3], kl2, kl3);
            }
        }

        // mask + row max
        float mx0 = -1e30f, mx1 = -1e30f;
        #pragma unroll
        for (int ni = 0; ni < 8; ni++) {
            int j = k0 + 8 * ni + 2 * qid;
            sacc[ni][0] = (j     <= i0 && j     > i0 - SW_) ? sacc[ni][0] : -1e30f;
            sacc[ni][1] = (j + 1 <= i0 && j + 1 > i0 - SW_) ? sacc[ni][1] : -1e30f;
            sacc[ni][2] = (j     <= i1 && j     > i1 - SW_) ? sacc[ni][2] : -1e30f;
            sacc[ni][3] = (j + 1 <= i1 && j + 1 > i1 - SW_) ? sacc[ni][3] : -1e30f;
            mx0 = fmaxf(mx0, fmaxf(sacc[ni][0], sacc[ni][1]));
            mx1 = fmaxf(mx1, fmaxf(sacc[ni][2], sacc[ni][3]));
        }
        mx0 = fmaxf(mx0, __shfl_xor_sync(0xffffffffu, mx0, 1));
        mx0 = fmaxf(mx0, __shfl_xor_sync(0xffffffffu, mx0, 2));
        mx1 = fmaxf(mx1, __shfl_xor_sync(0xffffffffu, mx1, 1));
        mx1 = fmaxf(mx1, __shfl_xor_sync(0xffffffffu, mx1, 2));
        float mn0 = fmaxf(m0, mx0), mn1 = fmaxf(m1, mx1);
        float sc0 = ex2f(m0 - mn0), sc1 = ex2f(m1 - mn1);
        m0 = mn0; m1 = mn1; d0 *= sc0; d1 *= sc1;
        #pragma unroll
        for (int nd = 0; nd < 8; nd++) {
            oacc[nd][0] *= sc0; oacc[nd][1] *= sc0;
            oacc[nd][2] *= sc1; oacc[nd][3] *= sc1;
        }

        // e = 2^(s-m), pack to f16 (hi only); accumulate row sums
        unsigned pfh[8][2];
        float t0 = 0.f, t1 = 0.f;
        #pragma unroll
        for (int ni = 0; ni < 8; ni++) {
            float e0 = ex2f(fmaxf(sacc[ni][0] - mn0, -126.f));
            float e1 = ex2f(fmaxf(sacc[ni][1] - mn0, -126.f));
            float e2 = ex2f(fmaxf(sacc[ni][2] - mn1, -126.f));
            float e3 = ex2f(fmaxf(sacc[ni][3] - mn1, -126.f));
            t0 += e0 + e1; t1 += e2 + e3;
            pfh[ni][0] = packh(e0, e1);
            pfh[ni][1] = packh(e2, e3);
        }
        t0 += __shfl_xor_sync(0xffffffffu, t0, 1);
        t0 += __shfl_xor_sync(0xffffffffu, t0, 2);
        t1 += __shfl_xor_sync(0xffffffffu, t1, 1);
        t1 += __shfl_xor_sync(0xffffffffu, t1, 2);
        d0 += t0; d1 += t1;

        // O += P V (2-pass: Phi*Vhi + Phi*Vlo); skip fully-masked kf blocks
        #pragma unroll
        for (int kf = 0; kf < 4; kf++) {
            const int c0b = k0 + 16 * kf;
            if (c0b > rmax || c0b + 15 < rmin - (SW_ - 1)) continue;   // warp-uniform
            unsigned a0 = pfh[2*kf][0], a1 = pfh[2*kf][1];
            unsigned a2 = pfh[2*kf+1][0], a3 = pfh[2*kf+1][1];
            #pragma unroll
            for (int p = 0; p < 4; p++) {
                unsigned vh0, vh1, vh2, vh3, vl0, vl1, vl2, vl3;
                unsigned ad = vBase + (unsigned)((kf * 576 + p * 8) << 2);
                ldsm4t(vh0, vh1, vh2, vh3, ad);
                ldsm4t(vl0, vl1, vl2, vl3, ad + (unsigned)((AVL - AVH) << 2));
                mma16816h(oacc[2*p],   a0, a1, a2, a3, vh0, vh1);
                mma16816h(oacc[2*p+1], a0, a1, a2, a3, vh2, vh3);
                mma16816h(oacc[2*p],   a0, a1, a2, a3, vl0, vl1);
                mma16816h(oacc[2*p+1], a0, a1, a2, a3, vl2, vl3);
            }
        }
    }

    // epilogue: AO blocked [kc][4096 rows][16 words], f16 split
    float inv0 = 1.f / d0, inv1 = 1.f / d1;
    #pragma unroll
    for (int nd = 0; nd < 8; nd++) {
        int col = 64 * h + 8 * nd + 2 * qid;
        int kc = col >> 5, wic = (col & 31) >> 1;
        unsigned hi, lo;
        splitf16(oacc[nd][0] * inv0, oacc[nd][1] * inv0, hi, lo);
        size_t w0 = (size_t)kc * CS_X + (size_t)(b * N_ + i0) * 16 + wic;
        g_AOh[w0] = hi; g_AOl[w0] = lo;
        splitf16(oacc[nd][2] * inv1, oacc[nd][3] * inv1, hi, lo);
        size_t w1 = (size_t)kc * CS_X + (size_t)(b * N_ + i1) * 16 + wic;
        g_AOh[w1] = hi; g_AOl[w1] = lo;
    }
}

extern "C" void kernel_launch(void* const* d_in, const int* in_sizes, int n_in,
                              void* d_out, int out_size)
{
    const float* x      = (const float*)d_in[0];
    const float* qkv_w  = (const float*)d_in[1];
    const float* qn_w   = (const float*)d_in[2];
    const float* qn_b   = (const float*)d_in[3];
    const float* kn_w   = (const float*)d_in[4];
    const float* kn_b   = (const float*)d_in[5];
    const float* sinks  = (const float*)d_in[6];
    const float* proj_w = (const float*)d_in[7];
    const float* proj_b = (const float*)d_in[8];
    float* out = (float*)d_out;

    cudaFuncSetAttribute(qkv_mm,  cudaFuncAttributeMaxDynamicSharedMemorySize, GEMM_SMEM);
    cudaFuncSetAttribute(proj_mm, cudaFuncAttributeMaxDynamicSharedMemorySize, GEMM_SMEM);
    cudaFuncSetAttribute(attn_tc, cudaFuncAttributeMaxDynamicSharedMemorySize, ATT_SMEM);

    presplit_all<<<dim3(1024, 4), 256>>>((const float4*)x, (const float4*)qkv_w,
                                         (const float4*)proj_w);
    qkv_mm<<<dim3(24, 32), 256, GEMM_SMEM>>>(qn_w, qn_b, kn_w, kn_b);
    attn_tc<<<dim3(16, 64), 128, ATT_SMEM>>>(sinks);
    proj_mm<<<dim3(8, 32), 256, GEMM_SMEM>>>(proj_b, out);
}

// round 15
// speedup vs baseline: 1.5833x; 1.1387x over previous
#include <cuda_runtime.h>
#include <cuda_bf16.h>
#include <cuda_fp16.h>
#include <math.h>
#include <cstdint>

#define B_   4
#define N_   1024
#define DIM_ 1024
#define H_   16
#define D_   64
#define SW_  256
#define LOG2E  1.4426950408889634f
#define QSCALE 0.18033688011112042f   // sm_scale * log2(e)

// ---------------- device globals (word = 2 f16) ----------------
// x/w/pw/AO stored CHUNK-BLOCKED: [kc][row][16 words] (kc = K/32 chunks)
__device__ unsigned g_xh[2097152],  g_xl[2097152];    // x      4096x1024 f16 split
__device__ unsigned g_wh[1572864],  g_wl[1572864];    // qkv_w  3072x1024 f16 split
__device__ unsigned g_pwh[524288];                    // proj_w 1024x1024 f16
__device__ unsigned g_Qh[2097152];                    // [b,h,n,d] f16 (pre-scaled)
__device__ unsigned g_Kh[2097152],  g_Kl[2097152];    // [b,h,n,d] f16 split
__device__ unsigned g_Vh[2097152];                    // [b,h,n,d] f16
__device__ unsigned g_AOh[2097152];                   // blocked [kc][4096][16] f16
__device__ float2  g_rope[32768];                     // [n][j] (cos, sin), j<32

#define CS_X  65536     // chunk stride (words): 4096 rows * 16
#define CS_W  49152     // 3072 * 16
#define CS_P  16384     // 1024 * 16

// ---------------- helpers ----------------
__device__ __forceinline__ void splitf16(float x, float y, unsigned &hi, unsigned &lo) {
    __half hx = __float2half_rn(x), hy = __float2half_rn(y);
    float rx = x - __half2float(hx);
    float ry = y - __half2float(hy);
    __half lx = __float2half_rn(rx), ly = __float2half_rn(ry);
    hi = ((unsigned)__half_as_ushort(hy) << 16) | (unsigned)__half_as_ushort(hx);
    lo = ((unsigned)__half_as_ushort(ly) << 16) | (unsigned)__half_as_ushort(lx);
}
__device__ __forceinline__ unsigned packh(float x, float y) {
    __half hx = __float2half_rn(x), hy = __float2half_rn(y);
    return ((unsigned)__half_as_ushort(hy) << 16) | (unsigned)__half_as_ushort(hx);
}
__device__ __forceinline__ void mma16816h(float* c, unsigned a0, unsigned a1,
                                          unsigned a2, unsigned a3,
                                          unsigned b0, unsigned b1) {
    asm volatile(
        "mma.sync.aligned.m16n8k16.row.col.f32.f16.f16.f32 "
        "{%0,%1,%2,%3}, {%4,%5,%6,%7}, {%8,%9}, {%0,%1,%2,%3};"
        : "+f"(c[0]), "+f"(c[1]), "+f"(c[2]), "+f"(c[3])
        : "r"(a0), "r"(a1), "r"(a2), "r"(a3), "r"(b0), "r"(b1));
}
__device__ __forceinline__ void ldsm4(unsigned &r0, unsigned &r1, unsigned &r2,
                                      unsigned &r3, unsigned addr) {
    asm volatile("ldmatrix.sync.aligned.m8n8.x4.shared.b16 {%0,%1,%2,%3}, [%4];"
                 : "=r"(r0), "=r"(r1), "=r"(r2), "=r"(r3) : "r"(addr));
}
__device__ __forceinline__ void ldsm4t(unsigned &r0, unsigned &r1, unsigned &r2,
                                       unsigned &r3, unsigned addr) {
    asm volatile("ldmatrix.sync.aligned.m8n8.x4.trans.shared.b16 {%0,%1,%2,%3}, [%4];"
                 : "=r"(r0), "=r"(r1), "=r"(r2), "=r"(r3) : "r"(addr));
}
__device__ __forceinline__ float ex2f(float x) {
    float y; asm("ex2.approx.f32 %0, %1;" : "=f"(y) : "f"(x)); return y;
}
__device__ __forceinline__ unsigned smem_u32(const void* p){
    unsigned a;
    asm("{ .reg .u64 t; cvta.to.shared.u64 t, %1; cvt.u32.u64 %0, t; }" : "=r"(a) : "l"(p));
    return a;
}
__device__ __forceinline__ void cpa16(unsigned daddr, const void* g){
    asm volatile("cp.async.cg.shared.global [%0], [%1], 16;" :: "r"(daddr), "l"(g) : "memory");
}
#define CP_COMMIT() asm volatile("cp.async.commit_group;" ::: "memory")
#define CP_WAIT0()  asm volatile("cp.async.wait_group 0;" ::: "memory")

// ---------------- presplit: fp32 -> f16 hi/lo, chunk-blocked; + rope table ----
__global__ void presplit_all(const float4* __restrict__ x,
                             const float4* __restrict__ w,
                             const float4* __restrict__ pw)
{
    if (blockIdx.y == 3) {
        for (int i = blockIdx.x * blockDim.x + threadIdx.x; i < 32768;
             i += gridDim.x * blockDim.x) {
            int n = i >> 5, j = i & 31;
            float invf = expf(-(float)j * 0.2878231366242557f);  // 10000^(-j/32)
            float sn, cs;
            sincosf((float)n * invf, &sn, &cs);
            g_rope[i] = make_float2(cs, sn);
        }
        return;
    }
    if (blockIdx.y == 2) {
        // proj_w: single f16
        for (int i = blockIdx.x * blockDim.x + threadIdx.x; i < 262144;
             i += gridDim.x * blockDim.x) {
            float4 f = pw[i];
            int r = i >> 8, c4 = i & 255;
            int kc = c4 >> 3, wic = (c4 & 7) * 2;
            size_t dw = (size_t)kc * 16384 + (size_t)r * 16 + wic;
            *(uint2*)(g_pwh + dw) = make_uint2(packh(f.x, f.y), packh(f.z, f.w));
        }
        return;
    }
    const float4* s; unsigned *hp, *lp; int rows;
    if (blockIdx.y == 0) { s = x; hp = g_xh; lp = g_xl; rows = 4096; }
    else                 { s = w; hp = g_wh; lp = g_wl; rows = 3072; }
    const int n4 = rows * 256;
    for (int i = blockIdx.x * blockDim.x + threadIdx.x; i < n4; i += gridDim.x * blockDim.x) {
        float4 f = s[i];
        unsigned h0, l0, h1, l1;
        splitf16(f.x, f.y, h0, l0);
        splitf16(f.z, f.w, h1, l1);
        int r = i >> 8, c4 = i & 255;
        int kc = c4 >> 3, wic = (c4 & 7) * 2;
        size_t dw = (size_t)kc * rows * 16 + (size_t)r * 16 + wic;
        *(uint2*)(hp + dw) = make_uint2(h0, h1);
        *(uint2*)(lp + dw) = make_uint2(l0, l1);
    }
}

// ------------- GEMM mainloop: 3-stage, swizzled 16-word rows, 1 barrier/chunk --
// twoA=1: C = Ah*Bh + Al*Bh. twoA=0: C = Ah*Bh.
#define STG_W  8192
#define O_ALO  2048
#define O_BHI  4096
#define GEMM_SMEM 98304     // 3 stages * 32768 B

__device__ __forceinline__ void mainloop_pre(
    const unsigned* __restrict__ gAh, const unsigned* __restrict__ gAl,
    const unsigned* __restrict__ gBh,
    int row0, int col0, int csA, int csB, int twoA, unsigned* u, float acc[4][4][4])
{
    const int tid = threadIdx.x;
    const int wid = tid >> 5, lane = tid & 31;
    const int wm = wid >> 2, wn = wid & 3;
    const int lq = lane >> 3, lr = lane & 7;
    const int lqh = lq >> 1, lql = lq & 1;
    const unsigned ub = smem_u32(u);

    int dof[2];
    const unsigned* aP[2]; const unsigned* bP[2];
    #pragma unroll
    for (int v = 0; v < 2; v++) {
        int q = tid + 256 * v;               // 0..511
        int r = q >> 2, qd = q & 3;
        dof[v] = r * 16 + ((qd ^ ((r >> 1) & 3)) << 2);
        aP[v] = gAh + (size_t)(row0 + r) * 16 + qd * 4;
        bP[v] = gBh + (size_t)(col0 + r) * 16 + qd * 4;
    }
    const ptrdiff_t dAl = gAl - gAh;

    const int rowA = 64 * wm + lql * 8 + lr;
    const int xrA  = (rowA >> 1) & 3;
    const unsigned aRow = ub + (unsigned)(rowA * 64);
    const unsigned qa0 = (unsigned)(((lqh    ) ^ xrA) << 4);
    const unsigned qa1 = (unsigned)(((lqh + 2) ^ xrA) << 4);
    const int rowB = 32 * wn + lqh * 8 + lr;
    const int xrB  = (rowB >> 1) & 3;
    const unsigned bRow = ub + (unsigned)(O_BHI * 4 + rowB * 64);
    const unsigned qb0 = (unsigned)(((lql    ) ^ xrB) << 4);
    const unsigned qb1 = (unsigned)(((lql + 2) ^ xrB) << 4);

    auto fill = [&](int stage, int cidx) {
        const int oa = cidx * csA, ob = cidx * csB;
        #pragma unroll
        for (int v = 0; v < 2; v++) {
            unsigned da = ub + (unsigned)((stage * STG_W + dof[v]) << 2);
            cpa16(da,               aP[v] + oa);
            if (twoA) cpa16(da + O_ALO * 4, aP[v] + oa + dAl);
            cpa16(da + O_BHI * 4,   bP[v] + ob);
        }
        CP_COMMIT();
    };

    fill(0, 0);
    fill(1, 1);

    int stc = 0, stf = 2;
    for (int c = 0; c < 32; c++) {
        if (c < 31) asm volatile("cp.async.wait_group 1;" ::: "memory");
        else        asm volatile("cp.async.wait_group 0;" ::: "memory");
        __syncthreads();
        if (c + 2 < 32) { fill(stf, c + 2); stf = (stf == 2) ? 0 : stf + 1; }

        const unsigned so = (unsigned)(stc * (STG_W << 2));
        stc = (stc == 2) ? 0 : stc + 1;

        #pragma unroll
        for (int ks = 0; ks < 2; ks++) {
            const unsigned qa = ks ? qa1 : qa0;
            const unsigned qb = ks ? qb1 : qb0;
            unsigned bhf[2][4];
            #pragma unroll
            for (int p = 0; p < 2; p++) {
                unsigned ad = bRow + so + (unsigned)(p * 1024) + qb;
                ldsm4(bhf[p][0], bhf[p][1], bhf[p][2], bhf[p][3], ad);
            }
            #pragma unroll
            for (int mi = 0; mi < 4; mi++) {
                unsigned ad = aRow + so + (unsigned)(mi * 1024) + qa;
                unsigned ah0, ah1, ah2, ah3;
                ldsm4(ah0, ah1, ah2, ah3, ad);
                mma16816h(acc[mi][0], ah0, ah1, ah2, ah3, bhf[0][0], bhf[0][1]);
                mma16816h(acc[mi][1], ah0, ah1, ah2, ah3, bhf[0][2], bhf[0][3]);
                mma16816h(acc[mi][2], ah0, ah1, ah2, ah3, bhf[1][0], bhf[1][1]);
                mma16816h(acc[mi][3], ah0, ah1, ah2, ah3, bhf[1][2], bhf[1][3]);
                if (twoA) {
                    unsigned al0, al1, al2, al3;
                    ldsm4(al0, al1, al2, al3, ad + 8192);
                    mma16816h(acc[mi][0], al0, al1, al2, al3, bhf[0][0], bhf[0][1]);
                    mma16816h(acc[mi][1], al0, al1, al2, al3, bhf[0][2], bhf[0][3]);
                    mma16816h(acc[mi][2], al0, al1, al2, al3, bhf[1][0], bhf[1][1]);
                    mma16816h(acc[mi][3], al0, al1, al2, al3, bhf[1][2], bhf[1][3]);
                }
            }
        }
    }
    __syncthreads();
}

// ---------------- Kernel 1: QKV GEMM + LN + RoPE + store ----------------
__global__ __launch_bounds__(256, 2) void qkv_mm(
    const float* __restrict__ qn_w, const float* __restrict__ qn_b,
    const float* __restrict__ kn_w, const float* __restrict__ kn_b)
{
    extern __shared__ __align__(16) unsigned u[];
    const int tid = threadIdx.x;
    const int wid = tid >> 5, lane = tid & 31;
    const int wm = wid >> 2, wn = wid & 3;
    const int grp = lane >> 2, qid = lane & 3;
    const int row0 = blockIdx.y * 128;
    const int col0 = blockIdx.x * 128;

    float acc[4][4][4];
    #pragma unroll
    for (int i = 0; i < 4; i++)
        #pragma unroll
        for (int j = 0; j < 4; j++)
            #pragma unroll
            for (int k = 0; k < 4; k++) acc[i][j][k] = 0.f;

    mainloop_pre(g_xh, g_xl, g_wh, row0, col0, CS_X, CS_W, 1, u, acc);

    // stage 128x128 f32 tile (stride 132)
    float* stg = (float*)u;
    #pragma unroll
    for (int mi = 0; mi < 4; mi++) {
        int rr2 = 64 * wm + 16 * mi + grp;
        #pragma unroll
        for (int ni = 0; ni < 4; ni++) {
            int cc = 32 * wn + 8 * ni + 2 * qid;
            stg[rr2 * 132 + cc]           = acc[mi][ni][0];
            stg[rr2 * 132 + cc + 1]       = acc[mi][ni][1];
            stg[(rr2 + 8) * 132 + cc]     = acc[mi][ni][2];
            stg[(rr2 + 8) * 132 + cc + 1] = acc[mi][ni][3];
        }
    }
    __syncthreads();

    const int hh = tid >> 7, r = tid & 127;
    float d[64];
    const float* src = stg + r * 132 + hh * 64;
    #pragma unroll
    for (int j = 0; j < 16; j++) {
        float4 v = *(const float4*)(src + 4 * j);
        d[4*j] = v.x; d[4*j+1] = v.y; d[4*j+2] = v.z; d[4*j+3] = v.w;
    }

    const int t = col0 >> 10;                      // 0=q,1=k,2=v
    const int h = ((col0 & 1023) >> 6) + hh;
    const int grow = row0 + r;
    const int b = grow >> 10, n = grow & 1023;
    const size_t wbase = ((size_t)(b * H_ + h) * N_ + n) * 32;   // word offset

    unsigned hw[32], lw2[32];
    if (t == 2) {
        // V: single f16
        #pragma unroll
        for (int cpair = 0; cpair < 32; cpair++)
            hw[cpair] = packh(d[2*cpair], d[2*cpair+1]);
        #pragma unroll
        for (int q8 = 0; q8 < 8; q8++)
            *(uint4*)(g_Vh + wbase + 4*q8) = make_uint4(hw[4*q8], hw[4*q8+1], hw[4*q8+2], hw[4*q8+3]);
        return;
    }

    const float* lw = t ? kn_w : qn_w;
    const float* lb = t ? kn_b : qn_b;
    float s1 = 0.f, s2 = 0.f;
    #pragma unroll
    for (int j = 0; j < 64; j++) { s1 += d[j]; s2 += d[j] * d[j]; }
    float mu = s1 * (1.f / 64.f);
    float var = s2 * (1.f / 64.f) - mu * mu;
    float rstd = rsqrtf(var + 1e-5f);
    #pragma unroll
    for (int j = 0; j < 64; j++)
        d[j] = (d[j] - mu) * rstd * __ldg(lw + j) + __ldg(lb + j);
    const float2* rt = g_rope + n * 32;
    #pragma unroll
    for (int j = 0; j < 32; j++) {
        float2 cs = __ldg(rt + j);
        float t0 = d[j];
        d[j]      = t0 * cs.x - d[j + 32] * cs.y;
        d[j + 32] = d[j + 32] * cs.x + t0 * cs.y;
    }
    if (t == 0) {
        // Q: single f16 (pre-scaled)
        #pragma unroll
        for (int cpair = 0; cpair < 32; cpair++)
            hw[cpair] = packh(d[2*cpair] * QSCALE, d[2*cpair+1] * QSCALE);
        #pragma unroll
        for (int q8 = 0; q8 < 8; q8++)
            *(uint4*)(g_Qh + wbase + 4*q8) = make_uint4(hw[4*q8], hw[4*q8+1], hw[4*q8+2], hw[4*q8+3]);
        return;
    }
    #pragma unroll
    for (int cpair = 0; cpair < 32; cpair++)
        splitf16(d[2*cpair], d[2*cpair+1], hw[cpair], lw2[cpair]);
    #pragma unroll
    for (int q8 = 0; q8 < 8; q8++) {
        *(uint4*)(g_Kh + wbase + 4*q8) = make_uint4(hw[4*q8], hw[4*q8+1], hw[4*q8+2], hw[4*q8+3]);
        *(uint4*)(g_Kl + wbase + 4*q8) = make_uint4(lw2[4*q8], lw2[4*q8+1], lw2[4*q8+2], lw2[4*q8+3]);
    }
}

// ---------------- Kernel 3: proj GEMM + bias (1-pass) ----------------
__global__ __launch_bounds__(256, 2) void proj_mm(
    const float* __restrict__ bias, float* __restrict__ out)
{
    extern __shared__ __align__(16) unsigned u[];
    const int tid = threadIdx.x;
    const int wid = tid >> 5, lane = tid & 31;
    const int wm = wid >> 2, wn = wid & 3;
    const int grp = lane >> 2, qid = lane & 3;
    const int row0 = blockIdx.y * 128;
    const int col0 = blockIdx.x * 128;

    float acc[4][4][4];
    #pragma unroll
    for (int i = 0; i < 4; i++)
        #pragma unroll
        for (int j = 0; j < 4; j++)
            #pragma unroll
            for (int k = 0; k < 4; k++) acc[i][j][k] = 0.f;

    mainloop_pre(g_AOh, g_AOh, g_pwh, row0, col0, CS_X, CS_P, 0, u, acc);

    #pragma unroll
    for (int mi = 0; mi < 4; mi++) {
        int rr = row0 + 64 * wm + 16 * mi + grp;
        #pragma unroll
        for (int ni = 0; ni < 4; ni++) {
            int cc = col0 + 32 * wn + 8 * ni + 2 * qid;
            float b0 = __ldg(bias + cc), b1 = __ldg(bias + cc + 1);
            *(float2*)(out + (size_t)rr * DIM_ + cc) =
                make_float2(acc[mi][ni][0] + b0, acc[mi][ni][1] + b1);
            *(float2*)(out + (size_t)(rr + 8) * DIM_ + cc) =
                make_float2(acc[mi][ni][2] + b0, acc[mi][ni][3] + b1);
        }
    }
}

// ------ Kernel 2: flash attention (Q/V single f16; QK 2-pass; PV 1-pass) ------
// smem word offsets: Qh, Kh, Kl, Vh each 64 rows x 36 words
#define AQH 0
#define AKH 2304
#define AKL 4608
#define AVH 6912
#define ATT_SMEM 36864

__global__ __launch_bounds__(128) void attn_tc(const float* __restrict__ sinks)
{
    extern __shared__ __align__(16) unsigned u[];
    const int tid = threadIdx.x;
    const int wid = tid >> 5, lane = tid & 31;
    const int g8 = lane >> 2, qid = lane & 3;
    const int lq = lane >> 3, lr = lane & 7;
    const int bh = blockIdx.y, b = bh >> 4, h = bh & 15;
    const int q0 = blockIdx.x * 64;
    const unsigned ub = smem_u32(u);

    const size_t base = (size_t)(b * H_ + h) * N_ * 32;   // word base of this (b,h)
    const unsigned* Qhg = g_Qh + base + (size_t)q0 * 32;
    const unsigned* Khg = g_Kh + base;
    const unsigned* Klg = g_Kl + base;
    const unsigned* Vhg = g_Vh + base;

    #pragma unroll
    for (int v = 0; v < 4; v++) {
        int idx = tid + 128 * v;          // 0..511
        int r = idx >> 3, f = (idx & 7) * 4;
        unsigned da = ub + (unsigned)((r * 36 + f) << 2);
        cpa16(da + AQH * 4, Qhg + r * 32 + f);
    }
    CP_COMMIT(); CP_WAIT0();
    __syncthreads();

    // hoist Q fragments (loop-invariant over kt)
    unsigned qh[4][4];
    const unsigned qBase = ub + ((AQH + (16 * wid + (lq & 1) * 8 + lr) * 36 + (lq >> 1) * 4) << 2);
    #pragma unroll
    for (int ks = 0; ks < 4; ks++)
        ldsm4(qh[ks][0], qh[ks][1], qh[ks][2], qh[ks][3], qBase + (unsigned)((ks * 8) << 2));

    const unsigned kBase = ub + ((AKH + ((lq >> 1) * 8 + lr) * 36 + (lq & 1) * 4) << 2);
    const unsigned vBase = ub + ((AVH + ((lq & 1) * 8 + lr) * 36 + (lq >> 1) * 4) << 2);

    float m0 = __ldg(sinks + h) * LOG2E, m1 = m0;
    float d0 = 1.f, d1 = 1.f;
    float oacc[8][4];
    #pragma unroll
    for (int i = 0; i < 8; i++)
        #pragma unroll
        for (int j = 0; j < 4; j++) oacc[i][j] = 0.f;

    const int i0 = q0 + 16 * wid + g8;
    const int i1 = i0 + 8;
    const int rmin = q0 + 16 * wid;          // warp's min row
    const int rmax = rmin + 15;              // warp's max row
    const int kt_lo = (q0 >= SW_) ? ((q0 - SW_ + 1) >> 6) : 0;
    const int kt_hi = q0 >> 6;

    for (int kt = kt_lo; kt <= kt_hi; kt++) {
        const int k0 = kt << 6;
        __syncthreads();
        #pragma unroll
        for (int v = 0; v < 4; v++) {
            int idx = tid + 128 * v;
            int r = idx >> 3, f = (idx & 7) * 4;
            unsigned da = ub + (unsigned)((r * 36 + f) << 2);
            int so = (k0 + r) * 32 + f;
            cpa16(da + AKH * 4, Khg + so);
            cpa16(da + AKL * 4, Klg + so);
            cpa16(da + AVH * 4, Vhg + so);
        }
        CP_COMMIT(); CP_WAIT0();
        __syncthreads();

        // S = Q K^T (2-pass: Qh*Kh + Qh*Kl); skip fully-masked 16-col blocks
        float sacc[8][4];
        #pragma unroll
        for (int i = 0; i < 8; i++)
            #pragma unroll
            for (int j = 0; j < 4; j++) sacc[i][j] = 0.f;

        #pragma unroll
        for (int p = 0; p < 4; p++) {
            const int c0b = k0 + 16 * p;
            if (c0b > rmax || c0b + 15 < rmin - (SW_ - 1)) continue;   // warp-uniform
            #pragma unroll
            for (int ks = 0; ks < 4; ks++) {
                unsigned kh0, kh1, kh2, kh3, kl0, kl1, kl2, kl3;
                unsigned ad = kBase + (unsigned)((p * 576 + ks * 8) << 2);
                ldsm4(kh0, kh1, kh2, kh3, ad);
                ldsm4(kl0, kl1, kl2, kl3, ad + (unsigned)((AKL - AKH) << 2));
                mma16816h(sacc[2*p],   qh[ks][0], qh[ks][1], qh[ks][2], qh[ks][3], kh0, kh1);
                mma16816h(sacc[2*p+1], qh[ks][0], qh[ks][1], qh[ks][2], qh[ks][3], kh2, kh3);
                mma16816h(sacc[2*p],   qh[ks][0], qh[ks][1], qh[ks][2], qh[ks][3], kl0, kl1);
                mma16816h(sacc[2*p+1], qh[ks][0], qh[ks][1], qh[ks][2], qh[ks][3], kl2, kl3);
            }
        }

        // mask + row max
        float mx0 = -1e30f, mx1 = -1e30f;
        #pragma unroll
        for (int ni = 0; ni < 8; ni++) {
            int j = k0 + 8 * ni + 2 * qid;
            sacc[ni][0] = (j     <= i0 && j     > i0 - SW_) ? sacc[ni][0] : -1e30f;
            sacc[ni][1] = (j + 1 <= i0 && j + 1 > i0 - SW_) ? sacc[ni][1] : -1e30f;
            sacc[ni][2] = (j     <= i1 && j     > i1 - SW_) ? sacc[ni][2] : -1e30f;
            sacc[ni][3] = (j + 1 <= i1 && j + 1 > i1 - SW_) ? sacc[ni][3] : -1e30f;
            mx0 = fmaxf(mx0, fmaxf(sacc[ni][0], sacc[ni][1]));
            mx1 = fmaxf(mx1, fmaxf(sacc[ni][2], sacc[ni][3]));
        }
        mx0 = fmaxf(mx0, __shfl_xor_sync(0xffffffffu, mx0, 1));
        mx0 = fmaxf(mx0, __shfl_xor_sync(0xffffffffu, mx0, 2));
        mx1 = fmaxf(mx1, __shfl_xor_sync(0xffffffffu, mx1, 1));
        mx1 = fmaxf(mx1, __shfl_xor_sync(0xffffffffu, mx1, 2));
        float mn0 = fmaxf(m0, mx0), mn1 = fmaxf(m1, mx1);
        float sc0 = ex2f(m0 - mn0), sc1 = ex2f(m1 - mn1);
        m0 = mn0; m1 = mn1; d0 *= sc0; d1 *= sc1;
        #pragma unroll
        for (int nd = 0; nd < 8; nd++) {
            oacc[nd][0] *= sc0; oacc[nd][1] *= sc0;
            oacc[nd][2] *= sc1; oacc[nd][3] *= sc1;
        }

        // e = 2^(s-m), pack to f16; accumulate row sums
        unsigned pfh[8][2];
        float t0 = 0.f, t1 = 0.f;
        #pragma unroll
        for (int ni = 0; ni < 8; ni++) {
            float e0 = ex2f(fmaxf(sacc[ni][0] - mn0, -126.f));
            float e1 = ex2f(fmaxf(sacc[ni][1] - mn0, -126.f));
            float e2 = ex2f(fmaxf(sacc[ni][2] - mn1, -126.f));
            float e3 = ex2f(fmaxf(sacc[ni][3] - mn1, -126.f));
            t0 += e0 + e1; t1 += e2 + e3;
            pfh[ni][0] = packh(e0, e1);
            pfh[ni][1] = packh(e2, e3);
        }
        t0 += __shfl_xor_sync(0xffffffffu, t0, 1);
        t0 += __shfl_xor_sync(0xffffffffu, t0, 2);
        t1 += __shfl_xor_sync(0xffffffffu, t1, 1);
        t1 += __shfl_xor_sync(0xffffffffu, t1, 2);
        d0 += t0; d1 += t1;

        // O += P V (1-pass: P*Vh); skip fully-masked kf blocks
        #pragma unroll
        for (int kf = 0; kf < 4; kf++) {
            const int c0b = k0 + 16 * kf;
            if (c0b > rmax || c0b + 15 < rmin - (SW_ - 1)) continue;   // warp-uniform
            unsigned a0 = pfh[2*kf][0], a1 = pfh[2*kf][1];
            unsigned a2 = pfh[2*kf+1][0], a3 = pfh[2*kf+1][1];
            #pragma unroll
            for (int p = 0; p < 4; p++) {
                unsigned vh0, vh1, vh2, vh3;
                unsigned ad = vBase + (unsigned)((kf * 576 + p * 8) << 2);
                ldsm4t(vh0, vh1, vh2, vh3, ad);
                mma16816h(oacc[2*p],   a0, a1, a2, a3, vh0, vh1);
                mma16816h(oacc[2*p+1], a0, a1, a2, a3, vh2, vh3);
            }
        }
    }

    // epilogue: AO blocked [kc][4096 rows][16 words], single f16
    float inv0 = 1.f / d0, inv1 = 1.f / d1;
    #pragma unroll
    for (int nd = 0; nd < 8; nd++) {
        int col = 64 * h + 8 * nd + 2 * qid;
        int kc = col >> 5, wic = (col & 31) >> 1;
        size_t w0 = (size_t)kc * CS_X + (size_t)(b * N_ + i0) * 16 + wic;
        g_AOh[w0] = packh(oacc[nd][0] * inv0, oacc[nd][1] * inv0);
        size_t w1 = (size_t)kc * CS_X + (size_t)(b * N_ + i1) * 16 + wic;
        g_AOh[w1] = packh(oacc[nd][2] * inv1, oacc[nd][3] * inv1);
    }
}

extern "C" void kernel_launch(void* const* d_in, const int* in_sizes, int n_in,
                              void* d_out, int out_size)
{
    const float* x      = (const float*)d_in[0];
    const float* qkv_w  = (const float*)d_in[1];
    const float* qn_w   = (const float*)d_in[2];
    const float* qn_b   = (const float*)d_in[3];
    const float* kn_w   = (const float*)d_in[4];
    const float* kn_b   = (const float*)d_in[5];
    const float* sinks  = (const float*)d_in[6];
    const float* proj_w = (const float*)d_in[7];
    const float* proj_b = (const float*)d_in[8];
    float* out = (float*)d_out;

    cudaFuncSetAttribute(qkv_mm,  cudaFuncAttributeMaxDynamicSharedMemorySize, GEMM_SMEM);
    cudaFuncSetAttribute(proj_mm, cudaFuncAttributeMaxDynamicSharedMemorySize, GEMM_SMEM);
    cudaFuncSetAttribute(attn_tc, cudaFuncAttributeMaxDynamicSharedMemorySize, ATT_SMEM);

    presplit_all<<<dim3(1024, 4), 256>>>((const float4*)x, (const float4*)qkv_w,
                                         (const float4*)proj_w);
    qkv_mm<<<dim3(24, 32), 256, GEMM_SMEM>>>(qn_w, qn_b, kn_w, kn_b);
    attn_tc<<<dim3(16, 64), 128, ATT_SMEM>>>(sinks);
    proj_mm<<<dim3(8, 32), 256, GEMM_SMEM>>>(proj_b, out);
}

// round 16
// speedup vs baseline: 2.0647x; 1.3040x over previous
#include <cuda_runtime.h>
#include <cuda_bf16.h>
#include <cuda_fp16.h>
#include <math.h>
#include <cstdint>

#define B_   4
#define N_   1024
#define DIM_ 1024
#define H_   16
#define D_   64
#define SW_  256
#define LOG2E  1.4426950408889634f
#define QSCALE 0.18033688011112042f   // sm_scale * log2(e)

// ---------------- device globals (word = 2 f16) ----------------
// x/w/pw/AO stored CHUNK-BLOCKED: [kc][row][16 words] (kc = K/32 chunks)
__device__ unsigned g_xh[2097152];                    // x      4096x1024 f16
__device__ unsigned g_wh[1572864];                    // qkv_w  3072x1024 f16
__device__ unsigned g_pwh[524288];                    // proj_w 1024x1024 f16
__device__ unsigned g_Qh[2097152];                    // [b,h,n,d] f16 (pre-scaled)
__device__ unsigned g_Kh[2097152],  g_Kl[2097152];    // [b,h,n,d] f16 split
__device__ unsigned g_Vh[2097152];                    // [b,h,n,d] f16
__device__ unsigned g_AOh[2097152];                   // blocked [kc][4096][16] f16
__device__ float2  g_rope[32768];                     // [n][j] (cos, sin), j<32

#define CS_X  65536     // chunk stride (words): 4096 rows * 16
#define CS_W  49152     // 3072 * 16
#define CS_P  16384     // 1024 * 16

// ---------------- helpers ----------------
__device__ __forceinline__ void splitf16(float x, float y, unsigned &hi, unsigned &lo) {
    __half hx = __float2half_rn(x), hy = __float2half_rn(y);
    float rx = x - __half2float(hx);
    float ry = y - __half2float(hy);
    __half lx = __float2half_rn(rx), ly = __float2half_rn(ry);
    hi = ((unsigned)__half_as_ushort(hy) << 16) | (unsigned)__half_as_ushort(hx);
    lo = ((unsigned)__half_as_ushort(ly) << 16) | (unsigned)__half_as_ushort(lx);
}
__device__ __forceinline__ unsigned packh(float x, float y) {
    __half hx = __float2half_rn(x), hy = __float2half_rn(y);
    return ((unsigned)__half_as_ushort(hy) << 16) | (unsigned)__half_as_ushort(hx);
}
__device__ __forceinline__ void mma16816h(float* c, unsigned a0, unsigned a1,
                                          unsigned a2, unsigned a3,
                                          unsigned b0, unsigned b1) {
    asm volatile(
        "mma.sync.aligned.m16n8k16.row.col.f32.f16.f16.f32 "
        "{%0,%1,%2,%3}, {%4,%5,%6,%7}, {%8,%9}, {%0,%1,%2,%3};"
        : "+f"(c[0]), "+f"(c[1]), "+f"(c[2]), "+f"(c[3])
        : "r"(a0), "r"(a1), "r"(a2), "r"(a3), "r"(b0), "r"(b1));
}
__device__ __forceinline__ void ldsm4(unsigned &r0, unsigned &r1, unsigned &r2,
                                      unsigned &r3, unsigned addr) {
    asm volatile("ldmatrix.sync.aligned.m8n8.x4.shared.b16 {%0,%1,%2,%3}, [%4];"
                 : "=r"(r0), "=r"(r1), "=r"(r2), "=r"(r3) : "r"(addr));
}
__device__ __forceinline__ void ldsm4t(unsigned &r0, unsigned &r1, unsigned &r2,
                                       unsigned &r3, unsigned addr) {
    asm volatile("ldmatrix.sync.aligned.m8n8.x4.trans.shared.b16 {%0,%1,%2,%3}, [%4];"
                 : "=r"(r0), "=r"(r1), "=r"(r2), "=r"(r3) : "r"(addr));
}
__device__ __forceinline__ float ex2f(float x) {
    float y; asm("ex2.approx.f32 %0, %1;" : "=f"(y) : "f"(x)); return y;
}
__device__ __forceinline__ unsigned smem_u32(const void* p){
    unsigned a;
    asm("{ .reg .u64 t; cvta.to.shared.u64 t, %1; cvt.u32.u64 %0, t; }" : "=r"(a) : "l"(p));
    return a;
}
__device__ __forceinline__ void cpa16(unsigned daddr, const void* g){
    asm volatile("cp.async.cg.shared.global [%0], [%1], 16;" :: "r"(daddr), "l"(g) : "memory");
}
#define CP_COMMIT() asm volatile("cp.async.commit_group;" ::: "memory")
#define CP_WAIT0()  asm volatile("cp.async.wait_group 0;" ::: "memory")

// ---------------- presplit: fp32 -> f16, chunk-blocked; + rope table ----------
__global__ void presplit_all(const float4* __restrict__ x,
                             const float4* __restrict__ w,
                             const float4* __restrict__ pw)
{
    if (blockIdx.y == 3) {
        for (int i = blockIdx.x * blockDim.x + threadIdx.x; i < 32768;
             i += gridDim.x * blockDim.x) {
            int n = i >> 5, j = i & 31;
            float invf = expf(-(float)j * 0.2878231366242557f);  // 10000^(-j/32)
            float sn, cs;
            sincosf((float)n * invf, &sn, &cs);
            g_rope[i] = make_float2(cs, sn);
        }
        return;
    }
    const float4* s; unsigned *hp; int rows;
    if (blockIdx.y == 0)      { s = x;  hp = g_xh;  rows = 4096; }
    else if (blockIdx.y == 1) { s = w;  hp = g_wh;  rows = 3072; }
    else                      { s = pw; hp = g_pwh; rows = 1024; }
    const int n4 = rows * 256;
    for (int i = blockIdx.x * blockDim.x + threadIdx.x; i < n4; i += gridDim.x * blockDim.x) {
        float4 f = s[i];
        int r = i >> 8, c4 = i & 255;
        int kc = c4 >> 3, wic = (c4 & 7) * 2;
        size_t dw = (size_t)kc * rows * 16 + (size_t)r * 16 + wic;
        *(uint2*)(hp + dw) = make_uint2(packh(f.x, f.y), packh(f.z, f.w));
    }
}

// ------------- GEMM mainloop: 3-stage, swizzled 16-word rows, 1 barrier/chunk --
// 1-pass: C = Ah*Bh (both single f16)
#define STG_W  8192
#define O_ALO  2048
#define O_BHI  4096
#define GEMM_SMEM 98304     // 3 stages * 32768 B

__device__ __forceinline__ void mainloop_pre(
    const unsigned* __restrict__ gAh,
    const unsigned* __restrict__ gBh,
    int row0, int col0, int csA, int csB, unsigned* u, float acc[4][4][4])
{
    const int tid = threadIdx.x;
    const int wid = tid >> 5, lane = tid & 31;
    const int wm = wid >> 2, wn = wid & 3;
    const int lq = lane >> 3, lr = lane & 7;
    const int lqh = lq >> 1, lql = lq & 1;
    const unsigned ub = smem_u32(u);

    int dof[2];
    const unsigned* aP[2]; const unsigned* bP[2];
    #pragma unroll
    for (int v = 0; v < 2; v++) {
        int q = tid + 256 * v;               // 0..511
        int r = q >> 2, qd = q & 3;
        dof[v] = r * 16 + ((qd ^ ((r >> 1) & 3)) << 2);
        aP[v] = gAh + (size_t)(row0 + r) * 16 + qd * 4;
        bP[v] = gBh + (size_t)(col0 + r) * 16 + qd * 4;
    }

    const int rowA = 64 * wm + lql * 8 + lr;
    const int xrA  = (rowA >> 1) & 3;
    const unsigned aRow = ub + (unsigned)(rowA * 64);
    const unsigned qa0 = (unsigned)(((lqh    ) ^ xrA) << 4);
    const unsigned qa1 = (unsigned)(((lqh + 2) ^ xrA) << 4);
    const int rowB = 32 * wn + lqh * 8 + lr;
    const int xrB  = (rowB >> 1) & 3;
    const unsigned bRow = ub + (unsigned)(O_BHI * 4 + rowB * 64);
    const unsigned qb0 = (unsigned)(((lql    ) ^ xrB) << 4);
    const unsigned qb1 = (unsigned)(((lql + 2) ^ xrB) << 4);

    auto fill = [&](int stage, int cidx) {
        const int oa = cidx * csA, ob = cidx * csB;
        #pragma unroll
        for (int v = 0; v < 2; v++) {
            unsigned da = ub + (unsigned)((stage * STG_W + dof[v]) << 2);
            cpa16(da,             aP[v] + oa);
            cpa16(da + O_BHI * 4, bP[v] + ob);
        }
        CP_COMMIT();
    };

    fill(0, 0);
    fill(1, 1);

    int stc = 0, stf = 2;
    for (int c = 0; c < 32; c++) {
        if (c < 31) asm volatile("cp.async.wait_group 1;" ::: "memory");
        else        asm volatile("cp.async.wait_group 0;" ::: "memory");
        __syncthreads();
        if (c + 2 < 32) { fill(stf, c + 2); stf = (stf == 2) ? 0 : stf + 1; }

        const unsigned so = (unsigned)(stc * (STG_W << 2));
        stc = (stc == 2) ? 0 : stc + 1;

        #pragma unroll
        for (int ks = 0; ks < 2; ks++) {
            const unsigned qa = ks ? qa1 : qa0;
            const unsigned qb = ks ? qb1 : qb0;
            unsigned bhf[2][4];
            #pragma unroll
            for (int p = 0; p < 2; p++) {
                unsigned ad = bRow + so + (unsigned)(p * 1024) + qb;
                ldsm4(bhf[p][0], bhf[p][1], bhf[p][2], bhf[p][3], ad);
            }
            #pragma unroll
            for (int mi = 0; mi < 4; mi++) {
                unsigned ad = aRow + so + (unsigned)(mi * 1024) + qa;
                unsigned ah0, ah1, ah2, ah3;
                ldsm4(ah0, ah1, ah2, ah3, ad);
                mma16816h(acc[mi][0], ah0, ah1, ah2, ah3, bhf[0][0], bhf[0][1]);
                mma16816h(acc[mi][1], ah0, ah1, ah2, ah3, bhf[0][2], bhf[0][3]);
                mma16816h(acc[mi][2], ah0, ah1, ah2, ah3, bhf[1][0], bhf[1][1]);
                mma16816h(acc[mi][3], ah0, ah1, ah2, ah3, bhf[1][2], bhf[1][3]);
            }
        }
    }
    __syncthreads();
}

// ---------------- Kernel 1: QKV GEMM + LN + RoPE + store ----------------
__global__ __launch_bounds__(256, 2) void qkv_mm(
    const float* __restrict__ qn_w, const float* __restrict__ qn_b,
    const float* __restrict__ kn_w, const float* __restrict__ kn_b)
{
    extern __shared__ __align__(16) unsigned u[];
    const int tid = threadIdx.x;
    const int wid = tid >> 5, lane = tid & 31;
    const int wm = wid >> 2, wn = wid & 3;
    const int grp = lane >> 2, qid = lane & 3;
    const int row0 = blockIdx.y * 128;
    const int col0 = blockIdx.x * 128;

    float acc[4][4][4];
    #pragma unroll
    for (int i = 0; i < 4; i++)
        #pragma unroll
        for (int j = 0; j < 4; j++)
            #pragma unroll
            for (int k = 0; k < 4; k++) acc[i][j][k] = 0.f;

    mainloop_pre(g_xh, g_wh, row0, col0, CS_X, CS_W, u, acc);

    // stage 128x128 f32 tile (stride 132)
    float* stg = (float*)u;
    #pragma unroll
    for (int mi = 0; mi < 4; mi++) {
        int rr2 = 64 * wm + 16 * mi + grp;
        #pragma unroll
        for (int ni = 0; ni < 4; ni++) {
            int cc = 32 * wn + 8 * ni + 2 * qid;
            stg[rr2 * 132 + cc]           = acc[mi][ni][0];
            stg[rr2 * 132 + cc + 1]       = acc[mi][ni][1];
            stg[(rr2 + 8) * 132 + cc]     = acc[mi][ni][2];
            stg[(rr2 + 8) * 132 + cc + 1] = acc[mi][ni][3];
        }
    }
    __syncthreads();

    const int hh = tid >> 7, r = tid & 127;
    float d[64];
    const float* src = stg + r * 132 + hh * 64;
    #pragma unroll
    for (int j = 0; j < 16; j++) {
        float4 v = *(const float4*)(src + 4 * j);
        d[4*j] = v.x; d[4*j+1] = v.y; d[4*j+2] = v.z; d[4*j+3] = v.w;
    }

    const int t = col0 >> 10;                      // 0=q,1=k,2=v
    const int h = ((col0 & 1023) >> 6) + hh;
    const int grow = row0 + r;
    const int b = grow >> 10, n = grow & 1023;
    const size_t wbase = ((size_t)(b * H_ + h) * N_ + n) * 32;   // word offset

    unsigned hw[32], lw2[32];
    if (t == 2) {
        // V: single f16
        #pragma unroll
        for (int cpair = 0; cpair < 32; cpair++)
            hw[cpair] = packh(d[2*cpair], d[2*cpair+1]);
        #pragma unroll
        for (int q8 = 0; q8 < 8; q8++)
            *(uint4*)(g_Vh + wbase + 4*q8) = make_uint4(hw[4*q8], hw[4*q8+1], hw[4*q8+2], hw[4*q8+3]);
        return;
    }

    const float* lw = t ? kn_w : qn_w;
    const float* lb = t ? kn_b : qn_b;
    float s1 = 0.f, s2 = 0.f;
    #pragma unroll
    for (int j = 0; j < 64; j++) { s1 += d[j]; s2 += d[j] * d[j]; }
    float mu = s1 * (1.f / 64.f);
    float var = s2 * (1.f / 64.f) - mu * mu;
    float rstd = rsqrtf(var + 1e-5f);
    #pragma unroll
    for (int j = 0; j < 64; j++)
        d[j] = (d[j] - mu) * rstd * __ldg(lw + j) + __ldg(lb + j);
    const float2* rt = g_rope + n * 32;
    #pragma unroll
    for (int j = 0; j < 32; j++) {
        float2 cs = __ldg(rt + j);
        float t0 = d[j];
        d[j]      = t0 * cs.x - d[j + 32] * cs.y;
        d[j + 32] = d[j + 32] * cs.x + t0 * cs.y;
    }
    if (t == 0) {
        // Q: single f16 (pre-scaled)
        #pragma unroll
        for (int cpair = 0; cpair < 32; cpair++)
            hw[cpair] = packh(d[2*cpair] * QSCALE, d[2*cpair+1] * QSCALE);
        #pragma unroll
        for (int q8 = 0; q8 < 8; q8++)
            *(uint4*)(g_Qh + wbase + 4*q8) = make_uint4(hw[4*q8], hw[4*q8+1], hw[4*q8+2], hw[4*q8+3]);
        return;
    }
    #pragma unroll
    for (int cpair = 0; cpair < 32; cpair++)
        splitf16(d[2*cpair], d[2*cpair+1], hw[cpair], lw2[cpair]);
    #pragma unroll
    for (int q8 = 0; q8 < 8; q8++) {
        *(uint4*)(g_Kh + wbase + 4*q8) = make_uint4(hw[4*q8], hw[4*q8+1], hw[4*q8+2], hw[4*q8+3]);
        *(uint4*)(g_Kl + wbase + 4*q8) = make_uint4(lw2[4*q8], lw2[4*q8+1], lw2[4*q8+2], lw2[4*q8+3]);
    }
}

// ---------------- Kernel 3: proj GEMM + bias (1-pass) ----------------
__global__ __launch_bounds__(256, 2) void proj_mm(
    const float* __restrict__ bias, float* __restrict__ out)
{
    extern __shared__ __align__(16) unsigned u[];
    const int tid = threadIdx.x;
    const int wid = tid >> 5, lane = tid & 31;
    const int wm = wid >> 2, wn = wid & 3;
    const int grp = lane >> 2, qid = lane & 3;
    const int row0 = blockIdx.y * 128;
    const int col0 = blockIdx.x * 128;

    float acc[4][4][4];
    #pragma unroll
    for (int i = 0; i < 4; i++)
        #pragma unroll
        for (int j = 0; j < 4; j++)
            #pragma unroll
            for (int k = 0; k < 4; k++) acc[i][j][k] = 0.f;

    mainloop_pre(g_AOh, g_pwh, row0, col0, CS_X, CS_P, u, acc);

    #pragma unroll
    for (int mi = 0; mi < 4; mi++) {
        int rr = row0 + 64 * wm + 16 * mi + grp;
        #pragma unroll
        for (int ni = 0; ni < 4; ni++) {
            int cc = col0 + 32 * wn + 8 * ni + 2 * qid;
            float b0 = __ldg(bias + cc), b1 = __ldg(bias + cc + 1);
            *(float2*)(out + (size_t)rr * DIM_ + cc) =
                make_float2(acc[mi][ni][0] + b0, acc[mi][ni][1] + b1);
            *(float2*)(out + (size_t)(rr + 8) * DIM_ + cc) =
                make_float2(acc[mi][ni][2] + b0, acc[mi][ni][3] + b1);
        }
    }
}

// ------ Kernel 2: flash attention (Q/V single f16; QK 2-pass; PV 1-pass) ------
// smem word offsets: Qh, Kh, Kl, Vh each 64 rows x 36 words
#define AQH 0
#define AKH 2304
#define AKL 4608
#define AVH 6912
#define ATT_SMEM 36864

__global__ __launch_bounds__(128) void attn_tc(const float* __restrict__ sinks)
{
    extern __shared__ __align__(16) unsigned u[];
    const int tid = threadIdx.x;
    const int wid = tid >> 5, lane = tid & 31;
    const int g8 = lane >> 2, qid = lane & 3;
    const int lq = lane >> 3, lr = lane & 7;
    const int bh = blockIdx.y, b = bh >> 4, h = bh & 15;
    const int q0 = blockIdx.x * 64;
    const unsigned ub = smem_u32(u);

    const size_t base = (size_t)(b * H_ + h) * N_ * 32;   // word base of this (b,h)
    const unsigned* Qhg = g_Qh + base + (size_t)q0 * 32;
    const unsigned* Khg = g_Kh + base;
    const unsigned* Klg = g_Kl + base;
    const unsigned* Vhg = g_Vh + base;

    #pragma unroll
    for (int v = 0; v < 4; v++) {
        int idx = tid + 128 * v;          // 0..511
        int r = idx >> 3, f = (idx & 7) * 4;
        unsigned da = ub + (unsigned)((r * 36 + f) << 2);
        cpa16(da + AQH * 4, Qhg + r * 32 + f);
    }
    CP_COMMIT(); CP_WAIT0();
    __syncthreads();

    // hoist Q fragments (loop-invariant over kt)
    unsigned qh[4][4];
    const unsigned qBase = ub + ((AQH + (16 * wid + (lq & 1) * 8 + lr) * 36 + (lq >> 1) * 4) << 2);
    #pragma unroll
    for (int ks = 0; ks < 4; ks++)
        ldsm4(qh[ks][0], qh[ks][1], qh[ks][2], qh[ks][3], qBase + (unsigned)((ks * 8) << 2));

    const unsigned kBase = ub + ((AKH + ((lq >> 1) * 8 + lr) * 36 + (lq & 1) * 4) << 2);
    const unsigned vBase = ub + ((AVH + ((lq & 1) * 8 + lr) * 36 + (lq >> 1) * 4) << 2);

    float m0 = __ldg(sinks + h) * LOG2E, m1 = m0;
    float d0 = 1.f, d1 = 1.f;
    float oacc[8][4];
    #pragma unroll
    for (int i = 0; i < 8; i++)
        #pragma unroll
        for (int j = 0; j < 4; j++) oacc[i][j] = 0.f;

    const int i0 = q0 + 16 * wid + g8;
    const int i1 = i0 + 8;
    const int rmin = q0 + 16 * wid;          // warp's min row
    const int rmax = rmin + 15;              // warp's max row
    const int kt_lo = (q0 >= SW_) ? ((q0 - SW_ + 1) >> 6) : 0;
    const int kt_hi = q0 >> 6;

    for (int kt = kt_lo; kt <= kt_hi; kt++) {
        const int k0 = kt << 6;
        __syncthreads();
        #pragma unroll
        for (int v = 0; v < 4; v++) {
            int idx = tid + 128 * v;
            int r = idx >> 3, f = (idx & 7) * 4;
            unsigned da = ub + (unsigned)((r * 36 + f) << 2);
            int so = (k0 + r) * 32 + f;
            cpa16(da + AKH * 4, Khg + so);
            cpa16(da + AKL * 4, Klg + so);
            cpa16(da + AVH * 4, Vhg + so);
        }
        CP_COMMIT(); CP_WAIT0();
        __syncthreads();

        // S = Q K^T (2-pass: Qh*Kh + Qh*Kl); skip fully-masked 16-col blocks
        float sacc[8][4];
        #pragma unroll
        for (int i = 0; i < 8; i++)
            #pragma unroll
            for (int j = 0; j < 4; j++) sacc[i][j] = 0.f;

        #pragma unroll
        for (int p = 0; p < 4; p++) {
            const int c0b = k0 + 16 * p;
            if (c0b > rmax || c0b + 15 < rmin - (SW_ - 1)) continue;   // warp-uniform
            #pragma unroll
            for (int ks = 0; ks < 4; ks++) {
                unsigned kh0, kh1, kh2, kh3, kl0, kl1, kl2, kl3;
                unsigned ad = kBase + (unsigned)((p * 576 + ks * 8) << 2);
                ldsm4(kh0, kh1, kh2, kh3, ad);
                ldsm4(kl0, kl1, kl2, kl3, ad + (unsigned)((AKL - AKH) << 2));
                mma16816h(sacc[2*p],   qh[ks][0], qh[ks][1], qh[ks][2], qh[ks][3], kh0, kh1);
                mma16816h(sacc[2*p+1], qh[ks][0], qh[ks][1], qh[ks][2], qh[ks][3], kh2, kh3);
                mma16816h(sacc[2*p],   qh[ks][0], qh[ks][1], qh[ks][2], qh[ks][3], kl0, kl1);
                mma16816h(sacc[2*p+1], qh[ks][0], qh[ks][1], qh[ks][2], qh[ks][3], kl2, kl3);
            }
        }

        // mask + row max
        float mx0 = -1e30f, mx1 = -1e30f;
        #pragma unroll
        for (int ni = 0; ni < 8; ni++) {
            int j = k0 + 8 * ni + 2 * qid;
            sacc[ni][0] = (j     <= i0 && j     > i0 - SW_) ? sacc[ni][0] : -1e30f;
            sacc[ni][1] = (j + 1 <= i0 && j + 1 > i0 - SW_) ? sacc[ni][1] : -1e30f;
            sacc[ni][2] = (j     <= i1 && j     > i1 - SW_) ? sacc[ni][2] : -1e30f;
            sacc[ni][3] = (j + 1 <= i1 && j + 1 > i1 - SW_) ? sacc[ni][3] : -1e30f;
            mx0 = fmaxf(mx0, fmaxf(sacc[ni][0], sacc[ni][1]));
            mx1 = fmaxf(mx1, fmaxf(sacc[ni][2], sacc[ni][3]));
        }
        mx0 = fmaxf(mx0, __shfl_xor_sync(0xffffffffu, mx0, 1));
        mx0 = fmaxf(mx0, __shfl_xor_sync(0xffffffffu, mx0, 2));
        mx1 = fmaxf(mx1, __shfl_xor_sync(0xffffffffu, mx1, 1));
        mx1 = fmaxf(mx1, __shfl_xor_sync(0xffffffffu, mx1, 2));
        float mn0 = fmaxf(m0, mx0), mn1 = fmaxf(m1, mx1);
        float sc0 = ex2f(m0 - mn0), sc1 = ex2f(m1 - mn1);
        m0 = mn0; m1 = mn1; d0 *= sc0; d1 *= sc1;
        #pragma unroll
        for (int nd = 0; nd < 8; nd++) {
            oacc[nd][0] *= sc0; oacc[nd][1] *= sc0;
            oacc[nd][2] *= sc1; oacc[nd][3] *= sc1;
        }

        // e = 2^(s-m), pack to f16; accumulate row sums
        unsigned pfh[8][2];
        float t0 = 0.f, t1 = 0.f;
        #pragma unroll
        for (int ni = 0; ni < 8; ni++) {
            float e0 = ex2f(fmaxf(sacc[ni][0] - mn0, -126.f));
            float e1 = ex2f(fmaxf(sacc[ni][1] - mn0, -126.f));
            float e2 = ex2f(fmaxf(sacc[ni][2] - mn1, -126.f));
            float e3 = ex2f(fmaxf(sacc[ni][3] - mn1, -126.f));
            t0 += e0 + e1; t1 += e2 + e3;
            pfh[ni][0] = packh(e0, e1);
            pfh[ni][1] = packh(e2, e3);
        }
        t0 += __shfl_xor_sync(0xffffffffu, t0, 1);
        t0 += __shfl_xor_sync(0xffffffffu, t0, 2);
        t1 += __shfl_xor_sync(0xffffffffu, t1, 1);
        t1 += __shfl_xor_sync(0xffffffffu, t1, 2);
        d0 += t0; d1 += t1;

        // O += P V (1-pass: P*Vh); skip fully-masked kf blocks
        #pragma unroll
        for (int kf = 0; kf < 4; kf++) {
            const int c0b = k0 + 16 * kf;
            if (c0b > rmax || c0b + 15 < rmin - (SW_ - 1)) continue;   // warp-uniform
            unsigned a0 = pfh[2*kf][0], a1 = pfh[2*kf][1];
            unsigned a2 = pfh[2*kf+1][0], a3 = pfh[2*kf+1][1];
            #pragma unroll
            for (int p = 0; p < 4; p++) {
                unsigned vh0, vh1, vh2, vh3;
                unsigned ad = vBase + (unsigned)((kf * 576 + p * 8) << 2);
                ldsm4t(vh0, vh1, vh2, vh3, ad);
                mma16816h(oacc[2*p],   a0, a1, a2, a3, vh0, vh1);
                mma16816h(oacc[2*p+1], a0, a1, a2, a3, vh2, vh3);
            }
        }
    }

    // epilogue: AO blocked [kc][4096 rows][16 words], single f16
    float inv0 = 1.f / d0, inv1 = 1.f / d1;
    #pragma unroll
    for (int nd = 0; nd < 8; nd++) {
        int col = 64 * h + 8 * nd + 2 * qid;
        int kc = col >> 5, wic = (col & 31) >> 1;
        size_t w0 = (size_t)kc * CS_X + (size_t)(b * N_ + i0) * 16 + wic;
        g_AOh[w0] = packh(oacc[nd][0] * inv0, oacc[nd][1] * inv0);
        size_t w1 = (size_t)kc * CS_X + (size_t)(b * N_ + i1) * 16 + wic;
        g_AOh[w1] = packh(oacc[nd][2] * inv1, oacc[nd][3] * inv1);
    }
}

extern "C" void kernel_launch(void* const* d_in, const int* in_sizes, int n_in,
                              void* d_out, int out_size)
{
    const float* x      = (const float*)d_in[0];
    const float* qkv_w  = (const float*)d_in[1];
    const float* qn_w   = (const float*)d_in[2];
    const float* qn_b   = (const float*)d_in[3];
    const float* kn_w   = (const float*)d_in[4];
    const float* kn_b   = (const float*)d_in[5];
    const float* sinks  = (const float*)d_in[6];
    const float* proj_w = (const float*)d_in[7];
    const float* proj_b = (const float*)d_in[8];
    float* out = (float*)d_out;

    cudaFuncSetAttribute(qkv_mm,  cudaFuncAttributeMaxDynamicSharedMemorySize, GEMM_SMEM);
    cudaFuncSetAttribute(proj_mm, cudaFuncAttributeMaxDynamicSharedMemorySize, GEMM_SMEM);
    cudaFuncSetAttribute(attn_tc, cudaFuncAttributeMaxDynamicSharedMemorySize, ATT_SMEM);

    presplit_all<<<dim3(1024, 4), 256>>>((const float4*)x, (const float4*)qkv_w,
                                         (const float4*)proj_w);
    qkv_mm<<<dim3(24, 32), 256, GEMM_SMEM>>>(qn_w, qn_b, kn_w, kn_b);
    attn_tc<<<dim3(16, 64), 128, ATT_SMEM>>>(sinks);
    proj_mm<<<dim3(8, 32), 256, GEMM_SMEM>>>(proj_b, out);
}

// round 17
// speedup vs baseline: 2.1385x; 1.0357x over previous
#include <cuda_runtime.h>
#include <cuda_bf16.h>
#include <cuda_fp16.h>
#include <math.h>
#include <cstdint>

#define B_   4
#define N_   1024
#define DIM_ 1024
#define H_   16
#define D_   64
#define SW_  256
#define LOG2E  1.4426950408889634f
#define QSCALE 0.18033688011112042f   // sm_scale * log2(e)

// ---------------- device globals (word = 2 f16) ----------------
// x/w/pw/AO stored CHUNK-BLOCKED: [kc][row][16 words] (kc = K/32 chunks)
__device__ unsigned g_xh[2097152];                    // x      4096x1024 f16
__device__ unsigned g_wh[1572864];                    // qkv_w  3072x1024 f16
__device__ unsigned g_pwh[524288];                    // proj_w 1024x1024 f16
__device__ unsigned g_Qh[2097152];                    // [b,h,n,d] f16 (pre-scaled)
__device__ unsigned g_Kh[2097152];                    // [b,h,n,d] f16
__device__ unsigned g_Vh[2097152];                    // [b,h,n,d] f16
__device__ unsigned g_AOh[2097152];                   // blocked [kc][4096][16] f16
__device__ float2  g_rope[32768];                     // [n][j] (cos, sin), j<32

#define CS_X  65536     // 32-elem chunk stride (words): 4096 rows * 16
#define CS_W  49152     // 3072 * 16
#define CS_P  16384     // 1024 * 16

// ---------------- helpers ----------------
__device__ __forceinline__ unsigned packh(float x, float y) {
    __half hx = __float2half_rn(x), hy = __float2half_rn(y);
    return ((unsigned)__half_as_ushort(hy) << 16) | (unsigned)__half_as_ushort(hx);
}
__device__ __forceinline__ void mma16816h(float* c, unsigned a0, unsigned a1,
                                          unsigned a2, unsigned a3,
                                          unsigned b0, unsigned b1) {
    asm volatile(
        "mma.sync.aligned.m16n8k16.row.col.f32.f16.f16.f32 "
        "{%0,%1,%2,%3}, {%4,%5,%6,%7}, {%8,%9}, {%0,%1,%2,%3};"
        : "+f"(c[0]), "+f"(c[1]), "+f"(c[2]), "+f"(c[3])
        : "r"(a0), "r"(a1), "r"(a2), "r"(a3), "r"(b0), "r"(b1));
}
__device__ __forceinline__ void ldsm4(unsigned &r0, unsigned &r1, unsigned &r2,
                                      unsigned &r3, unsigned addr) {
    asm volatile("ldmatrix.sync.aligned.m8n8.x4.shared.b16 {%0,%1,%2,%3}, [%4];"
                 : "=r"(r0), "=r"(r1), "=r"(r2), "=r"(r3) : "r"(addr));
}
__device__ __forceinline__ void ldsm4t(unsigned &r0, unsigned &r1, unsigned &r2,
                                       unsigned &r3, unsigned addr) {
    asm volatile("ldmatrix.sync.aligned.m8n8.x4.trans.shared.b16 {%0,%1,%2,%3}, [%4];"
                 : "=r"(r0), "=r"(r1), "=r"(r2), "=r"(r3) : "r"(addr));
}
__device__ __forceinline__ float ex2f(float x) {
    float y; asm("ex2.approx.f32 %0, %1;" : "=f"(y) : "f"(x)); return y;
}
__device__ __forceinline__ unsigned smem_u32(const void* p){
    unsigned a;
    asm("{ .reg .u64 t; cvta.to.shared.u64 t, %1; cvt.u32.u64 %0, t; }" : "=r"(a) : "l"(p));
    return a;
}
__device__ __forceinline__ void cpa16(unsigned daddr, const void* g){
    asm volatile("cp.async.cg.shared.global [%0], [%1], 16;" :: "r"(daddr), "l"(g) : "memory");
}
#define CP_COMMIT() asm volatile("cp.async.commit_group;" ::: "memory")
#define CP_WAIT0()  asm volatile("cp.async.wait_group 0;" ::: "memory")

// ---------------- presplit: fp32 -> f16, chunk-blocked; + rope table ----------
__global__ void presplit_all(const float4* __restrict__ x,
                             const float4* __restrict__ w,
                             const float4* __restrict__ pw)
{
    if (blockIdx.y == 3) {
        for (int i = blockIdx.x * blockDim.x + threadIdx.x; i < 32768;
             i += gridDim.x * blockDim.x) {
            int n = i >> 5, j = i & 31;
            float invf = expf(-(float)j * 0.2878231366242557f);  // 10000^(-j/32)
            float sn, cs;
            sincosf((float)n * invf, &sn, &cs);
            g_rope[i] = make_float2(cs, sn);
        }
        return;
    }
    const float4* s; unsigned *hp; int rows;
    if (blockIdx.y == 0)      { s = x;  hp = g_xh;  rows = 4096; }
    else if (blockIdx.y == 1) { s = w;  hp = g_wh;  rows = 3072; }
    else                      { s = pw; hp = g_pwh; rows = 1024; }
    const int n4 = rows * 256;
    for (int i = blockIdx.x * blockDim.x + threadIdx.x; i < n4; i += gridDim.x * blockDim.x) {
        float4 f = s[i];
        int r = i >> 8, c4 = i & 255;
        int kc = c4 >> 3, wic = (c4 & 7) * 2;
        size_t dw = (size_t)kc * rows * 16 + (size_t)r * 16 + wic;
        *(uint2*)(hp + dw) = make_uint2(packh(f.x, f.y), packh(f.z, f.w));
    }
}

// ------- GEMM mainloop: K-chunk 64, 3-stage, swizzled 32-word rows ------------
// stage (bytes): A 128x128B @0, B 128x128B @16384. phys quad = q8 ^ (row & 7).
#define STG_B  32768
#define GEMM_SMEM 98304     // 3 stages

__device__ __forceinline__ void mainloop_pre(
    const unsigned* __restrict__ gAh,
    const unsigned* __restrict__ gBh,
    int row0, int col0, int csA, int csB, unsigned* u, float acc[4][4][4])
{
    const int tid = threadIdx.x;
    const int wid = tid >> 5, lane = tid & 31;
    const int wm = wid >> 2, wn = wid & 3;
    const int lq = lane >> 3, lr = lane & 7;
    const int lqh = lq >> 1, lql = lq & 1;
    const unsigned ub = smem_u32(u);

    // fill coords: 1024 16B-vectors per array per chunk; 4 per thread each
    int dof[4];
    const unsigned* aP[4]; const unsigned* bP[4];
    #pragma unroll
    for (int v = 0; v < 4; v++) {
        int vi = tid + 256 * v;              // 0..1023
        int r = vi >> 3, q8 = vi & 7;
        dof[v] = r * 128 + ((q8 ^ (r & 7)) << 4);      // bytes in stage
        int h = q8 >> 2, qd = q8 & 3;
        aP[v] = gAh + (size_t)h * csA + (size_t)(row0 + r) * 16 + qd * 4;
        bP[v] = gBh + (size_t)h * csB + (size_t)(col0 + r) * 16 + qd * 4;
    }

    const int rowA = 64 * wm + lql * 8 + lr;
    const int xrA  = rowA & 7;
    const unsigned aRow = ub + (unsigned)(rowA * 128);
    unsigned qa[4], qb[4];
    const int rowB = 32 * wn + lqh * 8 + lr;
    const int xrB  = rowB & 7;
    const unsigned bRow = ub + 16384u + (unsigned)(rowB * 128);
    #pragma unroll
    for (int ks = 0; ks < 4; ks++) {
        qa[ks] = (unsigned)(((ks * 2 + lqh) ^ xrA) << 4);
        qb[ks] = (unsigned)(((ks * 2 + lql) ^ xrB) << 4);
    }

    auto fill = [&](int stage, int cidx) {
        const int oa = 2 * cidx * csA, ob = 2 * cidx * csB;
        #pragma unroll
        for (int v = 0; v < 4; v++) {
            unsigned da = ub + (unsigned)(stage * STG_B + dof[v]);
            cpa16(da,          aP[v] + oa);
            cpa16(da + 16384u, bP[v] + ob);
        }
        CP_COMMIT();
    };

    fill(0, 0);
    fill(1, 1);

    int stc = 0, stf = 2;
    for (int c = 0; c < 16; c++) {
        if (c < 15) asm volatile("cp.async.wait_group 1;" ::: "memory");
        else        asm volatile("cp.async.wait_group 0;" ::: "memory");
        __syncthreads();
        if (c + 2 < 16) { fill(stf, c + 2); stf = (stf == 2) ? 0 : stf + 1; }

        const unsigned so = (unsigned)(stc * STG_B);
        stc = (stc == 2) ? 0 : stc + 1;

        #pragma unroll
        for (int ks = 0; ks < 4; ks++) {
            unsigned bhf[2][4];
            #pragma unroll
            for (int p = 0; p < 2; p++) {
                unsigned ad = bRow + so + (unsigned)(p * 2048) + qb[ks];
                ldsm4(bhf[p][0], bhf[p][1], bhf[p][2], bhf[p][3], ad);
            }
            #pragma unroll
            for (int mi = 0; mi < 4; mi++) {
                unsigned ad = aRow + so + (unsigned)(mi * 2048) + qa[ks];
                unsigned ah0, ah1, ah2, ah3;
                ldsm4(ah0, ah1, ah2, ah3, ad);
                mma16816h(acc[mi][0], ah0, ah1, ah2, ah3, bhf[0][0], bhf[0][1]);
                mma16816h(acc[mi][1], ah0, ah1, ah2, ah3, bhf[0][2], bhf[0][3]);
                mma16816h(acc[mi][2], ah0, ah1, ah2, ah3, bhf[1][0], bhf[1][1]);
                mma16816h(acc[mi][3], ah0, ah1, ah2, ah3, bhf[1][2], bhf[1][3]);
            }
        }
    }
    __syncthreads();
}

// ---------------- Kernel 1: QKV GEMM + LN + RoPE + store ----------------
__global__ __launch_bounds__(256, 2) void qkv_mm(
    const float* __restrict__ qn_w, const float* __restrict__ qn_b,
    const float* __restrict__ kn_w, const float* __restrict__ kn_b)
{
    extern __shared__ __align__(16) unsigned u[];
    const int tid = threadIdx.x;
    const int wid = tid >> 5, lane = tid & 31;
    const int wm = wid >> 2, wn = wid & 3;
    const int grp = lane >> 2, qid = lane & 3;
    const int row0 = blockIdx.y * 128;
    const int col0 = blockIdx.x * 128;

    float acc[4][4][4];
    #pragma unroll
    for (int i = 0; i < 4; i++)
        #pragma unroll
        for (int j = 0; j < 4; j++)
            #pragma unroll
            for (int k = 0; k < 4; k++) acc[i][j][k] = 0.f;

    mainloop_pre(g_xh, g_wh, row0, col0, CS_X, CS_W, u, acc);

    // stage 128x128 f32 tile (stride 132)
    float* stg = (float*)u;
    #pragma unroll
    for (int mi = 0; mi < 4; mi++) {
        int rr2 = 64 * wm + 16 * mi + grp;
        #pragma unroll
        for (int ni = 0; ni < 4; ni++) {
            int cc = 32 * wn + 8 * ni + 2 * qid;
            stg[rr2 * 132 + cc]           = acc[mi][ni][0];
            stg[rr2 * 132 + cc + 1]       = acc[mi][ni][1];
            stg[(rr2 + 8) * 132 + cc]     = acc[mi][ni][2];
            stg[(rr2 + 8) * 132 + cc + 1] = acc[mi][ni][3];
        }
    }
    __syncthreads();

    const int hh = tid >> 7, r = tid & 127;
    float d[64];
    const float* src = stg + r * 132 + hh * 64;
    #pragma unroll
    for (int j = 0; j < 16; j++) {
        float4 v = *(const float4*)(src + 4 * j);
        d[4*j] = v.x; d[4*j+1] = v.y; d[4*j+2] = v.z; d[4*j+3] = v.w;
    }

    const int t = col0 >> 10;                      // 0=q,1=k,2=v
    const int h = ((col0 & 1023) >> 6) + hh;
    const int grow = row0 + r;
    const int b = grow >> 10, n = grow & 1023;
    const size_t wbase = ((size_t)(b * H_ + h) * N_ + n) * 32;   // word offset

    unsigned hw[32];
    if (t == 2) {
        #pragma unroll
        for (int cpair = 0; cpair < 32; cpair++)
            hw[cpair] = packh(d[2*cpair], d[2*cpair+1]);
        #pragma unroll
        for (int q8 = 0; q8 < 8; q8++)
            *(uint4*)(g_Vh + wbase + 4*q8) = make_uint4(hw[4*q8], hw[4*q8+1], hw[4*q8+2], hw[4*q8+3]);
        return;
    }

    const float* lw = t ? kn_w : qn_w;
    const float* lb = t ? kn_b : qn_b;
    float s1 = 0.f, s2 = 0.f;
    #pragma unroll
    for (int j = 0; j < 64; j++) { s1 += d[j]; s2 += d[j] * d[j]; }
    float mu = s1 * (1.f / 64.f);
    float var = s2 * (1.f / 64.f) - mu * mu;
    float rstd = rsqrtf(var + 1e-5f);
    #pragma unroll
    for (int j = 0; j < 64; j++)
        d[j] = (d[j] - mu) * rstd * __ldg(lw + j) + __ldg(lb + j);
    const float2* rt = g_rope + n * 32;
    #pragma unroll
    for (int j = 0; j < 32; j++) {
        float2 cs = __ldg(rt + j);
        float t0 = d[j];
        d[j]      = t0 * cs.x - d[j + 32] * cs.y;
        d[j + 32] = d[j + 32] * cs.x + t0 * cs.y;
    }
    const float qs = (t == 0) ? QSCALE : 1.f;
    #pragma unroll
    for (int cpair = 0; cpair < 32; cpair++)
        hw[cpair] = packh(d[2*cpair] * qs, d[2*cpair+1] * qs);
    unsigned* dst = t ? g_Kh : g_Qh;
    #pragma unroll
    for (int q8 = 0; q8 < 8; q8++)
        *(uint4*)(dst + wbase + 4*q8) = make_uint4(hw[4*q8], hw[4*q8+1], hw[4*q8+2], hw[4*q8+3]);
}

// ---------------- Kernel 3: proj GEMM + bias (1-pass) ----------------
__global__ __launch_bounds__(256, 2) void proj_mm(
    const float* __restrict__ bias, float* __restrict__ out)
{
    extern __shared__ __align__(16) unsigned u[];
    const int tid = threadIdx.x;
    const int wid = tid >> 5, lane = tid & 31;
    const int wm = wid >> 2, wn = wid & 3;
    const int grp = lane >> 2, qid = lane & 3;
    const int row0 = blockIdx.y * 128;
    const int col0 = blockIdx.x * 128;

    float acc[4][4][4];
    #pragma unroll
    for (int i = 0; i < 4; i++)
        #pragma unroll
        for (int j = 0; j < 4; j++)
            #pragma unroll
            for (int k = 0; k < 4; k++) acc[i][j][k] = 0.f;

    mainloop_pre(g_AOh, g_pwh, row0, col0, CS_X, CS_P, u, acc);

    #pragma unroll
    for (int mi = 0; mi < 4; mi++) {
        int rr = row0 + 64 * wm + 16 * mi + grp;
        #pragma unroll
        for (int ni = 0; ni < 4; ni++) {
            int cc = col0 + 32 * wn + 8 * ni + 2 * qid;
            float b0 = __ldg(bias + cc), b1 = __ldg(bias + cc + 1);
            *(float2*)(out + (size_t)rr * DIM_ + cc) =
                make_float2(acc[mi][ni][0] + b0, acc[mi][ni][1] + b1);
            *(float2*)(out + (size_t)(rr + 8) * DIM_ + cc) =
                make_float2(acc[mi][ni][2] + b0, acc[mi][ni][3] + b1);
        }
    }
}

// ------ Kernel 2: flash attention (Q/K/V single f16; QK 1-pass; PV 1-pass) ----
// smem word offsets: Qh, Kh, Vh each 64 rows x 36 words
#define AQH 0
#define AKH 2304
#define AVH 4608
#define ATT_SMEM 27648

__global__ __launch_bounds__(128) void attn_tc(const float* __restrict__ sinks)
{
    extern __shared__ __align__(16) unsigned u[];
    const int tid = threadIdx.x;
    const int wid = tid >> 5, lane = tid & 31;
    const int g8 = lane >> 2, qid = lane & 3;
    const int lq = lane >> 3, lr = lane & 7;
    const int bh = blockIdx.y, b = bh >> 4, h = bh & 15;
    const int q0 = blockIdx.x * 64;
    const unsigned ub = smem_u32(u);

    const size_t base = (size_t)(b * H_ + h) * N_ * 32;   // word base of this (b,h)
    const unsigned* Qhg = g_Qh + base + (size_t)q0 * 32;
    const unsigned* Khg = g_Kh + base;
    const unsigned* Vhg = g_Vh + base;

    #pragma unroll
    for (int v = 0; v < 4; v++) {
        int idx = tid + 128 * v;          // 0..511
        int r = idx >> 3, f = (idx & 7) * 4;
        unsigned da = ub + (unsigned)((r * 36 + f) << 2);
        cpa16(da + AQH * 4, Qhg + r * 32 + f);
    }
    CP_COMMIT(); CP_WAIT0();
    __syncthreads();

    // hoist Q fragments (loop-invariant over kt)
    unsigned qh[4][4];
    const unsigned qBase = ub + ((AQH + (16 * wid + (lq & 1) * 8 + lr) * 36 + (lq >> 1) * 4) << 2);
    #pragma unroll
    for (int ks = 0; ks < 4; ks++)
        ldsm4(qh[ks][0], qh[ks][1], qh[ks][2], qh[ks][3], qBase + (unsigned)((ks * 8) << 2));

    const unsigned kBase = ub + ((AKH + ((lq >> 1) * 8 + lr) * 36 + (lq & 1) * 4) << 2);
    const unsigned vBase = ub + ((AVH + ((lq & 1) * 8 + lr) * 36 + (lq >> 1) * 4) << 2);

    float m0 = __ldg(sinks + h) * LOG2E, m1 = m0;
    float d0 = 1.f, d1 = 1.f;
    float oacc[8][4];
    #pragma unroll
    for (int i = 0; i < 8; i++)
        #pragma unroll
        for (int j = 0; j < 4; j++) oacc[i][j] = 0.f;

    const int i0 = q0 + 16 * wid + g8;
    const int i1 = i0 + 8;
    const int rmin = q0 + 16 * wid;          // warp's min row
    const int rmax = rmin + 15;              // warp's max row
    const int kt_lo = (q0 >= SW_) ? ((q0 - SW_ + 1) >> 6) : 0;
    const int kt_hi = q0 >> 6;

    for (int kt = kt_lo; kt <= kt_hi; kt++) {
        const int k0 = kt << 6;
        __syncthreads();
        #pragma unroll
        for (int v = 0; v < 4; v++) {
            int idx = tid + 128 * v;
            int r = idx >> 3, f = (idx & 7) * 4;
            unsigned da = ub + (unsigned)((r * 36 + f) << 2);
            int so = (k0 + r) * 32 + f;
            cpa16(da + AKH * 4, Khg + so);
            cpa16(da + AVH * 4, Vhg + so);
        }
        CP_COMMIT(); CP_WAIT0();
        __syncthreads();

        // S = Q K^T (1-pass: Qh*Kh); skip fully-masked 16-col blocks
        float sacc[8][4];
        #pragma unroll
        for (int i = 0; i < 8; i++)
            #pragma unroll
            for (int j = 0; j < 4; j++) sacc[i][j] = 0.f;

        #pragma unroll
        for (int p = 0; p < 4; p++) {
            const int c0b = k0 + 16 * p;
            if (c0b > rmax || c0b + 15 < rmin - (SW_ - 1)) continue;   // warp-uniform
            #pragma unroll
            for (int ks = 0; ks < 4; ks++) {
                unsigned kh0, kh1, kh2, kh3;
                unsigned ad = kBase + (unsigned)((p * 576 + ks * 8) << 2);
                ldsm4(kh0, kh1, kh2, kh3, ad);
                mma16816h(sacc[2*p],   qh[ks][0], qh[ks][1], qh[ks][2], qh[ks][3], kh0, kh1);
                mma16816h(sacc[2*p+1], qh[ks][0], qh[ks][1], qh[ks][2], qh[ks][3], kh2, kh3);
            }
        }

        // mask + row max
        float mx0 = -1e30f, mx1 = -1e30f;
        #pragma unroll
        for (int ni = 0; ni < 8; ni++) {
            int j = k0 + 8 * ni + 2 * qid;
            sacc[ni][0] = (j     <= i0 && j     > i0 - SW_) ? sacc[ni][0] : -1e30f;
            sacc[ni][1] = (j + 1 <= i0 && j + 1 > i0 - SW_) ? sacc[ni][1] : -1e30f;
            sacc[ni][2] = (j     <= i1 && j     > i1 - SW_) ? sacc[ni][2] : -1e30f;
            sacc[ni][3] = (j + 1 <= i1 && j + 1 > i1 - SW_) ? sacc[ni][3] : -1e30f;
            mx0 = fmaxf(mx0, fmaxf(sacc[ni][0], sacc[ni][1]));
            mx1 = fmaxf(mx1, fmaxf(sacc[ni][2], sacc[ni][3]));
        }
        mx0 = fmaxf(mx0, __shfl_xor_sync(0xffffffffu, mx0, 1));
        mx0 = fmaxf(mx0, __shfl_xor_sync(0xffffffffu, mx0, 2));
        mx1 = fmaxf(mx1, __shfl_xor_sync(0xffffffffu, mx1, 1));
        mx1 = fmaxf(mx1, __shfl_xor_sync(0xffffffffu, mx1, 2));
        float mn0 = fmaxf(m0, mx0), mn1 = fmaxf(m1, mx1);
        float sc0 = ex2f(m0 - mn0), sc1 = ex2f(m1 - mn1);
        m0 = mn0; m1 = mn1; d0 *= sc0; d1 *= sc1;
        #pragma unroll
        for (int nd = 0; nd < 8; nd++) {
            oacc[nd][0] *= sc0; oacc[nd][1] *= sc0;
            oacc[nd][2] *= sc1; oacc[nd][3] *= sc1;
        }

        // e = 2^(s-m), pack to f16; accumulate row sums
        unsigned pfh[8][2];
        float t0 = 0.f, t1 = 0.f;
        #pragma unroll
        for (int ni = 0; ni < 8; ni++) {
            float e0 = ex2f(fmaxf(sacc[ni][0] - mn0, -126.f));
            float e1 = ex2f(fmaxf(sacc[ni][1] - mn0, -126.f));
            float e2 = ex2f(fmaxf(sacc[ni][2] - mn1, -126.f));
            float e3 = ex2f(fmaxf(sacc[ni][3] - mn1, -126.f));
            t0 += e0 + e1; t1 += e2 + e3;
            pfh[ni][0] = packh(e0, e1);
            pfh[ni][1] = packh(e2, e3);
        }
        t0 += __shfl_xor_sync(0xffffffffu, t0, 1);
        t0 += __shfl_xor_sync(0xffffffffu, t0, 2);
        t1 += __shfl_xor_sync(0xffffffffu, t1, 1);
        t1 += __shfl_xor_sync(0xffffffffu, t1, 2);
        d0 += t0; d1 += t1;

        // O += P V (1-pass: P*Vh); skip fully-masked kf blocks
        #pragma unroll
        for (int kf = 0; kf < 4; kf++) {
            const int c0b = k0 + 16 * kf;
            if (c0b > rmax || c0b + 15 < rmin - (SW_ - 1)) continue;   // warp-uniform
            unsigned a0 = pfh[2*kf][0], a1 = pfh[2*kf][1];
            unsigned a2 = pfh[2*kf+1][0], a3 = pfh[2*kf+1][1];
            #pragma unroll
            for (int p = 0; p < 4; p++) {
                unsigned vh0, vh1, vh2, vh3;
                unsigned ad = vBase + (unsigned)((kf * 576 + p * 8) << 2);
                ldsm4t(vh0, vh1, vh2, vh3, ad);
                mma16816h(oacc[2*p],   a0, a1, a2, a3, vh0, vh1);
                mma16816h(oacc[2*p+1], a0, a1, a2, a3, vh2, vh3);
            }
        }
    }

    // epilogue: AO blocked [kc][4096 rows][16 words], single f16
    float inv0 = 1.f / d0, inv1 = 1.f / d1;
    #pragma unroll
    for (int nd = 0; nd < 8; nd++) {
        int col = 64 * h + 8 * nd + 2 * qid;
        int kc = col >> 5, wic = (col & 31) >> 1;
        size_t w0 = (size_t)kc * CS_X + (size_t)(b * N_ + i0) * 16 + wic;
        g_AOh[w0] = packh(oacc[nd][0] * inv0, oacc[nd][1] * inv0);
        size_t w1 = (size_t)kc * CS_X + (size_t)(b * N_ + i1) * 16 + wic;
        g_AOh[w1] = packh(oacc[nd][2] * inv1, oacc[nd][3] * inv1);
    }
}

extern "C" void kernel_launch(void* const* d_in, const int* in_sizes, int n_in,
                              void* d_out, int out_size)
{
    const float* x      = (const float*)d_in[0];
    const float* qkv_w  = (const float*)d_in[1];
    const float* qn_w   = (const float*)d_in[2];
    const float* qn_b   = (const float*)d_in[3];
    const float* kn_w   = (const float*)d_in[4];
    const float* kn_b   = (const float*)d_in[5];
    const float* sinks  = (const float*)d_in[6];
    const float* proj_w = (const float*)d_in[7];
    const float* proj_b = (const float*)d_in[8];
    float* out = (float*)d_out;

    cudaFuncSetAttribute(qkv_mm,  cudaFuncAttributeMaxDynamicSharedMemorySize, GEMM_SMEM);
    cudaFuncSetAttribute(proj_mm, cudaFuncAttributeMaxDynamicSharedMemorySize, GEMM_SMEM);
    cudaFuncSetAttribute(attn_tc, cudaFuncAttributeMaxDynamicSharedMemorySize, ATT_SMEM);

    presplit_all<<<dim3(1024, 4), 256>>>((const float4*)x, (const float4*)qkv_w,
                                         (const float4*)proj_w);
    qkv_mm<<<dim3(24, 32), 256, GEMM_SMEM>>>(qn_w, qn_b, kn_w, kn_b);
    attn_tc<<<dim3(16, 64), 128, ATT_SMEM>>>(sinks);
    proj_mm<<<dim3(8, 32), 256, GEMM_SMEM>>>(proj_b, out);
}